// round 2
// baseline (speedup 1.0000x reference)
#include <cuda_runtime.h>
#include <math.h>

#define NB    4
#define QL    64
#define NH    32
#define HD    128
#define CTX   4096
#define TOT   4160
#define HID   4096
#define EPSR  1e-6f
#define INV_SQRT_D 0.08838834764831843f

// Scratch (allocation-free rule: __device__ globals)
__device__ float g_qraw[NB * QL * HID];        // raw Q projection  [bq][4096]
__device__ float g_q   [NB * NH * QL * HD];    // normed+roped+scaled Q, [bh][q][d]
__device__ float g_attn[NB * QL * HID];        // attention out [bq][h*128+d]

// ---------------------------------------------------------------------------
// SGEMM: C[M=256, N=4096] = A[256, K=4096] @ B[K, N]  (B row stride = ldb)
// BM=64, BN=128, BK=16, 256 threads, 4x8 microtile.
// ---------------------------------------------------------------------------
__global__ __launch_bounds__(256) void sgemm_k(const float* __restrict__ A,
                                               const float* __restrict__ Bm,
                                               float* __restrict__ C,
                                               int ldb)
{
    __shared__ float As[16][68];    // [k][m], padded
    __shared__ float Bs[16][128];   // [k][n]

    const int tid = threadIdx.x;
    const int tx  = tid & 15;        // n-group
    const int ty  = tid >> 4;        // m-group (0..15)
    const int m0  = ty * 4;
    const int bx  = blockIdx.x;      // 0..31  (N tiles of 128)
    const int by  = blockIdx.y;      // 0..3   (M tiles of 64)

    const float* Ab = A  + (size_t)(by * 64) * HID;
    const float* Bb = Bm + (size_t)(bx * 128);

    float acc[4][8];
#pragma unroll
    for (int i = 0; i < 4; i++)
#pragma unroll
        for (int j = 0; j < 8; j++) acc[i][j] = 0.f;

    const int ar = tid >> 2;           // 0..63 (m row)
    const int ac = (tid & 3) * 4;      // 0,4,8,12 (k)
    const int br = tid >> 5;           // 0..7  (k row)
    const int bc = (tid & 31) * 4;     // 0..124 (n)

    for (int k0 = 0; k0 < HID; k0 += 16) {
        float4 a4 = *(const float4*)(Ab + (size_t)ar * HID + k0 + ac);
        float4 b0 = *(const float4*)(Bb + (size_t)(k0 + br)     * ldb + bc);
        float4 b1 = *(const float4*)(Bb + (size_t)(k0 + br + 8) * ldb + bc);
        __syncthreads();   // protect previous iteration's smem reads
        As[ac + 0][ar] = a4.x;
        As[ac + 1][ar] = a4.y;
        As[ac + 2][ar] = a4.z;
        As[ac + 3][ar] = a4.w;
        *(float4*)&Bs[br][bc]     = b0;
        *(float4*)&Bs[br + 8][bc] = b1;
        __syncthreads();
#pragma unroll
        for (int k = 0; k < 16; k++) {
            float4 av  = *(float4*)&As[k][m0];
            float4 bv0 = *(float4*)&Bs[k][tx * 4];
            float4 bv1 = *(float4*)&Bs[k][64 + tx * 4];
            float am[4] = {av.x, av.y, av.z, av.w};
            float bn[8] = {bv0.x, bv0.y, bv0.z, bv0.w, bv1.x, bv1.y, bv1.z, bv1.w};
#pragma unroll
            for (int i = 0; i < 4; i++)
#pragma unroll
                for (int j = 0; j < 8; j++) acc[i][j] += am[i] * bn[j];
        }
    }
#pragma unroll
    for (int i = 0; i < 4; i++) {
        size_t row = (size_t)(by * 64 + m0 + i) * HID + (size_t)bx * 128;
        float4 c0 = make_float4(acc[i][0], acc[i][1], acc[i][2], acc[i][3]);
        float4 c1 = make_float4(acc[i][4], acc[i][5], acc[i][6], acc[i][7]);
        *(float4*)(C + row + tx * 4)      = c0;
        *(float4*)(C + row + 64 + tx * 4) = c1;
    }
}

// ---------------------------------------------------------------------------
// Q: double RMSNorm + RoPE + fold 1/sqrt(D). One warp per (b,q,h) head row.
// ---------------------------------------------------------------------------
__global__ __launch_bounds__(256) void qnorm_rope_k(const float* __restrict__ cosb,
                                                    const float* __restrict__ sinb,
                                                    const float* __restrict__ w)
{
    const int gw   = (blockIdx.x * 256 + threadIdx.x) >> 5;   // 0..8191
    const int lane = threadIdx.x & 31;
    const int h = gw & 31;
    const int q = (gw >> 5) & 63;
    const int b = gw >> 11;

    const float* src = g_qraw + (size_t)(b * QL + q) * HID + h * HD + lane * 4;
    float4 x4 = *(const float4*)src;
    float  x[4] = {x4.x, x4.y, x4.z, x4.w};
    float4 w4 = *(const float4*)(w + lane * 4);
    float  wv[4] = {w4.x, w4.y, w4.z, w4.w};

    float ss = x[0]*x[0] + x[1]*x[1] + x[2]*x[2] + x[3]*x[3];
#pragma unroll
    for (int o = 16; o > 0; o >>= 1) ss += __shfl_xor_sync(0xffffffffu, ss, o);
    float r1 = rsqrtf(ss * (1.f / 128.f) + EPSR);

    float y[4];
#pragma unroll
    for (int j = 0; j < 4; j++) y[j] = x[j] * r1 * wv[j];

    float ss2 = y[0]*y[0] + y[1]*y[1] + y[2]*y[2] + y[3]*y[3];
#pragma unroll
    for (int o = 16; o > 0; o >>= 1) ss2 += __shfl_xor_sync(0xffffffffu, ss2, o);
    float r2 = rsqrtf(ss2 * (1.f / 128.f) + EPSR);

    float z[4];
#pragma unroll
    for (int j = 0; j < 4; j++) z[j] = y[j] * r2 * wv[j];

    const float* cp = cosb + (size_t)(CTX + q) * HD + lane * 4;
    const float* sp = sinb + (size_t)(CTX + q) * HD + lane * 4;
    float4 c4 = *(const float4*)cp;
    float4 s4 = *(const float4*)sp;
    float cf[4] = {c4.x, c4.y, c4.z, c4.w};
    float sf[4] = {s4.x, s4.y, s4.z, s4.w};

    float o_[4];
#pragma unroll
    for (int j = 0; j < 4; j++) {
        float p   = __shfl_xor_sync(0xffffffffu, z[j], 16);
        float rot = (lane < 16) ? -p : p;
        o_[j] = (z[j] * cf[j] + rot * sf[j]) * INV_SQRT_D;
    }
    float* dst = g_q + (size_t)((b * NH + h) * QL + q) * HD + lane * 4;
    *(float4*)dst = make_float4(o_[0], o_[1], o_[2], o_[3]);
}

// ---------------------------------------------------------------------------
// Flash attention: one CTA per (b,h). 65 key tiles of 64.
// Vr = raw KV tile (used as V), Krt = roped K transposed [d][j] for
// conflict-free QK^T reads. Online softmax with per-row m/l.
// ---------------------------------------------------------------------------
#define ATTN_SMEM_FLOATS (64*128 + 64*128 + 128*68 + 64*68 + 3*64)
#define ATTN_SMEM_BYTES  (ATTN_SMEM_FLOATS * 4)

__global__ __launch_bounds__(256) void attn_k(const float* __restrict__ th,
                                              const float* __restrict__ hs,
                                              const float* __restrict__ cosb,
                                              const float* __restrict__ sinb)
{
    extern __shared__ float sm[];
    float* Qs   = sm;                    // [64][128]
    float* Vr   = Qs  + 64 * 128;        // [64][128] raw KV (V)
    float* Krt  = Vr  + 64 * 128;        // [128][68] roped K transposed
    float* Ss   = Krt + 128 * 68;        // [64][68] scores/probs
    float* mrow = Ss  + 64 * 68;
    float* lrow = mrow + 64;
    float* arow = lrow + 64;

    const int bh = blockIdx.x;           // b*32 + h
    const int h  = bh & 31;
    const int b  = bh >> 5;
    const int tid = threadIdx.x;
    const int ti = tid >> 4;             // 0..15 -> query rows i0..i0+3
    const int tj = tid & 15;             // j-groups (scores) / d-groups (PV)
    const int i0 = ti * 4;
    const int d0 = tj * 8;

    // Load Q (already normed, roped, scaled)
    const float* qsrc = g_q + (size_t)bh * 64 * 128;
    for (int e = tid * 4; e < 8192; e += 1024)
        *(float4*)&Qs[e] = *(const float4*)(qsrc + e);
    if (tid < 64) { mrow[tid] = -1e30f; lrow[tid] = 0.f; }

    float Oacc[4][8];
#pragma unroll
    for (int r = 0; r < 4; r++)
#pragma unroll
        for (int c = 0; c < 8; c++) Oacc[r][c] = 0.f;

    __syncthreads();

    for (int t = 0; t < 65; t++) {
        const int p0 = t * 64;

        // Load raw KV tile into Vr (coalesced)
        for (int e = tid * 4; e < 8192; e += 1024) {
            int j  = e >> 7;
            int dd = e & 127;
            int p  = p0 + j;
            const float* src = (p < CTX)
                ? th + ((size_t)b * CTX + p) * HID + h * HD + dd
                : hs + ((size_t)b * QL + (p - CTX)) * HID + h * HD + dd;
            *(float4*)&Vr[e] = *(const float4*)src;
        }
        __syncthreads();

        // RoPE K into transposed Krt[d][j]
        for (int e = tid; e < 8192; e += 256) {
            int dd = e & 127;
            int j  = e >> 7;
            int p  = p0 + j;
            float v   = Vr[j * 128 + dd];
            float vp  = Vr[j * 128 + (dd ^ 64)];
            float c   = cosb[(size_t)p * HD + dd];
            float s   = sinb[(size_t)p * HD + dd];
            float rot = (dd < 64) ? -vp : vp;
            Krt[dd * 68 + j] = v * c + rot * s;
        }
        __syncthreads();

        // Scores: S[i0+r][4*tj+c] = sum_d Q[i][d] * Krt[d][j]
        float sa[4][4];
#pragma unroll
        for (int r = 0; r < 4; r++)
#pragma unroll
            for (int c = 0; c < 4; c++) sa[r][c] = 0.f;

#pragma unroll 2
        for (int dd = 0; dd < 128; dd += 4) {
            float4 k0v = *(float4*)&Krt[(dd + 0) * 68 + tj * 4];
            float4 k1v = *(float4*)&Krt[(dd + 1) * 68 + tj * 4];
            float4 k2v = *(float4*)&Krt[(dd + 2) * 68 + tj * 4];
            float4 k3v = *(float4*)&Krt[(dd + 3) * 68 + tj * 4];
#pragma unroll
            for (int r = 0; r < 4; r++) {
                float4 q4 = *(float4*)&Qs[(i0 + r) * 128 + dd];
                sa[r][0] += q4.x * k0v.x + q4.y * k1v.x + q4.z * k2v.x + q4.w * k3v.x;
                sa[r][1] += q4.x * k0v.y + q4.y * k1v.y + q4.z * k2v.y + q4.w * k3v.y;
                sa[r][2] += q4.x * k0v.z + q4.y * k1v.z + q4.z * k2v.z + q4.w * k3v.z;
                sa[r][3] += q4.x * k0v.w + q4.y * k1v.w + q4.z * k2v.w + q4.w * k3v.w;
            }
        }
#pragma unroll
        for (int r = 0; r < 4; r++)
#pragma unroll
            for (int c = 0; c < 4; c++)
                Ss[(i0 + r) * 68 + tj * 4 + c] = sa[r][c];
        __syncthreads();

        // Online softmax, row per thread (threads 0..63)
        if (tid < 64) {
            float* srow = Ss + tid * 68;
            float mold = mrow[tid];
            float mt = mold;
#pragma unroll 4
            for (int j = 0; j < 64; j++) mt = fmaxf(mt, srow[j]);
            float al = __expf(mold - mt);
            float ls = 0.f;
#pragma unroll 4
            for (int j = 0; j < 64; j++) {
                float e_ = __expf(srow[j] - mt);
                srow[j] = e_;
                ls += e_;
            }
            mrow[tid] = mt;
            lrow[tid] = lrow[tid] * al + ls;
            arow[tid] = al;
        }
        __syncthreads();

        // Rescale O and accumulate P @ V
        float al[4];
#pragma unroll
        for (int r = 0; r < 4; r++) al[r] = arow[i0 + r];
#pragma unroll
        for (int r = 0; r < 4; r++)
#pragma unroll
            for (int c = 0; c < 8; c++) Oacc[r][c] *= al[r];

#pragma unroll 4
        for (int j = 0; j < 64; j++) {
            float4 v0 = *(float4*)&Vr[j * 128 + d0];
            float4 v1 = *(float4*)&Vr[j * 128 + d0 + 4];
#pragma unroll
            for (int r = 0; r < 4; r++) {
                float pr = Ss[(i0 + r) * 68 + j];
                Oacc[r][0] += pr * v0.x;
                Oacc[r][1] += pr * v0.y;
                Oacc[r][2] += pr * v0.z;
                Oacc[r][3] += pr * v0.w;
                Oacc[r][4] += pr * v1.x;
                Oacc[r][5] += pr * v1.y;
                Oacc[r][6] += pr * v1.z;
                Oacc[r][7] += pr * v1.w;
            }
        }
        __syncthreads();   // before next tile overwrites Vr/Ss
    }

    // Epilogue: divide by l, write [b][q][h*128+d]
#pragma unroll
    for (int r = 0; r < 4; r++) {
        float inv = 1.f / lrow[i0 + r];
        size_t row = (size_t)(b * QL + (i0 + r)) * HID + h * HD + d0;
        float4 c0 = make_float4(Oacc[r][0] * inv, Oacc[r][1] * inv,
                                Oacc[r][2] * inv, Oacc[r][3] * inv);
        float4 c1 = make_float4(Oacc[r][4] * inv, Oacc[r][5] * inv,
                                Oacc[r][6] * inv, Oacc[r][7] * inv);
        *(float4*)(g_attn + row)     = c0;
        *(float4*)(g_attn + row + 4) = c1;
    }
}

// ---------------------------------------------------------------------------
extern "C" void kernel_launch(void* const* d_in, const int* in_sizes, int n_in,
                              void* d_out, int out_size)
{
    const float* hs   = (const float*)d_in[0];   // hidden_states  [4,64,4096]
    const float* th   = (const float*)d_in[1];   // target_hidden  [4,4096,4096]
    const float* cosb = (const float*)d_in[2];   // [4160,128]
    const float* sinb = (const float*)d_in[3];   // [4160,128]
    const float* Wqkv = (const float*)d_in[4];   // [4096,12288]
    const float* Wo   = (const float*)d_in[5];   // [4096,4096]
    const float* qw   = (const float*)d_in[6];   // [128]
    float* out = (float*)d_out;

    float *qraw_p, *attn_p;
    cudaGetSymbolAddress((void**)&qraw_p, g_qraw);
    cudaGetSymbolAddress((void**)&attn_p, g_attn);

    cudaFuncSetAttribute(attn_k, cudaFuncAttributeMaxDynamicSharedMemorySize,
                         ATTN_SMEM_BYTES);

    dim3 gg(32, 4);
    // 1) Q projection (first 4096 cols of Wqkv only)
    sgemm_k<<<gg, 256>>>(hs, Wqkv, qraw_p, 3 * HID);
    // 2) double RMSNorm + RoPE + scale fold
    qnorm_rope_k<<<1024, 256>>>(cosb, sinb, qw);
    // 3) flash attention over 4160 keys (K roped on the fly, V raw)
    attn_k<<<NB * NH, 256, ATTN_SMEM_BYTES>>>(th, hs, cosb, sinb);
    // 4) output projection
    sgemm_k<<<gg, 256>>>(attn_p, Wo, out, HID);
}

// round 3
// speedup vs baseline: 1.7847x; 1.7847x over previous
#include <cuda_runtime.h>
#include <math.h>
#include <stdint.h>

#define NB    4
#define QL    64
#define NH    32
#define HD    128
#define CTX   4096
#define TOT   4160
#define HID   4096
#define EPSR  1e-6f
#define INV_SQRT_D 0.08838834764831843f

// Scratch (allocation-free rule: __device__ globals)
__device__ float g_qraw[NB * QL * HID];        // raw Q projection  [bq][4096]
__device__ float g_q   [NB * NH * QL * HD];    // normed+roped+scaled Q, [bh][q][d]
__device__ float g_attn[NB * QL * HID];        // attention out [bq][h*128+d]

// ---------------------------------------------------------------------------
// helpers: tf32 round-to-nearest, warp mma m16n8k8 tf32
// ---------------------------------------------------------------------------
__device__ __forceinline__ float rna(float x) {
    uint32_t u;
    asm("cvt.rna.tf32.f32 %0, %1;" : "=r"(u) : "f"(x));
    return __uint_as_float(u);
}

__device__ __forceinline__ void mma_tf32(float d[4],
                                         uint32_t a0, uint32_t a1, uint32_t a2, uint32_t a3,
                                         uint32_t b0, uint32_t b1) {
    asm volatile(
        "mma.sync.aligned.m16n8k8.row.col.f32.tf32.tf32.f32 "
        "{%0,%1,%2,%3}, {%4,%5,%6,%7}, {%8,%9}, {%0,%1,%2,%3};\n"
        : "+f"(d[0]), "+f"(d[1]), "+f"(d[2]), "+f"(d[3])
        : "r"(a0), "r"(a1), "r"(a2), "r"(a3), "r"(b0), "r"(b1));
}

// ---------------------------------------------------------------------------
// Tensor-core GEMM: C[256,4096] = A[256,4096] @ B[4096,N] (row stride ldb).
// CTA tile 64x128, BK=32, 8 warps (warp tile 32x32), register-prefetch
// double buffering, tf32-RN staged in smem.
// Grid: (32, 4).
// ---------------------------------------------------------------------------
__global__ __launch_bounds__(256) void gemm_tc(const float* __restrict__ A,
                                               const float* __restrict__ B,
                                               float* __restrict__ C, int ldb)
{
    __shared__ float As[64][36];
    __shared__ float Bs[32][132];

    const int tid  = threadIdx.x;
    const int lane = tid & 31, wid = tid >> 5;
    const int gid  = lane >> 2, tig = lane & 3;
    const int wm   = wid >> 2, wn = wid & 3;        // warp 32m x 32n
    const int bx   = blockIdx.x, by = blockIdx.y;

    const float* Ab = A + (size_t)(by * 64) * HID;
    const float* Bb = B + (size_t)(bx * 128);

    const int arow = tid >> 2;          // 0..63
    const int acol = (tid & 3) * 8;     // 0,8,16,24
    const int brow = tid >> 3;          // 0..31
    const int bcol = (tid & 7) * 16;    // 0..112

    float acc[2][4][4];
#pragma unroll
    for (int mt = 0; mt < 2; mt++)
#pragma unroll
        for (int nt = 0; nt < 4; nt++)
#pragma unroll
            for (int i = 0; i < 4; i++) acc[mt][nt][i] = 0.f;

    float4 aR0, aR1, bR0, bR1, bR2, bR3;
    // prologue: k0 = 0
    aR0 = *(const float4*)(Ab + (size_t)arow * HID + acol);
    aR1 = *(const float4*)(Ab + (size_t)arow * HID + acol + 4);
    bR0 = *(const float4*)(Bb + (size_t)brow * ldb + bcol);
    bR1 = *(const float4*)(Bb + (size_t)brow * ldb + bcol + 4);
    bR2 = *(const float4*)(Bb + (size_t)brow * ldb + bcol + 8);
    bR3 = *(const float4*)(Bb + (size_t)brow * ldb + bcol + 12);

    const int NK = HID / 32;
    for (int kt = 0; kt < NK; kt++) {
        if (kt) __syncthreads();
        // stage with tf32-RN
        As[arow][acol + 0] = rna(aR0.x); As[arow][acol + 1] = rna(aR0.y);
        As[arow][acol + 2] = rna(aR0.z); As[arow][acol + 3] = rna(aR0.w);
        As[arow][acol + 4] = rna(aR1.x); As[arow][acol + 5] = rna(aR1.y);
        As[arow][acol + 6] = rna(aR1.z); As[arow][acol + 7] = rna(aR1.w);
        Bs[brow][bcol + 0]  = rna(bR0.x); Bs[brow][bcol + 1]  = rna(bR0.y);
        Bs[brow][bcol + 2]  = rna(bR0.z); Bs[brow][bcol + 3]  = rna(bR0.w);
        Bs[brow][bcol + 4]  = rna(bR1.x); Bs[brow][bcol + 5]  = rna(bR1.y);
        Bs[brow][bcol + 6]  = rna(bR1.z); Bs[brow][bcol + 7]  = rna(bR1.w);
        Bs[brow][bcol + 8]  = rna(bR2.x); Bs[brow][bcol + 9]  = rna(bR2.y);
        Bs[brow][bcol + 10] = rna(bR2.z); Bs[brow][bcol + 11] = rna(bR2.w);
        Bs[brow][bcol + 12] = rna(bR3.x); Bs[brow][bcol + 13] = rna(bR3.y);
        Bs[brow][bcol + 14] = rna(bR3.z); Bs[brow][bcol + 15] = rna(bR3.w);
        __syncthreads();
        if (kt + 1 < NK) {
            int k0 = (kt + 1) * 32;
            aR0 = *(const float4*)(Ab + (size_t)arow * HID + k0 + acol);
            aR1 = *(const float4*)(Ab + (size_t)arow * HID + k0 + acol + 4);
            bR0 = *(const float4*)(Bb + (size_t)(k0 + brow) * ldb + bcol);
            bR1 = *(const float4*)(Bb + (size_t)(k0 + brow) * ldb + bcol + 4);
            bR2 = *(const float4*)(Bb + (size_t)(k0 + brow) * ldb + bcol + 8);
            bR3 = *(const float4*)(Bb + (size_t)(k0 + brow) * ldb + bcol + 12);
        }
#pragma unroll
        for (int k8 = 0; k8 < 4; k8++) {
            const int kk = k8 * 8;
            uint32_t a[2][4];
#pragma unroll
            for (int mt = 0; mt < 2; mt++) {
                const int rm = wm * 32 + mt * 16;
                a[mt][0] = __float_as_uint(As[rm + gid][kk + tig]);
                a[mt][1] = __float_as_uint(As[rm + gid + 8][kk + tig]);
                a[mt][2] = __float_as_uint(As[rm + gid][kk + tig + 4]);
                a[mt][3] = __float_as_uint(As[rm + gid + 8][kk + tig + 4]);
            }
#pragma unroll
            for (int nt = 0; nt < 4; nt++) {
                const int cn = wn * 32 + nt * 8;
                uint32_t b0 = __float_as_uint(Bs[kk + tig][cn + gid]);
                uint32_t b1 = __float_as_uint(Bs[kk + tig + 4][cn + gid]);
                mma_tf32(acc[0][nt], a[0][0], a[0][1], a[0][2], a[0][3], b0, b1);
                mma_tf32(acc[1][nt], a[1][0], a[1][1], a[1][2], a[1][3], b0, b1);
            }
        }
    }
#pragma unroll
    for (int mt = 0; mt < 2; mt++) {
        const int row = by * 64 + wm * 32 + mt * 16 + gid;
#pragma unroll
        for (int nt = 0; nt < 4; nt++) {
            const int col = bx * 128 + wn * 32 + nt * 8 + 2 * tig;
            *(float2*)(C + (size_t)row * HID + col) =
                make_float2(acc[mt][nt][0], acc[mt][nt][1]);
            *(float2*)(C + (size_t)(row + 8) * HID + col) =
                make_float2(acc[mt][nt][2], acc[mt][nt][3]);
        }
    }
}

// ---------------------------------------------------------------------------
// Q: double RMSNorm + RoPE + fold 1/sqrt(D). One warp per (b,q,h) head row.
// ---------------------------------------------------------------------------
__global__ __launch_bounds__(256) void qnorm_rope_k(const float* __restrict__ cosb,
                                                    const float* __restrict__ sinb,
                                                    const float* __restrict__ w)
{
    const int gw   = (blockIdx.x * 256 + threadIdx.x) >> 5;   // 0..8191
    const int lane = threadIdx.x & 31;
    const int h = gw & 31;
    const int q = (gw >> 5) & 63;
    const int b = gw >> 11;

    const float* src = g_qraw + (size_t)(b * QL + q) * HID + h * HD + lane * 4;
    float4 x4 = *(const float4*)src;
    float  x[4] = {x4.x, x4.y, x4.z, x4.w};
    float4 w4 = *(const float4*)(w + lane * 4);
    float  wv[4] = {w4.x, w4.y, w4.z, w4.w};

    float ss = x[0]*x[0] + x[1]*x[1] + x[2]*x[2] + x[3]*x[3];
#pragma unroll
    for (int o = 16; o > 0; o >>= 1) ss += __shfl_xor_sync(0xffffffffu, ss, o);
    float r1 = rsqrtf(ss * (1.f / 128.f) + EPSR);

    float y[4];
#pragma unroll
    for (int j = 0; j < 4; j++) y[j] = x[j] * r1 * wv[j];

    float ss2 = y[0]*y[0] + y[1]*y[1] + y[2]*y[2] + y[3]*y[3];
#pragma unroll
    for (int o = 16; o > 0; o >>= 1) ss2 += __shfl_xor_sync(0xffffffffu, ss2, o);
    float r2 = rsqrtf(ss2 * (1.f / 128.f) + EPSR);

    float z[4];
#pragma unroll
    for (int j = 0; j < 4; j++) z[j] = y[j] * r2 * wv[j];

    const float* cp = cosb + (size_t)(CTX + q) * HD + lane * 4;
    const float* sp = sinb + (size_t)(CTX + q) * HD + lane * 4;
    float4 c4 = *(const float4*)cp;
    float4 s4 = *(const float4*)sp;
    float cf[4] = {c4.x, c4.y, c4.z, c4.w};
    float sf[4] = {s4.x, s4.y, s4.z, s4.w};

    float o_[4];
#pragma unroll
    for (int j = 0; j < 4; j++) {
        float p   = __shfl_xor_sync(0xffffffffu, z[j], 16);
        float rot = (lane < 16) ? -p : p;
        o_[j] = (z[j] * cf[j] + rot * sf[j]) * INV_SQRT_D;
    }
    float* dst = g_q + (size_t)((b * NH + h) * QL + q) * HD + lane * 4;
    *(float4*)dst = make_float4(o_[0], o_[1], o_[2], o_[3]);
}

// ---------------------------------------------------------------------------
// Tensor-core flash attention. One CTA per (b,h), 8 warps.
// 33 chunks of 128 keys. Warp wid: key-group wg=wid>>2 (64-key half),
// query rows r0=16*(wid&3). Online softmax in fragments, P staged through
// per-warp smem for the C->A layout turn, 2 key groups merged at the end.
// ---------------------------------------------------------------------------
#define ATTN_SMEM_FLOATS (64*132 + 128*132 + 128*132 + 8*16*68 + 256)
#define ATTN_SMEM_BYTES  (ATTN_SMEM_FLOATS * 4)

__global__ __launch_bounds__(256) void attn_tc(const float* __restrict__ th,
                                               const float* __restrict__ hs,
                                               const float* __restrict__ cosb,
                                               const float* __restrict__ sinb)
{
    extern __shared__ float sm[];
    float* Qs   = sm;                       // [64][132]
    float* Ks   = Qs + 64 * 132;            // [128][132] roped K
    float* Vr   = Ks + 128 * 132;           // [128][132] raw V
    float* Ps   = Vr + 128 * 132;           // [8 warps][16][68]
    float* mred = Ps + 8 * 16 * 68;         // [2][64]
    float* lred = mred + 128;               // [2][64]
    float* Osm  = Ks;                       // overlay for final merge

    const int bh = blockIdx.x, h = bh & 31, b = bh >> 5;
    const int tid = threadIdx.x, lane = tid & 31, wid = tid >> 5;
    const int gid = lane >> 2, tig = lane & 3;
    const int wg = wid >> 2;                 // key half group 0/1
    const int r0 = (wid & 3) * 16;           // query row base
    const int j0 = wg * 64;                  // key base in chunk
    float* Pw = Ps + wid * 16 * 68;

    // Load Q (tf32-rounded)
    const float* qsrc = g_q + (size_t)bh * (QL * HD);
    for (int e = tid * 4; e < QL * HD; e += 1024) {
        int row = e >> 7, dd = e & 127;
        float4 v = *(const float4*)(qsrc + e);
        float* dst = &Qs[row * 132 + dd];
        dst[0] = rna(v.x); dst[1] = rna(v.y); dst[2] = rna(v.z); dst[3] = rna(v.w);
    }

    float m_lo = -1e30f, m_hi = -1e30f, l_lo = 0.f, l_hi = 0.f;
    float oacc[16][4];
#pragma unroll
    for (int nt = 0; nt < 16; nt++)
#pragma unroll
        for (int i = 0; i < 4; i++) oacc[nt][i] = 0.f;

    const float* thb = th + (size_t)b * CTX * HID + h * HD;
    const float* hsb = hs + (size_t)b * QL  * HID + h * HD;

    for (int t = 0; t < 33; t++) {
        const int p0 = t * 128;

        // ---- load raw KV chunk -> Vr
        for (int e = tid * 4; e < 128 * 128; e += 1024) {
            int j = e >> 7, dd = e & 127;
            int p = p0 + j;
            float4 v;
            if (p < CTX)      v = *(const float4*)(thb + (size_t)p * HID + dd);
            else if (p < TOT) v = *(const float4*)(hsb + (size_t)(p - CTX) * HID + dd);
            else              v = make_float4(0.f, 0.f, 0.f, 0.f);
            float* dst = &Vr[j * 132 + dd];
            dst[0] = rna(v.x); dst[1] = rna(v.y); dst[2] = rna(v.z); dst[3] = rna(v.w);
        }
        __syncthreads();

        // ---- rope K -> Ks
        for (int e = tid * 4; e < 128 * 128; e += 1024) {
            int j = e >> 7, dd = e & 127;
            int p = p0 + j;
            float4 v = *(float4*)&Vr[j * 132 + dd];
            float4 q = *(float4*)&Vr[j * 132 + (dd ^ 64)];
            float4 c, s;
            if (p < TOT) {
                c = *(const float4*)(cosb + (size_t)p * HD + dd);
                s = *(const float4*)(sinb + (size_t)p * HD + dd);
            } else {
                c = make_float4(0.f, 0.f, 0.f, 0.f);
                s = make_float4(0.f, 0.f, 0.f, 0.f);
            }
            float sgn = (dd < 64) ? -1.f : 1.f;
            float* dst = &Ks[j * 132 + dd];
            dst[0] = rna(v.x * c.x + sgn * q.x * s.x);
            dst[1] = rna(v.y * c.y + sgn * q.y * s.y);
            dst[2] = rna(v.z * c.z + sgn * q.z * s.z);
            dst[3] = rna(v.w * c.w + sgn * q.w * s.w);
        }
        __syncthreads();

        // ---- QK^T : S[16 rows][64 keys] per warp
        float sacc[8][4];
#pragma unroll
        for (int nt = 0; nt < 8; nt++)
#pragma unroll
            for (int i = 0; i < 4; i++) sacc[nt][i] = 0.f;

#pragma unroll
        for (int kt = 0; kt < 16; kt++) {
            const int kk = kt * 8;
            uint32_t a0 = __float_as_uint(Qs[(r0 + gid) * 132 + kk + tig]);
            uint32_t a1 = __float_as_uint(Qs[(r0 + gid + 8) * 132 + kk + tig]);
            uint32_t a2 = __float_as_uint(Qs[(r0 + gid) * 132 + kk + tig + 4]);
            uint32_t a3 = __float_as_uint(Qs[(r0 + gid + 8) * 132 + kk + tig + 4]);
#pragma unroll
            for (int nt = 0; nt < 8; nt++) {
                uint32_t b0 = __float_as_uint(Ks[(j0 + nt * 8 + gid) * 132 + kk + tig]);
                uint32_t b1 = __float_as_uint(Ks[(j0 + nt * 8 + gid) * 132 + kk + tig + 4]);
                mma_tf32(sacc[nt], a0, a1, a2, a3, b0, b1);
            }
        }

        // ---- mask tail
        if (p0 + 128 > TOT) {
#pragma unroll
            for (int nt = 0; nt < 8; nt++) {
                int jg = p0 + j0 + nt * 8 + 2 * tig;
                if (jg     >= TOT) { sacc[nt][0] = -1e30f; sacc[nt][2] = -1e30f; }
                if (jg + 1 >= TOT) { sacc[nt][1] = -1e30f; sacc[nt][3] = -1e30f; }
            }
        }

        // ---- online softmax (rows r0+gid and r0+gid+8)
        float mx_lo = -1e30f, mx_hi = -1e30f;
#pragma unroll
        for (int nt = 0; nt < 8; nt++) {
            mx_lo = fmaxf(mx_lo, fmaxf(sacc[nt][0], sacc[nt][1]));
            mx_hi = fmaxf(mx_hi, fmaxf(sacc[nt][2], sacc[nt][3]));
        }
        mx_lo = fmaxf(mx_lo, __shfl_xor_sync(0xffffffffu, mx_lo, 1));
        mx_lo = fmaxf(mx_lo, __shfl_xor_sync(0xffffffffu, mx_lo, 2));
        mx_hi = fmaxf(mx_hi, __shfl_xor_sync(0xffffffffu, mx_hi, 1));
        mx_hi = fmaxf(mx_hi, __shfl_xor_sync(0xffffffffu, mx_hi, 2));

        float nm_lo = fmaxf(m_lo, mx_lo), nm_hi = fmaxf(m_hi, mx_hi);
        float al_lo = __expf(m_lo - nm_lo), al_hi = __expf(m_hi - nm_hi);
        float sum_lo = 0.f, sum_hi = 0.f;
#pragma unroll
        for (int nt = 0; nt < 8; nt++) {
            float e0 = rna(__expf(sacc[nt][0] - nm_lo));
            float e1 = rna(__expf(sacc[nt][1] - nm_lo));
            float e2 = rna(__expf(sacc[nt][2] - nm_hi));
            float e3 = rna(__expf(sacc[nt][3] - nm_hi));
            sum_lo += e0 + e1;  sum_hi += e2 + e3;
            *(float2*)&Pw[gid * 68 + nt * 8 + 2 * tig]       = make_float2(e0, e1);
            *(float2*)&Pw[(gid + 8) * 68 + nt * 8 + 2 * tig] = make_float2(e2, e3);
        }
        sum_lo += __shfl_xor_sync(0xffffffffu, sum_lo, 1);
        sum_lo += __shfl_xor_sync(0xffffffffu, sum_lo, 2);
        sum_hi += __shfl_xor_sync(0xffffffffu, sum_hi, 1);
        sum_hi += __shfl_xor_sync(0xffffffffu, sum_hi, 2);
        l_lo = l_lo * al_lo + sum_lo;  l_hi = l_hi * al_hi + sum_hi;
        m_lo = nm_lo;  m_hi = nm_hi;

#pragma unroll
        for (int nt = 0; nt < 16; nt++) {
            oacc[nt][0] *= al_lo; oacc[nt][1] *= al_lo;
            oacc[nt][2] *= al_hi; oacc[nt][3] *= al_hi;
        }
        __syncwarp();

        // ---- PV : O[16 rows][128 d] += P[16][64] @ V[64][128]
#pragma unroll
        for (int kt = 0; kt < 8; kt++) {
            const int kk = kt * 8;
            uint32_t a0 = __float_as_uint(Pw[gid * 68 + kk + tig]);
            uint32_t a1 = __float_as_uint(Pw[(gid + 8) * 68 + kk + tig]);
            uint32_t a2 = __float_as_uint(Pw[gid * 68 + kk + tig + 4]);
            uint32_t a3 = __float_as_uint(Pw[(gid + 8) * 68 + kk + tig + 4]);
#pragma unroll
            for (int nt = 0; nt < 16; nt++) {
                uint32_t b0 = __float_as_uint(Vr[(j0 + kk + tig) * 132 + nt * 8 + gid]);
                uint32_t b1 = __float_as_uint(Vr[(j0 + kk + tig + 4) * 132 + nt * 8 + gid]);
                mma_tf32(oacc[nt], a0, a1, a2, a3, b0, b1);
            }
        }
        __syncthreads();  // Ks/Vr about to be overwritten
    }

    // ---- merge the two key groups
    if (tig == 0) {
        mred[wg * 64 + r0 + gid]     = m_lo;
        mred[wg * 64 + r0 + gid + 8] = m_hi;
        lred[wg * 64 + r0 + gid]     = l_lo;
        lred[wg * 64 + r0 + gid + 8] = l_hi;
    }
    __syncthreads();
    const int rlo = r0 + gid, rhi = r0 + gid + 8;
    float M_lo = fmaxf(mred[rlo], mred[64 + rlo]);
    float M_hi = fmaxf(mred[rhi], mred[64 + rhi]);
    float Lt_lo = lred[rlo] * __expf(mred[rlo] - M_lo)
                + lred[64 + rlo] * __expf(mred[64 + rlo] - M_lo);
    float Lt_hi = lred[rhi] * __expf(mred[rhi] - M_hi)
                + lred[64 + rhi] * __expf(mred[64 + rhi] - M_hi);
    float sc_lo = __expf(m_lo - M_lo) / Lt_lo;
    float sc_hi = __expf(m_hi - M_hi) / Lt_hi;
#pragma unroll
    for (int nt = 0; nt < 16; nt++) {
        oacc[nt][0] *= sc_lo; oacc[nt][1] *= sc_lo;
        oacc[nt][2] *= sc_hi; oacc[nt][3] *= sc_hi;
    }
    __syncthreads();
    if (wg == 0) {
#pragma unroll
        for (int nt = 0; nt < 16; nt++) {
            *(float2*)&Osm[rlo * 132 + nt * 8 + 2 * tig] = make_float2(oacc[nt][0], oacc[nt][1]);
            *(float2*)&Osm[rhi * 132 + nt * 8 + 2 * tig] = make_float2(oacc[nt][2], oacc[nt][3]);
        }
    }
    __syncthreads();
    if (wg == 1) {
#pragma unroll
        for (int nt = 0; nt < 16; nt++) {
            const int col = nt * 8 + 2 * tig;
            float2 v0 = *(float2*)&Osm[rlo * 132 + col];
            float2 v1 = *(float2*)&Osm[rhi * 132 + col];
            *(float2*)(g_attn + (size_t)(b * QL + rlo) * HID + h * HD + col) =
                make_float2(oacc[nt][0] + v0.x, oacc[nt][1] + v0.y);
            *(float2*)(g_attn + (size_t)(b * QL + rhi) * HID + h * HD + col) =
                make_float2(oacc[nt][2] + v1.x, oacc[nt][3] + v1.y);
        }
    }
}

// ---------------------------------------------------------------------------
extern "C" void kernel_launch(void* const* d_in, const int* in_sizes, int n_in,
                              void* d_out, int out_size)
{
    const float* hs   = (const float*)d_in[0];   // hidden_states  [4,64,4096]
    const float* th   = (const float*)d_in[1];   // target_hidden  [4,4096,4096]
    const float* cosb = (const float*)d_in[2];   // [4160,128]
    const float* sinb = (const float*)d_in[3];   // [4160,128]
    const float* Wqkv = (const float*)d_in[4];   // [4096,12288]
    const float* Wo   = (const float*)d_in[5];   // [4096,4096]
    const float* qw   = (const float*)d_in[6];   // [128]
    float* out = (float*)d_out;

    float *qraw_p, *attn_p;
    cudaGetSymbolAddress((void**)&qraw_p, g_qraw);
    cudaGetSymbolAddress((void**)&attn_p, g_attn);

    cudaFuncSetAttribute(attn_tc, cudaFuncAttributeMaxDynamicSharedMemorySize,
                         ATTN_SMEM_BYTES);

    dim3 gg(32, 4);
    // 1) Q projection (first 4096 cols of Wqkv only)
    gemm_tc<<<gg, 256>>>(hs, Wqkv, qraw_p, 3 * HID);
    // 2) double RMSNorm + RoPE + scale fold
    qnorm_rope_k<<<1024, 256>>>(cosb, sinb, qw);
    // 3) tensor-core flash attention
    attn_tc<<<NB * NH, 256, ATTN_SMEM_BYTES>>>(th, hs, cosb, sinb);
    // 4) output projection
    gemm_tc<<<gg, 256>>>(attn_p, Wo, out, HID);
}

// round 4
// speedup vs baseline: 2.1570x; 1.2086x over previous
#include <cuda_runtime.h>
#include <cuda_fp16.h>
#include <math.h>
#include <stdint.h>

#define NB    4
#define QL    64
#define NH    32
#define HD    128
#define CTX   4096
#define TOT   4160
#define HID   4096
#define EPSR  1e-6f
#define INV_SQRT_D 0.08838834764831843f

__device__ float g_qraw[NB * QL * HID];
__device__ float g_q   [NB * NH * QL * HD];
__device__ float g_attn[NB * QL * HID];

// ---------------------------------------------------------------------------
// helpers
// ---------------------------------------------------------------------------
__device__ __forceinline__ uint32_t smaddr(const void* p) {
    return (uint32_t)__cvta_generic_to_shared(p);
}
__device__ __forceinline__ void ldsm4(uint32_t& r0, uint32_t& r1, uint32_t& r2, uint32_t& r3, uint32_t a) {
    asm volatile("ldmatrix.sync.aligned.m8n8.x4.shared.b16 {%0,%1,%2,%3}, [%4];"
                 : "=r"(r0), "=r"(r1), "=r"(r2), "=r"(r3) : "r"(a));
}
__device__ __forceinline__ void ldsm4t(uint32_t& r0, uint32_t& r1, uint32_t& r2, uint32_t& r3, uint32_t a) {
    asm volatile("ldmatrix.sync.aligned.m8n8.x4.trans.shared.b16 {%0,%1,%2,%3}, [%4];"
                 : "=r"(r0), "=r"(r1), "=r"(r2), "=r"(r3) : "r"(a));
}
__device__ __forceinline__ void mma16816(float d[4],
                                         uint32_t a0, uint32_t a1, uint32_t a2, uint32_t a3,
                                         uint32_t b0, uint32_t b1) {
    asm volatile(
        "mma.sync.aligned.m16n8k16.row.col.f32.f16.f16.f32 "
        "{%0,%1,%2,%3},{%4,%5,%6,%7},{%8,%9},{%0,%1,%2,%3};"
        : "+f"(d[0]), "+f"(d[1]), "+f"(d[2]), "+f"(d[3])
        : "r"(a0), "r"(a1), "r"(a2), "r"(a3), "r"(b0), "r"(b1));
}
__device__ __forceinline__ uint32_t pack2(float x, float y) {
    __half2 h = __floats2half2_rn(x, y);
    return *(uint32_t*)&h;
}

// ---------------------------------------------------------------------------
// fp16 tensor-core GEMM: C[256,4096] = A[256,4096] @ B[4096,*ldb*]
// BM=32, BN=128, BK=32, 8 warps (warp tile 32m x 16n), grid (32,8)=256 CTAs,
// double-buffered smem (1 sync/iter), ldmatrix fragments.
// ---------------------------------------------------------------------------
__global__ __launch_bounds__(256) void hgemm_tc(const float* __restrict__ A,
                                                const float* __restrict__ B,
                                                float* __restrict__ C, int ldb)
{
    __shared__ half As[2][32][40];     // row stride 80B  (5x16B -> LDSM conflict-free)
    __shared__ half Bs[2][32][136];    // row stride 272B (17x16B -> conflict-free)

    const int tid = threadIdx.x, lane = tid & 31, wid = tid >> 5;
    const int gid = lane >> 2, tig = lane & 3;
    const int bx = blockIdx.x, by = blockIdx.y;
    const int n0 = wid * 16;

    const float* Ab = A + (size_t)(by * 32) * HID;
    const float* Bb = B + (size_t)(bx * 128);

    const int arow = tid >> 3, acol = (tid & 7) * 4;
    const int brow = tid >> 3, bcol = (tid & 7) * 16;

    float acc[2][2][4];
#pragma unroll
    for (int mt = 0; mt < 2; mt++)
#pragma unroll
        for (int nt = 0; nt < 2; nt++)
#pragma unroll
            for (int i = 0; i < 4; i++) acc[mt][nt][i] = 0.f;

    const uint32_t aAddr0 = smaddr(&As[0][lane & 15][8 * (lane >> 4)]);
    const uint32_t bAddr0 = smaddr(&Bs[0][(lane & 7) + 8 * ((lane >> 3) & 1)][n0 + 8 * (lane >> 4)]);
    const uint32_t ABUFB = 32 * 40 * 2;    // 2560
    const uint32_t BBUFB = 32 * 136 * 2;   // 8704

    float4 aR, bR0, bR1, bR2, bR3;
    aR  = *(const float4*)(Ab + (size_t)arow * HID + acol);
    bR0 = *(const float4*)(Bb + (size_t)brow * ldb + bcol);
    bR1 = *(const float4*)(Bb + (size_t)brow * ldb + bcol + 4);
    bR2 = *(const float4*)(Bb + (size_t)brow * ldb + bcol + 8);
    bR3 = *(const float4*)(Bb + (size_t)brow * ldb + bcol + 12);

    // stage buf 0
    {
        __half2 t0 = __floats2half2_rn(aR.x, aR.y), t1 = __floats2half2_rn(aR.z, aR.w);
        *(uint2*)&As[0][arow][acol] = make_uint2(*(uint32_t*)&t0, *(uint32_t*)&t1);
        uint4 u;
        u.x = pack2(bR0.x, bR0.y); u.y = pack2(bR0.z, bR0.w);
        u.z = pack2(bR1.x, bR1.y); u.w = pack2(bR1.z, bR1.w);
        *(uint4*)&Bs[0][brow][bcol] = u;
        u.x = pack2(bR2.x, bR2.y); u.y = pack2(bR2.z, bR2.w);
        u.z = pack2(bR3.x, bR3.y); u.w = pack2(bR3.z, bR3.w);
        *(uint4*)&Bs[0][brow][bcol + 8] = u;
    }
    __syncthreads();

    const int NK = HID / 32;
    for (int kt = 0; kt < NK; kt++) {
        if (kt + 1 < NK) {
            const int k0 = (kt + 1) * 32;
            aR  = *(const float4*)(Ab + (size_t)arow * HID + k0 + acol);
            bR0 = *(const float4*)(Bb + (size_t)(k0 + brow) * ldb + bcol);
            bR1 = *(const float4*)(Bb + (size_t)(k0 + brow) * ldb + bcol + 4);
            bR2 = *(const float4*)(Bb + (size_t)(k0 + brow) * ldb + bcol + 8);
            bR3 = *(const float4*)(Bb + (size_t)(k0 + brow) * ldb + bcol + 12);
        }
        const int cur = kt & 1;
        const uint32_t aA = aAddr0 + cur * ABUFB;
        const uint32_t bA = bAddr0 + cur * BBUFB;
#pragma unroll
        for (int kk = 0; kk < 2; kk++) {
            uint32_t x0, x1, x2, x3, y0, y1, y2, y3, b0, b1, b2, b3;
            ldsm4 (x0, x1, x2, x3, aA + kk * 32);
            ldsm4 (y0, y1, y2, y3, aA + kk * 32 + 16 * 80);
            ldsm4t(b0, b1, b2, b3, bA + kk * 16 * 272);
            mma16816(acc[0][0], x0, x1, x2, x3, b0, b1);
            mma16816(acc[0][1], x0, x1, x2, x3, b2, b3);
            mma16816(acc[1][0], y0, y1, y2, y3, b0, b1);
            mma16816(acc[1][1], y0, y1, y2, y3, b2, b3);
        }
        if (kt + 1 < NK) {
            const int nxt = cur ^ 1;
            __half2 t0 = __floats2half2_rn(aR.x, aR.y), t1 = __floats2half2_rn(aR.z, aR.w);
            *(uint2*)&As[nxt][arow][acol] = make_uint2(*(uint32_t*)&t0, *(uint32_t*)&t1);
            uint4 u;
            u.x = pack2(bR0.x, bR0.y); u.y = pack2(bR0.z, bR0.w);
            u.z = pack2(bR1.x, bR1.y); u.w = pack2(bR1.z, bR1.w);
            *(uint4*)&Bs[nxt][brow][bcol] = u;
            u.x = pack2(bR2.x, bR2.y); u.y = pack2(bR2.z, bR2.w);
            u.z = pack2(bR3.x, bR3.y); u.w = pack2(bR3.z, bR3.w);
            *(uint4*)&Bs[nxt][brow][bcol + 8] = u;
            __syncthreads();
        }
    }

#pragma unroll
    for (int mt = 0; mt < 2; mt++) {
        const int row = by * 32 + mt * 16 + gid;
#pragma unroll
        for (int nt = 0; nt < 2; nt++) {
            const int col = bx * 128 + n0 + nt * 8 + 2 * tig;
            *(float2*)(C + (size_t)row * HID + col) =
                make_float2(acc[mt][nt][0], acc[mt][nt][1]);
            *(float2*)(C + (size_t)(row + 8) * HID + col) =
                make_float2(acc[mt][nt][2], acc[mt][nt][3]);
        }
    }
}

// ---------------------------------------------------------------------------
// Q: double RMSNorm + RoPE + fold 1/sqrt(D). One warp per (b,q,h) head row.
// ---------------------------------------------------------------------------
__global__ __launch_bounds__(256) void qnorm_rope_k(const float* __restrict__ cosb,
                                                    const float* __restrict__ sinb,
                                                    const float* __restrict__ w)
{
    const int gw   = (blockIdx.x * 256 + threadIdx.x) >> 5;
    const int lane = threadIdx.x & 31;
    const int h = gw & 31;
    const int q = (gw >> 5) & 63;
    const int b = gw >> 11;

    const float* src = g_qraw + (size_t)(b * QL + q) * HID + h * HD + lane * 4;
    float4 x4 = *(const float4*)src;
    float  x[4] = {x4.x, x4.y, x4.z, x4.w};
    float4 w4 = *(const float4*)(w + lane * 4);
    float  wv[4] = {w4.x, w4.y, w4.z, w4.w};

    float ss = x[0]*x[0] + x[1]*x[1] + x[2]*x[2] + x[3]*x[3];
#pragma unroll
    for (int o = 16; o > 0; o >>= 1) ss += __shfl_xor_sync(0xffffffffu, ss, o);
    float r1 = rsqrtf(ss * (1.f / 128.f) + EPSR);

    float y[4];
#pragma unroll
    for (int j = 0; j < 4; j++) y[j] = x[j] * r1 * wv[j];

    float ss2 = y[0]*y[0] + y[1]*y[1] + y[2]*y[2] + y[3]*y[3];
#pragma unroll
    for (int o = 16; o > 0; o >>= 1) ss2 += __shfl_xor_sync(0xffffffffu, ss2, o);
    float r2 = rsqrtf(ss2 * (1.f / 128.f) + EPSR);

    float z[4];
#pragma unroll
    for (int j = 0; j < 4; j++) z[j] = y[j] * r2 * wv[j];

    const float4 c4 = *(const float4*)(cosb + (size_t)(CTX + q) * HD + lane * 4);
    const float4 s4 = *(const float4*)(sinb + (size_t)(CTX + q) * HD + lane * 4);
    const float cf[4] = {c4.x, c4.y, c4.z, c4.w};
    const float sf[4] = {s4.x, s4.y, s4.z, s4.w};

    float o_[4];
#pragma unroll
    for (int j = 0; j < 4; j++) {
        float p   = __shfl_xor_sync(0xffffffffu, z[j], 16);
        float rot = (lane < 16) ? -p : p;
        o_[j] = (z[j] * cf[j] + rot * sf[j]) * INV_SQRT_D;
    }
    float* dst = g_q + (size_t)((b * NH + h) * QL + q) * HD + lane * 4;
    *(float4*)dst = make_float4(o_[0], o_[1], o_[2], o_[3]);
}

// ---------------------------------------------------------------------------
// fp16 tensor-core flash attention.
// Grid 256 = (b, h, q-half of 32 rows). 8 warps = 2 q-tiles x 4 key stripes.
// Chunk = 128 keys; stripe = 32 keys/warp. P stays in registers (c-frag->a-frag).
// 4-way key-group merge through smem at the end.
// ---------------------------------------------------------------------------
#define ASMEM_BYTES (78336 + 1024)

__global__ __launch_bounds__(256, 2) void attn_h(const float* __restrict__ th,
                                                 const float* __restrict__ hs,
                                                 const float* __restrict__ cosb,
                                                 const float* __restrict__ sinb)
{
    extern __shared__ char smc[];
    half* Qs = (half*)smc;              // [32][136]
    half* Ks = Qs + 32 * 136;           // [128][136] roped K
    half* Vr = Ks + 128 * 136;          // [128][136] raw V
    float* mred = (float*)(smc + 78336);  // [4][32]
    float* lred = mred + 128;             // [4][32]
    float* Osm  = (float*)Ks;             // [32][132] overlay after mainloop

    const int bi = blockIdx.x;
    const int qh = bi & 1, h = (bi >> 1) & 31, b = bi >> 6;
    const int qb = qh * 32;
    const int tid = threadIdx.x, lane = tid & 31, wid = tid >> 5;
    const int gid = lane >> 2, tig = lane & 3;
    const int wq = wid >> 2, wg = wid & 3;
    const int r0 = wq * 16, j0 = wg * 32;

    // load Q (fp16)
    const float* qsrc = g_q + ((size_t)(b * NH + h) * QL + qb) * HD;
    for (int e = tid * 4; e < 32 * 128; e += 1024) {
        int j = e >> 7, dd = e & 127;
        float4 v = *(const float4*)(qsrc + j * 128 + dd);
        *(uint2*)&Qs[j * 136 + dd] = make_uint2(pack2(v.x, v.y), pack2(v.z, v.w));
    }

    float m_lo = -1e30f, m_hi = -1e30f, l_lo = 0.f, l_hi = 0.f;
    float oacc[16][4];
#pragma unroll
    for (int nt = 0; nt < 16; nt++)
#pragma unroll
        for (int i = 0; i < 4; i++) oacc[nt][i] = 0.f;

    const float* thb = th + (size_t)b * CTX * HID + h * HD;
    const float* hsb = hs + (size_t)b * QL  * HID + h * HD;

    const uint32_t qA = smaddr(&Qs[(r0 + (lane & 15)) * 136 + 8 * (lane >> 4)]);
    const uint32_t kA = smaddr(&Ks[(j0 + (lane & 7) + 8 * (lane >> 4)) * 136 + 8 * ((lane >> 3) & 1)]);
    const uint32_t vA = smaddr(&Vr[(j0 + (lane & 7) + 8 * ((lane >> 3) & 1)) * 136 + 8 * (lane >> 4)]);

    for (int t = 0; t < 33; t++) {
        const int p0 = t * 128;

        // raw KV -> Vr (fp16)
        for (int e = tid * 4; e < 128 * 128; e += 1024) {
            int j = e >> 7, dd = e & 127;
            int p = p0 + j;
            float4 v;
            if (p < CTX)      v = *(const float4*)(thb + (size_t)p * HID + dd);
            else if (p < TOT) v = *(const float4*)(hsb + (size_t)(p - CTX) * HID + dd);
            else              v = make_float4(0.f, 0.f, 0.f, 0.f);
            *(uint2*)&Vr[j * 136 + dd] = make_uint2(pack2(v.x, v.y), pack2(v.z, v.w));
        }
        __syncthreads();

        // rope K -> Ks (fp16)
        for (int e = tid * 4; e < 128 * 128; e += 1024) {
            int j = e >> 7, dd = e & 127;
            int p = p0 + j;
            if (p < TOT) {
                uint2 rv = *(uint2*)&Vr[j * 136 + dd];
                uint2 pv = *(uint2*)&Vr[j * 136 + (dd ^ 64)];
                float2 f0 = __half22float2(*(__half2*)&rv.x);
                float2 f1 = __half22float2(*(__half2*)&rv.y);
                float2 g0 = __half22float2(*(__half2*)&pv.x);
                float2 g1 = __half22float2(*(__half2*)&pv.y);
                float4 c = *(const float4*)(cosb + (size_t)p * HD + dd);
                float4 s = *(const float4*)(sinb + (size_t)p * HD + dd);
                float sgn = (dd < 64) ? -1.f : 1.f;
                float k0 = f0.x * c.x + sgn * g0.x * s.x;
                float k1 = f0.y * c.y + sgn * g0.y * s.y;
                float k2 = f1.x * c.z + sgn * g1.x * s.z;
                float k3 = f1.y * c.w + sgn * g1.y * s.w;
                *(uint2*)&Ks[j * 136 + dd] = make_uint2(pack2(k0, k1), pack2(k2, k3));
            } else {
                *(uint2*)&Ks[j * 136 + dd] = make_uint2(0u, 0u);
            }
        }
        __syncthreads();

        // QK^T: S[16q][32k] per warp
        float sacc[4][4];
#pragma unroll
        for (int nt = 0; nt < 4; nt++)
#pragma unroll
            for (int i = 0; i < 4; i++) sacc[nt][i] = 0.f;

#pragma unroll
        for (int kd = 0; kd < 8; kd++) {
            uint32_t a0, a1, a2, a3;
            ldsm4(a0, a1, a2, a3, qA + kd * 32);
#pragma unroll
            for (int jt = 0; jt < 2; jt++) {
                uint32_t b0, b1, b2, b3;
                ldsm4(b0, b1, b2, b3, kA + jt * 16 * 272 + kd * 32);
                mma16816(sacc[jt * 2],     a0, a1, a2, a3, b0, b1);
                mma16816(sacc[jt * 2 + 1], a0, a1, a2, a3, b2, b3);
            }
        }

        // tail mask
        if (p0 + 128 > TOT) {
#pragma unroll
            for (int nt = 0; nt < 4; nt++) {
                int jg = p0 + j0 + nt * 8 + 2 * tig;
                if (jg     >= TOT) { sacc[nt][0] = -1e30f; sacc[nt][2] = -1e30f; }
                if (jg + 1 >= TOT) { sacc[nt][1] = -1e30f; sacc[nt][3] = -1e30f; }
            }
        }

        // online softmax (rows r0+gid lo, r0+gid+8 hi)
        float mx_lo = -1e30f, mx_hi = -1e30f;
#pragma unroll
        for (int nt = 0; nt < 4; nt++) {
            mx_lo = fmaxf(mx_lo, fmaxf(sacc[nt][0], sacc[nt][1]));
            mx_hi = fmaxf(mx_hi, fmaxf(sacc[nt][2], sacc[nt][3]));
        }
        mx_lo = fmaxf(mx_lo, __shfl_xor_sync(0xffffffffu, mx_lo, 1));
        mx_lo = fmaxf(mx_lo, __shfl_xor_sync(0xffffffffu, mx_lo, 2));
        mx_hi = fmaxf(mx_hi, __shfl_xor_sync(0xffffffffu, mx_hi, 1));
        mx_hi = fmaxf(mx_hi, __shfl_xor_sync(0xffffffffu, mx_hi, 2));

        float nm_lo = fmaxf(m_lo, mx_lo), nm_hi = fmaxf(m_hi, mx_hi);
        float al_lo = __expf(m_lo - nm_lo), al_hi = __expf(m_hi - nm_hi);
        float sum_lo = 0.f, sum_hi = 0.f;
        uint32_t pa0[4], pa1[4];
#pragma unroll
        for (int nt = 0; nt < 4; nt++) {
            float e0 = __expf(sacc[nt][0] - nm_lo);
            float e1 = __expf(sacc[nt][1] - nm_lo);
            float e2 = __expf(sacc[nt][2] - nm_hi);
            float e3 = __expf(sacc[nt][3] - nm_hi);
            sum_lo += e0 + e1;  sum_hi += e2 + e3;
            pa0[nt] = pack2(e0, e1);
            pa1[nt] = pack2(e2, e3);
        }
        sum_lo += __shfl_xor_sync(0xffffffffu, sum_lo, 1);
        sum_lo += __shfl_xor_sync(0xffffffffu, sum_lo, 2);
        sum_hi += __shfl_xor_sync(0xffffffffu, sum_hi, 1);
        sum_hi += __shfl_xor_sync(0xffffffffu, sum_hi, 2);
        l_lo = l_lo * al_lo + sum_lo;  l_hi = l_hi * al_hi + sum_hi;
        m_lo = nm_lo;  m_hi = nm_hi;

#pragma unroll
        for (int nt = 0; nt < 16; nt++) {
            oacc[nt][0] *= al_lo; oacc[nt][1] *= al_lo;
            oacc[nt][2] *= al_hi; oacc[nt][3] *= al_hi;
        }

        // PV: O[16q][128d] += P[16][32] @ V[32][128], P from registers
#pragma unroll
        for (int kc = 0; kc < 2; kc++) {
            uint32_t a0 = pa0[2 * kc], a1 = pa1[2 * kc];
            uint32_t a2 = pa0[2 * kc + 1], a3 = pa1[2 * kc + 1];
#pragma unroll
            for (int dt = 0; dt < 8; dt++) {
                uint32_t b0, b1, b2, b3;
                ldsm4t(b0, b1, b2, b3, vA + kc * 16 * 272 + dt * 32);
                mma16816(oacc[dt * 2],     a0, a1, a2, a3, b0, b1);
                mma16816(oacc[dt * 2 + 1], a0, a1, a2, a3, b2, b3);
            }
        }
        __syncthreads();
    }

    // 4-way key-group merge
    const int rlo = r0 + gid, rhi = r0 + gid + 8;
    if (tig == 0) {
        mred[wg * 32 + rlo] = m_lo;  mred[wg * 32 + rhi] = m_hi;
        lred[wg * 32 + rlo] = l_lo;  lred[wg * 32 + rhi] = l_hi;
    }
    __syncthreads();
    float M_lo = -1e30f, M_hi = -1e30f;
#pragma unroll
    for (int g = 0; g < 4; g++) {
        M_lo = fmaxf(M_lo, mred[g * 32 + rlo]);
        M_hi = fmaxf(M_hi, mred[g * 32 + rhi]);
    }
    float Lt_lo = 0.f, Lt_hi = 0.f;
#pragma unroll
    for (int g = 0; g < 4; g++) {
        Lt_lo += lred[g * 32 + rlo] * __expf(mred[g * 32 + rlo] - M_lo);
        Lt_hi += lred[g * 32 + rhi] * __expf(mred[g * 32 + rhi] - M_hi);
    }
    float sc_lo = __expf(m_lo - M_lo) / Lt_lo;
    float sc_hi = __expf(m_hi - M_hi) / Lt_hi;
#pragma unroll
    for (int nt = 0; nt < 16; nt++) {
        oacc[nt][0] *= sc_lo; oacc[nt][1] *= sc_lo;
        oacc[nt][2] *= sc_hi; oacc[nt][3] *= sc_hi;
    }
    __syncthreads();   // everyone past mainloop; Ks region reusable as Osm

    for (int g = 0; g < 4; g++) {
        if (wg == g) {
#pragma unroll
            for (int nt = 0; nt < 16; nt++) {
                const int col = nt * 8 + 2 * tig;
                float* plo = &Osm[rlo * 132 + col];
                float* phi = &Osm[rhi * 132 + col];
                if (g == 0) {
                    plo[0] = oacc[nt][0]; plo[1] = oacc[nt][1];
                    phi[0] = oacc[nt][2]; phi[1] = oacc[nt][3];
                } else {
                    plo[0] += oacc[nt][0]; plo[1] += oacc[nt][1];
                    phi[0] += oacc[nt][2]; phi[1] += oacc[nt][3];
                }
            }
        }
        __syncthreads();
    }

    for (int e = tid * 4; e < 32 * 128; e += 1024) {
        int r = e >> 7, dd = e & 127;
        float4 v = *(float4*)&Osm[r * 132 + dd];
        *(float4*)(g_attn + (size_t)(b * QL + qb + r) * HID + h * HD + dd) = v;
    }
}

// ---------------------------------------------------------------------------
extern "C" void kernel_launch(void* const* d_in, const int* in_sizes, int n_in,
                              void* d_out, int out_size)
{
    const float* hs   = (const float*)d_in[0];
    const float* th   = (const float*)d_in[1];
    const float* cosb = (const float*)d_in[2];
    const float* sinb = (const float*)d_in[3];
    const float* Wqkv = (const float*)d_in[4];
    const float* Wo   = (const float*)d_in[5];
    const float* qw   = (const float*)d_in[6];
    float* out = (float*)d_out;

    float *qraw_p, *attn_p;
    cudaGetSymbolAddress((void**)&qraw_p, g_qraw);
    cudaGetSymbolAddress((void**)&attn_p, g_attn);

    cudaFuncSetAttribute(attn_h, cudaFuncAttributeMaxDynamicSharedMemorySize,
                         ASMEM_BYTES);

    dim3 gg(32, 8);
    hgemm_tc<<<gg, 256>>>(hs, Wqkv, qraw_p, 3 * HID);
    qnorm_rope_k<<<1024, 256>>>(cosb, sinb, qw);
    attn_h<<<NB * NH * 2, 256, ASMEM_BYTES>>>(th, hs, cosb, sinb);
    hgemm_tc<<<gg, 256>>>(attn_p, Wo, out, HID);
}

// round 5
// speedup vs baseline: 5.0954x; 2.3622x over previous
#include <cuda_runtime.h>
#include <cuda_fp16.h>
#include <math.h>
#include <stdint.h>

#define NB    4
#define QL    64
#define NH    32
#define HD    128
#define CTX   4096
#define TOT   4160
#define HID   4096
#define EPSR  1e-6f
#define INV_SQRT_D 0.08838834764831843f

__device__ float g_qraw[NB * QL * HID];
__device__ float g_q   [NB * NH * QL * HD];
__device__ half  g_hs_h [NB * QL * HID];
__device__ half  g_attn_h[NB * QL * HID];
__device__ half  g_wq_h[HID * HID];
__device__ half  g_wo_h[HID * HID];

// ---------------------------------------------------------------------------
// helpers
// ---------------------------------------------------------------------------
__device__ __forceinline__ uint32_t smaddr(const void* p) {
    return (uint32_t)__cvta_generic_to_shared(p);
}
__device__ __forceinline__ void ldsm4(uint32_t& r0, uint32_t& r1, uint32_t& r2, uint32_t& r3, uint32_t a) {
    asm volatile("ldmatrix.sync.aligned.m8n8.x4.shared.b16 {%0,%1,%2,%3}, [%4];"
                 : "=r"(r0), "=r"(r1), "=r"(r2), "=r"(r3) : "r"(a));
}
__device__ __forceinline__ void ldsm4t(uint32_t& r0, uint32_t& r1, uint32_t& r2, uint32_t& r3, uint32_t a) {
    asm volatile("ldmatrix.sync.aligned.m8n8.x4.trans.shared.b16 {%0,%1,%2,%3}, [%4];"
                 : "=r"(r0), "=r"(r1), "=r"(r2), "=r"(r3) : "r"(a));
}
__device__ __forceinline__ void mma16816(float d[4],
                                         uint32_t a0, uint32_t a1, uint32_t a2, uint32_t a3,
                                         uint32_t b0, uint32_t b1) {
    asm volatile(
        "mma.sync.aligned.m16n8k16.row.col.f32.f16.f16.f32 "
        "{%0,%1,%2,%3},{%4,%5,%6,%7},{%8,%9},{%0,%1,%2,%3};"
        : "+f"(d[0]), "+f"(d[1]), "+f"(d[2]), "+f"(d[3])
        : "r"(a0), "r"(a1), "r"(a2), "r"(a3), "r"(b0), "r"(b1));
}
__device__ __forceinline__ uint32_t pack2(float x, float y) {
    __half2 h = __floats2half2_rn(x, y);
    return *(uint32_t*)&h;
}
__device__ __forceinline__ void cpa16(uint32_t dst, const void* src) {
    asm volatile("cp.async.cg.shared.global [%0], [%1], 16;" :: "r"(dst), "l"(src));
}
#define CP_COMMIT() asm volatile("cp.async.commit_group;")
#define CP_WAIT(n)  asm volatile("cp.async.wait_group %0;" :: "n"(n))

// ---------------------------------------------------------------------------
// fp32 -> fp16 conversion (weights / activations). cols fixed at 4096.
// ---------------------------------------------------------------------------
__global__ __launch_bounds__(256) void cvt_f2h(const float* __restrict__ src,
                                               half* __restrict__ dst, int ld)
{
    size_t i = ((size_t)blockIdx.x * 256 + threadIdx.x) * 4;
    size_t row = i >> 12;
    int    col = (int)(i & 4095);
    float4 v = *(const float4*)(src + row * (size_t)ld + col);
    *(uint2*)(dst + row * 4096 + col) = make_uint2(pack2(v.x, v.y), pack2(v.z, v.w));
}

// ---------------------------------------------------------------------------
// Pure-fp16 GEMM with cp.async 4-stage pipeline.
// C[256,4096] = A[256,4096]h @ B[4096,4096]h, fp32 out.
// BM=32, BN=128, BK=64, 128 threads (4 warps, warp tile 32m x 32n).
// Grid (32, 8) = 256 CTAs, 2 CTAs/SM.
// ---------------------------------------------------------------------------
#define GA_SLOT 4608           // 32 rows * 144 B
#define GB_SLOT 17408          // 64 rows * 272 B
#define GB_BASE (4 * GA_SLOT)  // 18432
#define GSMEM_BYTES (GB_BASE + 4 * GB_SLOT)   // 88064

__global__ __launch_bounds__(128, 2) void hgemm2(const half* __restrict__ A,
                                                 const half* __restrict__ B,
                                                 float* __restrict__ C)
{
    extern __shared__ char smc[];
    const uint32_t smBase = smaddr(smc);

    const int tid = threadIdx.x, lane = tid & 31, wid = tid >> 5;
    const int gid = lane >> 2, tig = lane & 3;
    const int bx = blockIdx.x, by = blockIdx.y;
    const int n0 = wid * 32;

    const half* Ab = A + (size_t)(by * 32) * HID;
    const half* Bb = B + (size_t)(bx * 128);

    float acc[2][4][4];
#pragma unroll
    for (int mt = 0; mt < 2; mt++)
#pragma unroll
        for (int nt = 0; nt < 4; nt++)
#pragma unroll
            for (int i = 0; i < 4; i++) acc[mt][nt][i] = 0.f;

    // ldsm base offsets (within a slot)
    const uint32_t aOff = (uint32_t)((lane & 15) * 144 + (lane >> 4) * 16);
    const uint32_t bOff = (uint32_t)(((lane & 7) + 8 * ((lane >> 3) & 1)) * 272
                                     + (n0 + 8 * (lane >> 4)) * 2);

    // stage loader
    auto load_stage = [&](int kt) {
        const int slot = kt & 3;
        const int k0 = kt * 64;
        const uint32_t aS = smBase + slot * GA_SLOT;
        const uint32_t bS = smBase + GB_BASE + slot * GB_SLOT;
#pragma unroll
        for (int i = 0; i < 2; i++) {
            int u = tid + i * 128, r = u >> 3, c = u & 7;
            cpa16(aS + r * 144 + c * 16, Ab + (size_t)r * HID + k0 + c * 8);
        }
#pragma unroll
        for (int i = 0; i < 8; i++) {
            int u = tid + i * 128, r = u >> 4, c = u & 15;
            cpa16(bS + r * 272 + c * 16, Bb + (size_t)(k0 + r) * HID + c * 8);
        }
        CP_COMMIT();
    };

    load_stage(0); load_stage(1); load_stage(2);

    const int NK = HID / 64;   // 64
    for (int kt = 0; kt < NK; kt++) {
        CP_WAIT(2);
        __syncthreads();
        if (kt + 3 < NK) load_stage(kt + 3); else CP_COMMIT();

        const int slot = kt & 3;
        const uint32_t aA = smBase + slot * GA_SLOT + aOff;
        const uint32_t bA = smBase + GB_BASE + slot * GB_SLOT + bOff;
#pragma unroll
        for (int kk = 0; kk < 4; kk++) {
            uint32_t x0, x1, x2, x3, y0, y1, y2, y3;
            ldsm4(x0, x1, x2, x3, aA + kk * 32);
            ldsm4(y0, y1, y2, y3, aA + 16 * 144 + kk * 32);
#pragma unroll
            for (int nt2 = 0; nt2 < 2; nt2++) {
                uint32_t b0, b1, b2, b3;
                ldsm4t(b0, b1, b2, b3, bA + kk * 16 * 272 + nt2 * 32);
                mma16816(acc[0][nt2 * 2],     x0, x1, x2, x3, b0, b1);
                mma16816(acc[0][nt2 * 2 + 1], x0, x1, x2, x3, b2, b3);
                mma16816(acc[1][nt2 * 2],     y0, y1, y2, y3, b0, b1);
                mma16816(acc[1][nt2 * 2 + 1], y0, y1, y2, y3, b2, b3);
            }
        }
    }

#pragma unroll
    for (int mt = 0; mt < 2; mt++) {
        const int row = by * 32 + mt * 16 + gid;
#pragma unroll
        for (int nt = 0; nt < 4; nt++) {
            const int col = bx * 128 + n0 + nt * 8 + 2 * tig;
            *(float2*)(C + (size_t)row * HID + col) =
                make_float2(acc[mt][nt][0], acc[mt][nt][1]);
            *(float2*)(C + (size_t)(row + 8) * HID + col) =
                make_float2(acc[mt][nt][2], acc[mt][nt][3]);
        }
    }
}

// ---------------------------------------------------------------------------
// Q: double RMSNorm + RoPE + fold 1/sqrt(D). One warp per (b,q,h) head row.
// ---------------------------------------------------------------------------
__global__ __launch_bounds__(256) void qnorm_rope_k(const float* __restrict__ cosb,
                                                    const float* __restrict__ sinb,
                                                    const float* __restrict__ w)
{
    const int gw   = (blockIdx.x * 256 + threadIdx.x) >> 5;
    const int lane = threadIdx.x & 31;
    const int h = gw & 31;
    const int q = (gw >> 5) & 63;
    const int b = gw >> 11;

    const float* src = g_qraw + (size_t)(b * QL + q) * HID + h * HD + lane * 4;
    float4 x4 = *(const float4*)src;
    float  x[4] = {x4.x, x4.y, x4.z, x4.w};
    float4 w4 = *(const float4*)(w + lane * 4);
    float  wv[4] = {w4.x, w4.y, w4.z, w4.w};

    float ss = x[0]*x[0] + x[1]*x[1] + x[2]*x[2] + x[3]*x[3];
#pragma unroll
    for (int o = 16; o > 0; o >>= 1) ss += __shfl_xor_sync(0xffffffffu, ss, o);
    float r1 = rsqrtf(ss * (1.f / 128.f) + EPSR);

    float y[4];
#pragma unroll
    for (int j = 0; j < 4; j++) y[j] = x[j] * r1 * wv[j];

    float ss2 = y[0]*y[0] + y[1]*y[1] + y[2]*y[2] + y[3]*y[3];
#pragma unroll
    for (int o = 16; o > 0; o >>= 1) ss2 += __shfl_xor_sync(0xffffffffu, ss2, o);
    float r2 = rsqrtf(ss2 * (1.f / 128.f) + EPSR);

    float z[4];
#pragma unroll
    for (int j = 0; j < 4; j++) z[j] = y[j] * r2 * wv[j];

    const float4 c4 = *(const float4*)(cosb + (size_t)(CTX + q) * HD + lane * 4);
    const float4 s4 = *(const float4*)(sinb + (size_t)(CTX + q) * HD + lane * 4);
    const float cf[4] = {c4.x, c4.y, c4.z, c4.w};
    const float sf[4] = {s4.x, s4.y, s4.z, s4.w};

    float o_[4];
#pragma unroll
    for (int j = 0; j < 4; j++) {
        float p   = __shfl_xor_sync(0xffffffffu, z[j], 16);
        float rot = (lane < 16) ? -p : p;
        o_[j] = (z[j] * cf[j] + rot * sf[j]) * INV_SQRT_D;
    }
    float* dst = g_q + (size_t)((b * NH + h) * QL + q) * HD + lane * 4;
    *(float4*)dst = make_float4(o_[0], o_[1], o_[2], o_[3]);
}

// ---------------------------------------------------------------------------
// Flash attention with cp.async pipelined KV.
// Grid 128 = (b,h). 256 threads, 8 warps = 4 q-tiles(16 rows) x 2 key stripes.
// 65 chunks of 64 keys (no tail). Q frags register-resident. fp16 MMA.
// smem: raw fp32 [3][64][128], Kh/Vh fp16 [64][136], m/l reduce.
// ---------------------------------------------------------------------------
#define A_RAW_SLOT 32768                         // 64*128*4
#define A_KH_BASE  (3 * A_RAW_SLOT)              // 98304
#define A_VH_BASE  (A_KH_BASE + 17408)           // 115712
#define A_MRED     (A_VH_BASE + 17408)           // 133120
#define ASMEM_BYTES (A_MRED + 1024)              // 134144

__global__ __launch_bounds__(256, 1) void attn_h(const float* __restrict__ th,
                                                 const float* __restrict__ hs,
                                                 const float* __restrict__ cosb,
                                                 const float* __restrict__ sinb)
{
    extern __shared__ char smc[];
    const uint32_t smBase = smaddr(smc);
    half*  Kh   = (half*)(smc + A_KH_BASE);
    half*  Vh   = (half*)(smc + A_VH_BASE);
    float* mred = (float*)(smc + A_MRED);         // [2][64]
    float* lred = mred + 128;                     // [2][64]

    const int bh = blockIdx.x, h = bh & 31, b = bh >> 5;
    const int tid = threadIdx.x, lane = tid & 31, wid = tid >> 5;
    const int gid = lane >> 2, tig = lane & 3;
    const int wq = wid >> 1, wg = wid & 1;
    const int r0 = wq * 16, j0 = wg * 32;

    const float* thb = th + (size_t)b * CTX * HID + h * HD;
    const float* hsb = hs + (size_t)b * QL  * HID + h * HD;

    auto load_chunk = [&](int c) {
        const int slot = c % 3;
        const uint32_t rS = smBase + slot * A_RAW_SLOT;
        const float* base = (c < 64) ? (thb + (size_t)c * 64 * HID) : hsb;
#pragma unroll
        for (int i = 0; i < 8; i++) {
            int u = tid + i * 256, j = u >> 5, d4 = u & 31;
            cpa16(rS + j * 512 + d4 * 16, base + (size_t)j * HID + d4 * 4);
        }
        CP_COMMIT();
    };

    load_chunk(0); load_chunk(1); load_chunk(2);

    // Q staging (into Kh as temp), then register-resident fragments
    const float* qsrc = g_q + (size_t)bh * (QL * HD);
    for (int e = tid * 4; e < QL * HD; e += 1024) {
        int j = e >> 7, dd = e & 127;
        float4 v = *(const float4*)(qsrc + e);
        *(uint2*)&Kh[j * 136 + dd] = make_uint2(pack2(v.x, v.y), pack2(v.z, v.w));
    }
    __syncthreads();
    uint32_t qa[8][4];
    {
        const uint32_t qA = smBase + A_KH_BASE
                          + (uint32_t)((r0 + (lane & 15)) * 272 + (lane >> 4) * 16);
#pragma unroll
        for (int kd = 0; kd < 8; kd++)
            ldsm4(qa[kd][0], qa[kd][1], qa[kd][2], qa[kd][3], qA + kd * 32);
    }

    const uint32_t kA = smBase + A_KH_BASE
        + (uint32_t)((j0 + (lane & 7) + 8 * (lane >> 4)) * 272 + ((lane >> 3) & 1) * 16);
    const uint32_t vA = smBase + A_VH_BASE
        + (uint32_t)((j0 + (lane & 7) + 8 * ((lane >> 3) & 1)) * 272 + (lane >> 4) * 16);

    float m_lo = -1e30f, m_hi = -1e30f, l_lo = 0.f, l_hi = 0.f;
    float oacc[16][4];
#pragma unroll
    for (int nt = 0; nt < 16; nt++)
#pragma unroll
        for (int i = 0; i < 4; i++) oacc[nt][i] = 0.f;

    for (int t = 0; t < 65; t++) {
        CP_WAIT(2);
        __syncthreads();

        // convert: rope K -> Kh, raw V -> Vh
        {
            const float* rw = (const float*)(smc + (t % 3) * A_RAW_SLOT);
            const int p0 = t * 64;
            for (int e = tid * 4; e < 64 * 128; e += 1024) {
                int j = e >> 7, dd = e & 127;
                int p = p0 + j;
                float4 v = *(const float4*)&rw[j * 128 + dd];
                *(uint2*)&Vh[j * 136 + dd] = make_uint2(pack2(v.x, v.y), pack2(v.z, v.w));
                float4 q = *(const float4*)&rw[j * 128 + (dd ^ 64)];
                float4 c = *(const float4*)(cosb + (size_t)p * HD + dd);
                float4 s = *(const float4*)(sinb + (size_t)p * HD + dd);
                float sgn = (dd < 64) ? -1.f : 1.f;
                float k0 = v.x * c.x + sgn * q.x * s.x;
                float k1 = v.y * c.y + sgn * q.y * s.y;
                float k2 = v.z * c.z + sgn * q.z * s.z;
                float k3 = v.w * c.w + sgn * q.w * s.w;
                *(uint2*)&Kh[j * 136 + dd] = make_uint2(pack2(k0, k1), pack2(k2, k3));
            }
        }
        __syncthreads();
        if (t + 3 < 65) load_chunk(t + 3); else CP_COMMIT();

        // QK^T: S[16q][32k] per warp
        float sacc[4][4];
#pragma unroll
        for (int nt = 0; nt < 4; nt++)
#pragma unroll
            for (int i = 0; i < 4; i++) sacc[nt][i] = 0.f;
#pragma unroll
        for (int kd = 0; kd < 8; kd++) {
#pragma unroll
            for (int jt = 0; jt < 2; jt++) {
                uint32_t b0, b1, b2, b3;
                ldsm4(b0, b1, b2, b3, kA + jt * 16 * 272 + kd * 32);
                mma16816(sacc[jt * 2],     qa[kd][0], qa[kd][1], qa[kd][2], qa[kd][3], b0, b1);
                mma16816(sacc[jt * 2 + 1], qa[kd][0], qa[kd][1], qa[kd][2], qa[kd][3], b2, b3);
            }
        }

        // online softmax
        float mx_lo = -1e30f, mx_hi = -1e30f;
#pragma unroll
        for (int nt = 0; nt < 4; nt++) {
            mx_lo = fmaxf(mx_lo, fmaxf(sacc[nt][0], sacc[nt][1]));
            mx_hi = fmaxf(mx_hi, fmaxf(sacc[nt][2], sacc[nt][3]));
        }
        mx_lo = fmaxf(mx_lo, __shfl_xor_sync(0xffffffffu, mx_lo, 1));
        mx_lo = fmaxf(mx_lo, __shfl_xor_sync(0xffffffffu, mx_lo, 2));
        mx_hi = fmaxf(mx_hi, __shfl_xor_sync(0xffffffffu, mx_hi, 1));
        mx_hi = fmaxf(mx_hi, __shfl_xor_sync(0xffffffffu, mx_hi, 2));

        float nm_lo = fmaxf(m_lo, mx_lo), nm_hi = fmaxf(m_hi, mx_hi);
        float al_lo = __expf(m_lo - nm_lo), al_hi = __expf(m_hi - nm_hi);
        float sum_lo = 0.f, sum_hi = 0.f;
        uint32_t pa0[4], pa1[4];
#pragma unroll
        for (int nt = 0; nt < 4; nt++) {
            float e0 = __expf(sacc[nt][0] - nm_lo);
            float e1 = __expf(sacc[nt][1] - nm_lo);
            float e2 = __expf(sacc[nt][2] - nm_hi);
            float e3 = __expf(sacc[nt][3] - nm_hi);
            sum_lo += e0 + e1;  sum_hi += e2 + e3;
            pa0[nt] = pack2(e0, e1);
            pa1[nt] = pack2(e2, e3);
        }
        sum_lo += __shfl_xor_sync(0xffffffffu, sum_lo, 1);
        sum_lo += __shfl_xor_sync(0xffffffffu, sum_lo, 2);
        sum_hi += __shfl_xor_sync(0xffffffffu, sum_hi, 1);
        sum_hi += __shfl_xor_sync(0xffffffffu, sum_hi, 2);
        l_lo = l_lo * al_lo + sum_lo;  l_hi = l_hi * al_hi + sum_hi;
        m_lo = nm_lo;  m_hi = nm_hi;

#pragma unroll
        for (int nt = 0; nt < 16; nt++) {
            oacc[nt][0] *= al_lo; oacc[nt][1] *= al_lo;
            oacc[nt][2] *= al_hi; oacc[nt][3] *= al_hi;
        }

        // PV: O[16q][128d] += P[16][32] @ V[32][128]
#pragma unroll
        for (int kc = 0; kc < 2; kc++) {
            uint32_t a0 = pa0[2 * kc], a1 = pa1[2 * kc];
            uint32_t a2 = pa0[2 * kc + 1], a3 = pa1[2 * kc + 1];
#pragma unroll
            for (int dt = 0; dt < 8; dt++) {
                uint32_t b0, b1, b2, b3;
                ldsm4t(b0, b1, b2, b3, vA + kc * 16 * 272 + dt * 32);
                mma16816(oacc[dt * 2],     a0, a1, a2, a3, b0, b1);
                mma16816(oacc[dt * 2 + 1], a0, a1, a2, a3, b2, b3);
            }
        }
    }

    // drain async, 2-way key-group merge
    CP_WAIT(0);
    const int rlo = r0 + gid, rhi = r0 + gid + 8;
    if (tig == 0) {
        mred[wg * 64 + rlo] = m_lo;  mred[wg * 64 + rhi] = m_hi;
        lred[wg * 64 + rlo] = l_lo;  lred[wg * 64 + rhi] = l_hi;
    }
    __syncthreads();
    float M_lo = fmaxf(mred[rlo], mred[64 + rlo]);
    float M_hi = fmaxf(mred[rhi], mred[64 + rhi]);
    float Lt_lo = lred[rlo] * __expf(mred[rlo] - M_lo)
                + lred[64 + rlo] * __expf(mred[64 + rlo] - M_lo);
    float Lt_hi = lred[rhi] * __expf(mred[rhi] - M_hi)
                + lred[64 + rhi] * __expf(mred[64 + rhi] - M_hi);
    float sc_lo = __expf(m_lo - M_lo) / Lt_lo;
    float sc_hi = __expf(m_hi - M_hi) / Lt_hi;
#pragma unroll
    for (int nt = 0; nt < 16; nt++) {
        oacc[nt][0] *= sc_lo; oacc[nt][1] *= sc_lo;
        oacc[nt][2] *= sc_hi; oacc[nt][3] *= sc_hi;
    }

    float* OsmF = (float*)smc;  // reuse raw slot 0: 64x128 fp32
    if (wg == 0) {
#pragma unroll
        for (int nt = 0; nt < 16; nt++) {
            const int col = nt * 8 + 2 * tig;
            *(float2*)&OsmF[rlo * 128 + col] = make_float2(oacc[nt][0], oacc[nt][1]);
            *(float2*)&OsmF[rhi * 128 + col] = make_float2(oacc[nt][2], oacc[nt][3]);
        }
    }
    __syncthreads();
    if (wg == 1) {
#pragma unroll
        for (int nt = 0; nt < 16; nt++) {
            const int col = nt * 8 + 2 * tig;
            float2 v0 = *(float2*)&OsmF[rlo * 128 + col];
            float2 v1 = *(float2*)&OsmF[rhi * 128 + col];
            *(float2*)&OsmF[rlo * 128 + col] = make_float2(oacc[nt][0] + v0.x, oacc[nt][1] + v0.y);
            *(float2*)&OsmF[rhi * 128 + col] = make_float2(oacc[nt][2] + v1.x, oacc[nt][3] + v1.y);
        }
    }
    __syncthreads();

    for (int e = tid * 4; e < QL * HD; e += 1024) {
        int r = e >> 7, dd = e & 127;
        float4 v = *(const float4*)&OsmF[r * 128 + dd];
        *(uint2*)(g_attn_h + (size_t)(b * QL + r) * HID + h * HD + dd) =
            make_uint2(pack2(v.x, v.y), pack2(v.z, v.w));
    }
}

// ---------------------------------------------------------------------------
extern "C" void kernel_launch(void* const* d_in, const int* in_sizes, int n_in,
                              void* d_out, int out_size)
{
    const float* hs   = (const float*)d_in[0];
    const float* th   = (const float*)d_in[1];
    const float* cosb = (const float*)d_in[2];
    const float* sinb = (const float*)d_in[3];
    const float* Wqkv = (const float*)d_in[4];
    const float* Wo   = (const float*)d_in[5];
    const float* qw   = (const float*)d_in[6];
    float* out = (float*)d_out;

    float *qraw_p;
    half *hs_h, *attn_h_p, *wq_h, *wo_h;
    cudaGetSymbolAddress((void**)&qraw_p, g_qraw);
    cudaGetSymbolAddress((void**)&hs_h,   g_hs_h);
    cudaGetSymbolAddress((void**)&attn_h_p, g_attn_h);
    cudaGetSymbolAddress((void**)&wq_h,   g_wq_h);
    cudaGetSymbolAddress((void**)&wo_h,   g_wo_h);

    cudaFuncSetAttribute(hgemm2, cudaFuncAttributeMaxDynamicSharedMemorySize, GSMEM_BYTES);
    cudaFuncSetAttribute(attn_h, cudaFuncAttributeMaxDynamicSharedMemorySize, ASMEM_BYTES);

    // preps
    cvt_f2h<<<16384, 256>>>(Wqkv, wq_h, 3 * HID);   // first 4096 cols of Wqkv
    cvt_f2h<<<1024,  256>>>(hs,   hs_h, HID);
    cvt_f2h<<<16384, 256>>>(Wo,   wo_h, HID);

    dim3 gg(32, 8);
    hgemm2<<<gg, 128, GSMEM_BYTES>>>(hs_h, wq_h, qraw_p);
    qnorm_rope_k<<<1024, 256>>>(cosb, sinb, qw);
    attn_h<<<NB * NH, 256, ASMEM_BYTES>>>(th, hs, cosb, sinb);
    hgemm2<<<gg, 128, GSMEM_BYTES>>>(attn_h_p, wo_h, out);
}

// round 6
// speedup vs baseline: 5.5512x; 1.0895x over previous
#include <cuda_runtime.h>
#include <cuda_fp16.h>
#include <math.h>
#include <stdint.h>

#define NB    4
#define QL    64
#define NH    32
#define HD    128
#define CTX   4096
#define TOT   4160
#define HID   4096
#define EPSR  1e-6f
#define INV_SQRT_D 0.08838834764831843f
#define SPLIT 4

__device__ float g_qraw[NB * QL * HID];
__device__ float g_q   [NB * NH * QL * HD];
__device__ half  g_hs_h [NB * QL * HID];
__device__ half  g_attn_h[NB * QL * HID];
__device__ half  g_wq_h[HID * HID];
__device__ half  g_wo_h[HID * HID];
__device__ uint32_t g_csh[TOT * HD];                 // packed (cos,sin) fp16
__device__ float g_pO[SPLIT * NB * NH * QL * HD];    // split partial O (16.8MB)
__device__ float g_pm[SPLIT * NB * NH * QL];
__device__ float g_pl[SPLIT * NB * NH * QL];

// ---------------------------------------------------------------------------
// helpers
// ---------------------------------------------------------------------------
__device__ __forceinline__ uint32_t smaddr(const void* p) {
    return (uint32_t)__cvta_generic_to_shared(p);
}
__device__ __forceinline__ void ldsm4(uint32_t& r0, uint32_t& r1, uint32_t& r2, uint32_t& r3, uint32_t a) {
    asm volatile("ldmatrix.sync.aligned.m8n8.x4.shared.b16 {%0,%1,%2,%3}, [%4];"
                 : "=r"(r0), "=r"(r1), "=r"(r2), "=r"(r3) : "r"(a));
}
__device__ __forceinline__ void ldsm4t(uint32_t& r0, uint32_t& r1, uint32_t& r2, uint32_t& r3, uint32_t a) {
    asm volatile("ldmatrix.sync.aligned.m8n8.x4.trans.shared.b16 {%0,%1,%2,%3}, [%4];"
                 : "=r"(r0), "=r"(r1), "=r"(r2), "=r"(r3) : "r"(a));
}
__device__ __forceinline__ void mma16816(float d[4],
                                         uint32_t a0, uint32_t a1, uint32_t a2, uint32_t a3,
                                         uint32_t b0, uint32_t b1) {
    asm volatile(
        "mma.sync.aligned.m16n8k16.row.col.f32.f16.f16.f32 "
        "{%0,%1,%2,%3},{%4,%5,%6,%7},{%8,%9},{%0,%1,%2,%3};"
        : "+f"(d[0]), "+f"(d[1]), "+f"(d[2]), "+f"(d[3])
        : "r"(a0), "r"(a1), "r"(a2), "r"(a3), "r"(b0), "r"(b1));
}
__device__ __forceinline__ uint32_t pack2(float x, float y) {
    __half2 h = __floats2half2_rn(x, y);
    return *(uint32_t*)&h;
}
__device__ __forceinline__ void cpa16(uint32_t dst, const void* src) {
    asm volatile("cp.async.cg.shared.global [%0], [%1], 16;" :: "r"(dst), "l"(src));
}
#define CP_COMMIT() asm volatile("cp.async.commit_group;")
#define CP_WAIT(n)  asm volatile("cp.async.wait_group %0;" :: "n"(n))

// ---------------------------------------------------------------------------
// fp32 -> fp16 conversion (weights / activations). cols fixed at 4096.
// ---------------------------------------------------------------------------
__global__ __launch_bounds__(256) void cvt_f2h(const float* __restrict__ src,
                                               half* __restrict__ dst, int ld)
{
    size_t i = ((size_t)blockIdx.x * 256 + threadIdx.x) * 4;
    size_t row = i >> 12;
    int    col = (int)(i & 4095);
    float4 v = *(const float4*)(src + row * (size_t)ld + col);
    *(uint2*)(dst + row * 4096 + col) = make_uint2(pack2(v.x, v.y), pack2(v.z, v.w));
}

// packed (cos,sin) fp16 table
__global__ __launch_bounds__(256) void cs_prep(const float* __restrict__ cosb,
                                               const float* __restrict__ sinb)
{
    int i = blockIdx.x * 256 + threadIdx.x;   // 0 .. TOT*HD-1
    g_csh[i] = pack2(cosb[i], sinb[i]);
}

// ---------------------------------------------------------------------------
// Pure-fp16 GEMM with cp.async 4-stage pipeline (unchanged from R5).
// ---------------------------------------------------------------------------
#define GA_SLOT 4608
#define GB_SLOT 17408
#define GB_BASE (4 * GA_SLOT)
#define GSMEM_BYTES (GB_BASE + 4 * GB_SLOT)

__global__ __launch_bounds__(128, 2) void hgemm2(const half* __restrict__ A,
                                                 const half* __restrict__ B,
                                                 float* __restrict__ C)
{
    extern __shared__ char smc[];
    const uint32_t smBase = smaddr(smc);

    const int tid = threadIdx.x, lane = tid & 31, wid = tid >> 5;
    const int gid = lane >> 2, tig = lane & 3;
    const int bx = blockIdx.x, by = blockIdx.y;
    const int n0 = wid * 32;

    const half* Ab = A + (size_t)(by * 32) * HID;
    const half* Bb = B + (size_t)(bx * 128);

    float acc[2][4][4];
#pragma unroll
    for (int mt = 0; mt < 2; mt++)
#pragma unroll
        for (int nt = 0; nt < 4; nt++)
#pragma unroll
            for (int i = 0; i < 4; i++) acc[mt][nt][i] = 0.f;

    const uint32_t aOff = (uint32_t)((lane & 15) * 144 + (lane >> 4) * 16);
    const uint32_t bOff = (uint32_t)(((lane & 7) + 8 * ((lane >> 3) & 1)) * 272
                                     + (n0 + 8 * (lane >> 4)) * 2);

    auto load_stage = [&](int kt) {
        const int slot = kt & 3;
        const int k0 = kt * 64;
        const uint32_t aS = smBase + slot * GA_SLOT;
        const uint32_t bS = smBase + GB_BASE + slot * GB_SLOT;
#pragma unroll
        for (int i = 0; i < 2; i++) {
            int u = tid + i * 128, r = u >> 3, c = u & 7;
            cpa16(aS + r * 144 + c * 16, Ab + (size_t)r * HID + k0 + c * 8);
        }
#pragma unroll
        for (int i = 0; i < 8; i++) {
            int u = tid + i * 128, r = u >> 4, c = u & 15;
            cpa16(bS + r * 272 + c * 16, Bb + (size_t)(k0 + r) * HID + c * 8);
        }
        CP_COMMIT();
    };

    load_stage(0); load_stage(1); load_stage(2);

    const int NK = HID / 64;
    for (int kt = 0; kt < NK; kt++) {
        CP_WAIT(2);
        __syncthreads();
        if (kt + 3 < NK) load_stage(kt + 3); else CP_COMMIT();

        const int slot = kt & 3;
        const uint32_t aA = smBase + slot * GA_SLOT + aOff;
        const uint32_t bA = smBase + GB_BASE + slot * GB_SLOT + bOff;
#pragma unroll
        for (int kk = 0; kk < 4; kk++) {
            uint32_t x0, x1, x2, x3, y0, y1, y2, y3;
            ldsm4(x0, x1, x2, x3, aA + kk * 32);
            ldsm4(y0, y1, y2, y3, aA + 16 * 144 + kk * 32);
#pragma unroll
            for (int nt2 = 0; nt2 < 2; nt2++) {
                uint32_t b0, b1, b2, b3;
                ldsm4t(b0, b1, b2, b3, bA + kk * 16 * 272 + nt2 * 32);
                mma16816(acc[0][nt2 * 2],     x0, x1, x2, x3, b0, b1);
                mma16816(acc[0][nt2 * 2 + 1], x0, x1, x2, x3, b2, b3);
                mma16816(acc[1][nt2 * 2],     y0, y1, y2, y3, b0, b1);
                mma16816(acc[1][nt2 * 2 + 1], y0, y1, y2, y3, b2, b3);
            }
        }
    }

#pragma unroll
    for (int mt = 0; mt < 2; mt++) {
        const int row = by * 32 + mt * 16 + gid;
#pragma unroll
        for (int nt = 0; nt < 4; nt++) {
            const int col = bx * 128 + n0 + nt * 8 + 2 * tig;
            *(float2*)(C + (size_t)row * HID + col) =
                make_float2(acc[mt][nt][0], acc[mt][nt][1]);
            *(float2*)(C + (size_t)(row + 8) * HID + col) =
                make_float2(acc[mt][nt][2], acc[mt][nt][3]);
        }
    }
}

// ---------------------------------------------------------------------------
// Q: double RMSNorm + RoPE + fold 1/sqrt(D). (fp32 path, unchanged)
// ---------------------------------------------------------------------------
__global__ __launch_bounds__(256) void qnorm_rope_k(const float* __restrict__ cosb,
                                                    const float* __restrict__ sinb,
                                                    const float* __restrict__ w)
{
    const int gw   = (blockIdx.x * 256 + threadIdx.x) >> 5;
    const int lane = threadIdx.x & 31;
    const int h = gw & 31;
    const int q = (gw >> 5) & 63;
    const int b = gw >> 11;

    const float* src = g_qraw + (size_t)(b * QL + q) * HID + h * HD + lane * 4;
    float4 x4 = *(const float4*)src;
    float  x[4] = {x4.x, x4.y, x4.z, x4.w};
    float4 w4 = *(const float4*)(w + lane * 4);
    float  wv[4] = {w4.x, w4.y, w4.z, w4.w};

    float ss = x[0]*x[0] + x[1]*x[1] + x[2]*x[2] + x[3]*x[3];
#pragma unroll
    for (int o = 16; o > 0; o >>= 1) ss += __shfl_xor_sync(0xffffffffu, ss, o);
    float r1 = rsqrtf(ss * (1.f / 128.f) + EPSR);

    float y[4];
#pragma unroll
    for (int j = 0; j < 4; j++) y[j] = x[j] * r1 * wv[j];

    float ss2 = y[0]*y[0] + y[1]*y[1] + y[2]*y[2] + y[3]*y[3];
#pragma unroll
    for (int o = 16; o > 0; o >>= 1) ss2 += __shfl_xor_sync(0xffffffffu, ss2, o);
    float r2 = rsqrtf(ss2 * (1.f / 128.f) + EPSR);

    float z[4];
#pragma unroll
    for (int j = 0; j < 4; j++) z[j] = y[j] * r2 * wv[j];

    const float4 c4 = *(const float4*)(cosb + (size_t)(CTX + q) * HD + lane * 4);
    const float4 s4 = *(const float4*)(sinb + (size_t)(CTX + q) * HD + lane * 4);
    const float cf[4] = {c4.x, c4.y, c4.z, c4.w};
    const float sf[4] = {s4.x, s4.y, s4.z, s4.w};

    float o_[4];
#pragma unroll
    for (int j = 0; j < 4; j++) {
        float p   = __shfl_xor_sync(0xffffffffu, z[j], 16);
        float rot = (lane < 16) ? -p : p;
        o_[j] = (z[j] * cf[j] + rot * sf[j]) * INV_SQRT_D;
    }
    float* dst = g_q + (size_t)((b * NH + h) * QL + q) * HD + lane * 4;
    *(float4*)dst = make_float4(o_[0], o_[1], o_[2], o_[3]);
}

// ---------------------------------------------------------------------------
// KV-split flash attention. Grid (128 bh, 4 split), 256 threads, 2 CTAs/SM.
// Each split handles 16-17 chunks of 64 keys; writes partial (O, m, l).
// 2-slot cp.async pipeline; packed fp16 cos/sin table.
// ---------------------------------------------------------------------------
#define A_RAW_SLOT 32768                      // 64*128*4
#define A_KH_BASE  (2 * A_RAW_SLOT)           // 65536
#define A_VH_BASE  (A_KH_BASE + 17408)        // 82944
#define A_MRED     (A_VH_BASE + 17408)        // 100352
#define ASMEM_BYTES (A_MRED + 1024)           // 101376

__global__ __launch_bounds__(256, 2) void attn_h(const float* __restrict__ th,
                                                 const float* __restrict__ hs)
{
    extern __shared__ char smc[];
    const uint32_t smBase = smaddr(smc);
    half*  Kh   = (half*)(smc + A_KH_BASE);
    half*  Vh   = (half*)(smc + A_VH_BASE);
    float* mred = (float*)(smc + A_MRED);     // [2][64]
    float* lred = mred + 128;                 // [2][64]

    const int bh = blockIdx.x, h = bh & 31, b = bh >> 5;
    const int sp = blockIdx.y;
    const int c0 = (sp == 0) ? 0 : 17 + (sp - 1) * 16;
    const int c1 = (sp == 0) ? 17 : c0 + 16;

    const int tid = threadIdx.x, lane = tid & 31, wid = tid >> 5;
    const int gid = lane >> 2, tig = lane & 3;
    const int wq = wid >> 1, wg = wid & 1;
    const int r0 = wq * 16, j0 = wg * 32;

    const float* thb = th + (size_t)b * CTX * HID + h * HD;
    const float* hsb = hs + (size_t)b * QL  * HID + h * HD;

    auto load_chunk = [&](int c) {
        const uint32_t rS = smBase + (c & 1) * A_RAW_SLOT;
        const float* base = (c < 64) ? (thb + (size_t)c * 64 * HID) : hsb;
#pragma unroll
        for (int i = 0; i < 8; i++) {
            int u = tid + i * 256, j = u >> 5, d4 = u & 31;
            cpa16(rS + j * 512 + d4 * 16, base + (size_t)j * HID + d4 * 4);
        }
        CP_COMMIT();
    };

    load_chunk(c0); load_chunk(c0 + 1);

    // Q staging (via Kh as temp) -> register-resident fragments
    const float* qsrc = g_q + (size_t)bh * (QL * HD);
    for (int e = tid * 4; e < QL * HD; e += 1024) {
        int j = e >> 7, dd = e & 127;
        float4 v = *(const float4*)(qsrc + e);
        *(uint2*)&Kh[j * 136 + dd] = make_uint2(pack2(v.x, v.y), pack2(v.z, v.w));
    }
    __syncthreads();
    uint32_t qa[8][4];
    {
        const uint32_t qA = smBase + A_KH_BASE
                          + (uint32_t)((r0 + (lane & 15)) * 272 + (lane >> 4) * 16);
#pragma unroll
        for (int kd = 0; kd < 8; kd++)
            ldsm4(qa[kd][0], qa[kd][1], qa[kd][2], qa[kd][3], qA + kd * 32);
    }

    const uint32_t kA = smBase + A_KH_BASE
        + (uint32_t)((j0 + (lane & 7) + 8 * (lane >> 4)) * 272 + ((lane >> 3) & 1) * 16);
    const uint32_t vA = smBase + A_VH_BASE
        + (uint32_t)((j0 + (lane & 7) + 8 * ((lane >> 3) & 1)) * 272 + (lane >> 4) * 16);

    float m_lo = -1e30f, m_hi = -1e30f, l_lo = 0.f, l_hi = 0.f;
    float oacc[16][4];
#pragma unroll
    for (int nt = 0; nt < 16; nt++)
#pragma unroll
        for (int i = 0; i < 4; i++) oacc[nt][i] = 0.f;

    for (int t = c0; t < c1; t++) {
        CP_WAIT(1);
        __syncthreads();

        // convert: rope K -> Kh, raw V -> Vh (packed fp16 cos/sin)
        {
            const float* rw = (const float*)(smc + (t & 1) * A_RAW_SLOT);
            const int p0 = t * 64;
            for (int e = tid * 4; e < 64 * 128; e += 1024) {
                int j = e >> 7, dd = e & 127;
                int p = p0 + j;
                float4 v = *(const float4*)&rw[j * 128 + dd];
                *(uint2*)&Vh[j * 136 + dd] = make_uint2(pack2(v.x, v.y), pack2(v.z, v.w));
                float4 q = *(const float4*)&rw[j * 128 + (dd ^ 64)];
                uint4 cs = *(const uint4*)&g_csh[(size_t)p * HD + dd];
                float2 c0f = __half22float2(*(__half2*)&cs.x);
                float2 c1f = __half22float2(*(__half2*)&cs.y);
                float2 c2f = __half22float2(*(__half2*)&cs.z);
                float2 c3f = __half22float2(*(__half2*)&cs.w);
                float sgn = (dd < 64) ? -1.f : 1.f;
                float k0 = v.x * c0f.x + sgn * q.x * c0f.y;
                float k1 = v.y * c1f.x + sgn * q.y * c1f.y;
                float k2 = v.z * c2f.x + sgn * q.z * c2f.y;
                float k3 = v.w * c3f.x + sgn * q.w * c3f.y;
                *(uint2*)&Kh[j * 136 + dd] = make_uint2(pack2(k0, k1), pack2(k2, k3));
            }
        }
        __syncthreads();
        if (t + 2 < c1) load_chunk(t + 2); else CP_COMMIT();

        // QK^T
        float sacc[4][4];
#pragma unroll
        for (int nt = 0; nt < 4; nt++)
#pragma unroll
            for (int i = 0; i < 4; i++) sacc[nt][i] = 0.f;
#pragma unroll
        for (int kd = 0; kd < 8; kd++) {
#pragma unroll
            for (int jt = 0; jt < 2; jt++) {
                uint32_t b0, b1, b2, b3;
                ldsm4(b0, b1, b2, b3, kA + jt * 16 * 272 + kd * 32);
                mma16816(sacc[jt * 2],     qa[kd][0], qa[kd][1], qa[kd][2], qa[kd][3], b0, b1);
                mma16816(sacc[jt * 2 + 1], qa[kd][0], qa[kd][1], qa[kd][2], qa[kd][3], b2, b3);
            }
        }

        // online softmax
        float mx_lo = -1e30f, mx_hi = -1e30f;
#pragma unroll
        for (int nt = 0; nt < 4; nt++) {
            mx_lo = fmaxf(mx_lo, fmaxf(sacc[nt][0], sacc[nt][1]));
            mx_hi = fmaxf(mx_hi, fmaxf(sacc[nt][2], sacc[nt][3]));
        }
        mx_lo = fmaxf(mx_lo, __shfl_xor_sync(0xffffffffu, mx_lo, 1));
        mx_lo = fmaxf(mx_lo, __shfl_xor_sync(0xffffffffu, mx_lo, 2));
        mx_hi = fmaxf(mx_hi, __shfl_xor_sync(0xffffffffu, mx_hi, 1));
        mx_hi = fmaxf(mx_hi, __shfl_xor_sync(0xffffffffu, mx_hi, 2));

        float nm_lo = fmaxf(m_lo, mx_lo), nm_hi = fmaxf(m_hi, mx_hi);
        float al_lo = __expf(m_lo - nm_lo), al_hi = __expf(m_hi - nm_hi);
        float sum_lo = 0.f, sum_hi = 0.f;
        uint32_t pa0[4], pa1[4];
#pragma unroll
        for (int nt = 0; nt < 4; nt++) {
            float e0 = __expf(sacc[nt][0] - nm_lo);
            float e1 = __expf(sacc[nt][1] - nm_lo);
            float e2 = __expf(sacc[nt][2] - nm_hi);
            float e3 = __expf(sacc[nt][3] - nm_hi);
            sum_lo += e0 + e1;  sum_hi += e2 + e3;
            pa0[nt] = pack2(e0, e1);
            pa1[nt] = pack2(e2, e3);
        }
        sum_lo += __shfl_xor_sync(0xffffffffu, sum_lo, 1);
        sum_lo += __shfl_xor_sync(0xffffffffu, sum_lo, 2);
        sum_hi += __shfl_xor_sync(0xffffffffu, sum_hi, 1);
        sum_hi += __shfl_xor_sync(0xffffffffu, sum_hi, 2);
        l_lo = l_lo * al_lo + sum_lo;  l_hi = l_hi * al_hi + sum_hi;
        m_lo = nm_lo;  m_hi = nm_hi;

#pragma unroll
        for (int nt = 0; nt < 16; nt++) {
            oacc[nt][0] *= al_lo; oacc[nt][1] *= al_lo;
            oacc[nt][2] *= al_hi; oacc[nt][3] *= al_hi;
        }

        // PV
#pragma unroll
        for (int kc = 0; kc < 2; kc++) {
            uint32_t a0 = pa0[2 * kc], a1 = pa1[2 * kc];
            uint32_t a2 = pa0[2 * kc + 1], a3 = pa1[2 * kc + 1];
#pragma unroll
            for (int dt = 0; dt < 8; dt++) {
                uint32_t b0, b1, b2, b3;
                ldsm4t(b0, b1, b2, b3, vA + kc * 16 * 272 + dt * 32);
                mma16816(oacc[dt * 2],     a0, a1, a2, a3, b0, b1);
                mma16816(oacc[dt * 2 + 1], a0, a1, a2, a3, b2, b3);
            }
        }
    }

    CP_WAIT(0);
    // in-CTA merge of the 2 key stripes -> partial (unnormalized O, m, l)
    const int rlo = r0 + gid, rhi = r0 + gid + 8;
    if (tig == 0) {
        mred[wg * 64 + rlo] = m_lo;  mred[wg * 64 + rhi] = m_hi;
        lred[wg * 64 + rlo] = l_lo;  lred[wg * 64 + rhi] = l_hi;
    }
    __syncthreads();
    float M_lo = fmaxf(mred[rlo], mred[64 + rlo]);
    float M_hi = fmaxf(mred[rhi], mred[64 + rhi]);
    float L_lo = lred[rlo] * __expf(mred[rlo] - M_lo)
               + lred[64 + rlo] * __expf(mred[64 + rlo] - M_lo);
    float L_hi = lred[rhi] * __expf(mred[rhi] - M_hi)
               + lred[64 + rhi] * __expf(mred[64 + rhi] - M_hi);
    float sc_lo = __expf(m_lo - M_lo);
    float sc_hi = __expf(m_hi - M_hi);
#pragma unroll
    for (int nt = 0; nt < 16; nt++) {
        oacc[nt][0] *= sc_lo; oacc[nt][1] *= sc_lo;
        oacc[nt][2] *= sc_hi; oacc[nt][3] *= sc_hi;
    }

    const size_t pbase = ((size_t)sp * NB * NH + bh) * QL;
    if (tig == 0 && wg == 0) {
        g_pm[pbase + rlo] = M_lo;  g_pm[pbase + rhi] = M_hi;
        g_pl[pbase + rlo] = L_lo;  g_pl[pbase + rhi] = L_hi;
    }

    float* OsmF = (float*)smc;   // reuse raw slot 0: 64x128 fp32
    if (wg == 0) {
#pragma unroll
        for (int nt = 0; nt < 16; nt++) {
            const int col = nt * 8 + 2 * tig;
            *(float2*)&OsmF[rlo * 128 + col] = make_float2(oacc[nt][0], oacc[nt][1]);
            *(float2*)&OsmF[rhi * 128 + col] = make_float2(oacc[nt][2], oacc[nt][3]);
        }
    }
    __syncthreads();
    if (wg == 1) {
#pragma unroll
        for (int nt = 0; nt < 16; nt++) {
            const int col = nt * 8 + 2 * tig;
            float2 v0 = *(float2*)&OsmF[rlo * 128 + col];
            float2 v1 = *(float2*)&OsmF[rhi * 128 + col];
            *(float2*)&OsmF[rlo * 128 + col] = make_float2(oacc[nt][0] + v0.x, oacc[nt][1] + v0.y);
            *(float2*)&OsmF[rhi * 128 + col] = make_float2(oacc[nt][2] + v1.x, oacc[nt][3] + v1.y);
        }
    }
    __syncthreads();

    float* pO = g_pO + pbase * HD;
    for (int e = tid * 4; e < QL * HD; e += 1024)
        *(float4*)(pO + e) = *(const float4*)&OsmF[e];
}

// ---------------------------------------------------------------------------
// merge the 4 splits -> fp16 attention output
// ---------------------------------------------------------------------------
__global__ __launch_bounds__(256) void merge_k()
{
    __shared__ float sc[SPLIT][64];
    const int bh = blockIdx.x, h = bh & 31, b = bh >> 5;
    const int tid = threadIdx.x;

    if (tid < 64) {
        float m[SPLIT], l[SPLIT];
#pragma unroll
        for (int s = 0; s < SPLIT; s++) {
            size_t pb = ((size_t)s * NB * NH + bh) * QL + tid;
            m[s] = g_pm[pb];  l[s] = g_pl[pb];
        }
        float M = m[0];
#pragma unroll
        for (int s = 1; s < SPLIT; s++) M = fmaxf(M, m[s]);
        float L = 0.f;
#pragma unroll
        for (int s = 0; s < SPLIT; s++) L += l[s] * __expf(m[s] - M);
        float invL = 1.f / L;
#pragma unroll
        for (int s = 0; s < SPLIT; s++) sc[s][tid] = __expf(m[s] - M) * invL;
    }
    __syncthreads();

    for (int e = tid * 4; e < QL * HD; e += 1024) {
        int row = e >> 7, dd = e & 127;
        float4 acc = make_float4(0.f, 0.f, 0.f, 0.f);
#pragma unroll
        for (int s = 0; s < SPLIT; s++) {
            const float* pO = g_pO + (((size_t)s * NB * NH + bh) * QL) * HD + e;
            float4 v = *(const float4*)pO;
            float f = sc[s][row];
            acc.x += f * v.x; acc.y += f * v.y; acc.z += f * v.z; acc.w += f * v.w;
        }
        *(uint2*)(g_attn_h + (size_t)(b * QL + row) * HID + h * HD + dd) =
            make_uint2(pack2(acc.x, acc.y), pack2(acc.z, acc.w));
    }
}

// ---------------------------------------------------------------------------
extern "C" void kernel_launch(void* const* d_in, const int* in_sizes, int n_in,
                              void* d_out, int out_size)
{
    const float* hs   = (const float*)d_in[0];
    const float* th   = (const float*)d_in[1];
    const float* cosb = (const float*)d_in[2];
    const float* sinb = (const float*)d_in[3];
    const float* Wqkv = (const float*)d_in[4];
    const float* Wo   = (const float*)d_in[5];
    const float* qw   = (const float*)d_in[6];
    float* out = (float*)d_out;

    float *qraw_p;
    half *hs_h, *attn_h_p, *wq_h, *wo_h;
    cudaGetSymbolAddress((void**)&qraw_p, g_qraw);
    cudaGetSymbolAddress((void**)&hs_h,   g_hs_h);
    cudaGetSymbolAddress((void**)&attn_h_p, g_attn_h);
    cudaGetSymbolAddress((void**)&wq_h,   g_wq_h);
    cudaGetSymbolAddress((void**)&wo_h,   g_wo_h);

    cudaFuncSetAttribute(hgemm2, cudaFuncAttributeMaxDynamicSharedMemorySize, GSMEM_BYTES);
    cudaFuncSetAttribute(attn_h, cudaFuncAttributeMaxDynamicSharedMemorySize, ASMEM_BYTES);

    // preps
    cvt_f2h<<<16384, 256>>>(Wqkv, wq_h, 3 * HID);
    cvt_f2h<<<1024,  256>>>(hs,   hs_h, HID);
    cvt_f2h<<<16384, 256>>>(Wo,   wo_h, HID);
    cs_prep<<<TOT * HD / 256, 256>>>(cosb, sinb);

    dim3 gg(32, 8);
    hgemm2<<<gg, 128, GSMEM_BYTES>>>(hs_h, wq_h, qraw_p);
    qnorm_rope_k<<<1024, 256>>>(cosb, sinb, qw);
    attn_h<<<dim3(NB * NH, SPLIT), 256, ASMEM_BYTES>>>(th, hs);
    merge_k<<<NB * NH, 256>>>();
    hgemm2<<<gg, 128, GSMEM_BYTES>>>(attn_h_p, wo_h, out);
}

// round 7
// speedup vs baseline: 6.0671x; 1.0929x over previous
#include <cuda_runtime.h>
#include <cuda_fp16.h>
#include <math.h>
#include <stdint.h>

#define NB    4
#define QL    64
#define NH    32
#define HD    128
#define CTX   4096
#define TOT   4160
#define HID   4096
#define EPSR  1e-6f
#define INV_SQRT_D 0.08838834764831843f
#define SPLIT 4

__device__ float g_qraw[NB * QL * HID];
__device__ float g_q   [NB * NH * QL * HD];
__device__ half  g_hs_h [NB * QL * HID];
__device__ half  g_attn_h[NB * QL * HID];
__device__ half  g_wq_h[HID * HID];
__device__ half  g_wo_h[HID * HID];
__device__ uint32_t g_csh[TOT * HD];                 // packed (cos,sin) fp16
__device__ float g_pO[SPLIT * NB * NH * QL * HD];
__device__ float g_pm[SPLIT * NB * NH * QL];
__device__ float g_pl[SPLIT * NB * NH * QL];

// ---------------------------------------------------------------------------
// helpers
// ---------------------------------------------------------------------------
__device__ __forceinline__ uint32_t smaddr(const void* p) {
    return (uint32_t)__cvta_generic_to_shared(p);
}
__device__ __forceinline__ void ldsm4(uint32_t& r0, uint32_t& r1, uint32_t& r2, uint32_t& r3, uint32_t a) {
    asm volatile("ldmatrix.sync.aligned.m8n8.x4.shared.b16 {%0,%1,%2,%3}, [%4];"
                 : "=r"(r0), "=r"(r1), "=r"(r2), "=r"(r3) : "r"(a));
}
__device__ __forceinline__ void ldsm4t(uint32_t& r0, uint32_t& r1, uint32_t& r2, uint32_t& r3, uint32_t a) {
    asm volatile("ldmatrix.sync.aligned.m8n8.x4.trans.shared.b16 {%0,%1,%2,%3}, [%4];"
                 : "=r"(r0), "=r"(r1), "=r"(r2), "=r"(r3) : "r"(a));
}
__device__ __forceinline__ void mma16816(float d[4],
                                         uint32_t a0, uint32_t a1, uint32_t a2, uint32_t a3,
                                         uint32_t b0, uint32_t b1) {
    asm volatile(
        "mma.sync.aligned.m16n8k16.row.col.f32.f16.f16.f32 "
        "{%0,%1,%2,%3},{%4,%5,%6,%7},{%8,%9},{%0,%1,%2,%3};"
        : "+f"(d[0]), "+f"(d[1]), "+f"(d[2]), "+f"(d[3])
        : "r"(a0), "r"(a1), "r"(a2), "r"(a3), "r"(b0), "r"(b1));
}
__device__ __forceinline__ uint32_t pack2(float x, float y) {
    __half2 h = __floats2half2_rn(x, y);
    return *(uint32_t*)&h;
}
__device__ __forceinline__ void cpa16(uint32_t dst, const void* src) {
    asm volatile("cp.async.cg.shared.global [%0], [%1], 16;" :: "r"(dst), "l"(src));
}
#define CP_COMMIT() asm volatile("cp.async.commit_group;")
#define CP_WAIT(n)  asm volatile("cp.async.wait_group %0;" :: "n"(n))

// ---------------------------------------------------------------------------
// fp32 -> fp16 conversion, 16 elems/thread (MLP 4). cols fixed at 4096.
// ---------------------------------------------------------------------------
__global__ __launch_bounds__(256) void cvt_f2h(const float* __restrict__ src,
                                               half* __restrict__ dst, int ld)
{
    size_t i = ((size_t)blockIdx.x * 256 + threadIdx.x) * 16;
    size_t row = i >> 12;
    int    col = (int)(i & 4095);
    const float* s = src + row * (size_t)ld + col;
    half* d = dst + row * 4096 + col;
    float4 v0 = *(const float4*)(s);
    float4 v1 = *(const float4*)(s + 4);
    float4 v2 = *(const float4*)(s + 8);
    float4 v3 = *(const float4*)(s + 12);
    *(uint2*)(d)      = make_uint2(pack2(v0.x, v0.y), pack2(v0.z, v0.w));
    *(uint2*)(d + 4)  = make_uint2(pack2(v1.x, v1.y), pack2(v1.z, v1.w));
    *(uint2*)(d + 8)  = make_uint2(pack2(v2.x, v2.y), pack2(v2.z, v2.w));
    *(uint2*)(d + 12) = make_uint2(pack2(v3.x, v3.y), pack2(v3.z, v3.w));
}

// packed (cos,sin) fp16 table
__global__ __launch_bounds__(256) void cs_prep(const float* __restrict__ cosb,
                                               const float* __restrict__ sinb)
{
    int i = blockIdx.x * 256 + threadIdx.x;
    g_csh[i] = pack2(cosb[i], sinb[i]);
}

// ---------------------------------------------------------------------------
// fp16 GEMM, BM=32 BN=64 BK=64, 128 threads, 4-stage cp.async, 4 CTAs/SM.
// C[256,4096] = A[256,4096]h @ B[4096,4096]h. Grid (64, 8).
// ---------------------------------------------------------------------------
#define G3_ASLOT 4608            // 32 * 144
#define G3_BSLOT 9216            // 64 * 144
#define G3_STAGE (G3_ASLOT + G3_BSLOT)
#define G3_SMEM  (4 * G3_STAGE)  // 55296

__global__ __launch_bounds__(128, 4) void hgemm3(const half* __restrict__ A,
                                                 const half* __restrict__ B,
                                                 float* __restrict__ C)
{
    extern __shared__ char smc[];
    const uint32_t smBase = smaddr(smc);
    const int tid = threadIdx.x, lane = tid & 31, wid = tid >> 5;
    const int gid = lane >> 2, tig = lane & 3;
    const int wm = wid >> 1, wn = wid & 1;
    const int bx = blockIdx.x, by = blockIdx.y;

    const half* Ab = A + (size_t)(by * 32) * HID;
    const half* Bb = B + (size_t)(bx * 64);

    float acc[4][4];
#pragma unroll
    for (int nt = 0; nt < 4; nt++)
#pragma unroll
        for (int i = 0; i < 4; i++) acc[nt][i] = 0.f;

    const uint32_t aOff = (uint32_t)((wm * 16 + (lane & 15)) * 144 + (lane >> 4) * 16);
    const uint32_t bOff = (uint32_t)(((lane & 7) + 8 * ((lane >> 3) & 1)) * 144
                                     + (wn * 32 + 8 * (lane >> 4)) * 2);

    auto load_stage = [&](int kt) {
        const int slot = kt & 3;
        const int k0 = kt * 64;
        const uint32_t aS = smBase + slot * G3_STAGE;
        const uint32_t bS = aS + G3_ASLOT;
#pragma unroll
        for (int i = 0; i < 2; i++) {
            int u = tid + i * 128, r = u >> 3, c = u & 7;
            cpa16(aS + r * 144 + c * 16, Ab + (size_t)r * HID + k0 + c * 8);
        }
#pragma unroll
        for (int i = 0; i < 4; i++) {
            int u = tid + i * 128, r = u >> 3, c = u & 7;
            cpa16(bS + r * 144 + c * 16, Bb + (size_t)(k0 + r) * HID + c * 8);
        }
        CP_COMMIT();
    };

    load_stage(0); load_stage(1); load_stage(2);

    const int NK = HID / 64;   // 64
    for (int kt = 0; kt < NK; kt++) {
        CP_WAIT(2);
        __syncthreads();
        if (kt + 3 < NK) load_stage(kt + 3); else CP_COMMIT();

        const uint32_t aA = smBase + (kt & 3) * G3_STAGE + aOff;
        const uint32_t bA = smBase + (kt & 3) * G3_STAGE + G3_ASLOT + bOff;
#pragma unroll
        for (int kk = 0; kk < 4; kk++) {
            uint32_t x0, x1, x2, x3;
            ldsm4(x0, x1, x2, x3, aA + kk * 32);
#pragma unroll
            for (int nt2 = 0; nt2 < 2; nt2++) {
                uint32_t b0, b1, b2, b3;
                ldsm4t(b0, b1, b2, b3, bA + kk * 16 * 144 + nt2 * 32);
                mma16816(acc[nt2 * 2],     x0, x1, x2, x3, b0, b1);
                mma16816(acc[nt2 * 2 + 1], x0, x1, x2, x3, b2, b3);
            }
        }
    }

    const int row = by * 32 + wm * 16 + gid;
#pragma unroll
    for (int nt = 0; nt < 4; nt++) {
        const int col = bx * 64 + wn * 32 + nt * 8 + 2 * tig;
        *(float2*)(C + (size_t)row * HID + col) =
            make_float2(acc[nt][0], acc[nt][1]);
        *(float2*)(C + (size_t)(row + 8) * HID + col) =
            make_float2(acc[nt][2], acc[nt][3]);
    }
}

// ---------------------------------------------------------------------------
// Q: double RMSNorm + RoPE + fold 1/sqrt(D).
// ---------------------------------------------------------------------------
__global__ __launch_bounds__(256) void qnorm_rope_k(const float* __restrict__ cosb,
                                                    const float* __restrict__ sinb,
                                                    const float* __restrict__ w)
{
    const int gw   = (blockIdx.x * 256 + threadIdx.x) >> 5;
    const int lane = threadIdx.x & 31;
    const int h = gw & 31;
    const int q = (gw >> 5) & 63;
    const int b = gw >> 11;

    const float* src = g_qraw + (size_t)(b * QL + q) * HID + h * HD + lane * 4;
    float4 x4 = *(const float4*)src;
    float  x[4] = {x4.x, x4.y, x4.z, x4.w};
    float4 w4 = *(const float4*)(w + lane * 4);
    float  wv[4] = {w4.x, w4.y, w4.z, w4.w};

    float ss = x[0]*x[0] + x[1]*x[1] + x[2]*x[2] + x[3]*x[3];
#pragma unroll
    for (int o = 16; o > 0; o >>= 1) ss += __shfl_xor_sync(0xffffffffu, ss, o);
    float r1 = rsqrtf(ss * (1.f / 128.f) + EPSR);

    float y[4];
#pragma unroll
    for (int j = 0; j < 4; j++) y[j] = x[j] * r1 * wv[j];

    float ss2 = y[0]*y[0] + y[1]*y[1] + y[2]*y[2] + y[3]*y[3];
#pragma unroll
    for (int o = 16; o > 0; o >>= 1) ss2 += __shfl_xor_sync(0xffffffffu, ss2, o);
    float r2 = rsqrtf(ss2 * (1.f / 128.f) + EPSR);

    float z[4];
#pragma unroll
    for (int j = 0; j < 4; j++) z[j] = y[j] * r2 * wv[j];

    const float4 c4 = *(const float4*)(cosb + (size_t)(CTX + q) * HD + lane * 4);
    const float4 s4 = *(const float4*)(sinb + (size_t)(CTX + q) * HD + lane * 4);
    const float cf[4] = {c4.x, c4.y, c4.z, c4.w};
    const float sf[4] = {s4.x, s4.y, s4.z, s4.w};

    float o_[4];
#pragma unroll
    for (int j = 0; j < 4; j++) {
        float p   = __shfl_xor_sync(0xffffffffu, z[j], 16);
        float rot = (lane < 16) ? -p : p;
        o_[j] = (z[j] * cf[j] + rot * sf[j]) * INV_SQRT_D;
    }
    float* dst = g_q + (size_t)((b * NH + h) * QL + q) * HD + lane * 4;
    *(float4*)dst = make_float4(o_[0], o_[1], o_[2], o_[3]);
}

// ---------------------------------------------------------------------------
// KV-split flash attention (pair-wise rope convert, halved LDS traffic).
// Grid (128 bh, 4 split), 256 threads, 2 CTAs/SM.
// ---------------------------------------------------------------------------
#define A_RAW_SLOT 32768                      // 64*128*4
#define A_KH_BASE  (2 * A_RAW_SLOT)           // 65536
#define A_VH_BASE  (A_KH_BASE + 17408)
#define A_MRED     (A_VH_BASE + 17408)
#define ASMEM_BYTES (A_MRED + 1024)

__global__ __launch_bounds__(256, 2) void attn_h(const float* __restrict__ th,
                                                 const float* __restrict__ hs)
{
    extern __shared__ char smc[];
    const uint32_t smBase = smaddr(smc);
    half*  Kh   = (half*)(smc + A_KH_BASE);
    half*  Vh   = (half*)(smc + A_VH_BASE);
    float* mred = (float*)(smc + A_MRED);
    float* lred = mred + 128;

    const int bh = blockIdx.x, h = bh & 31, b = bh >> 5;
    const int sp = blockIdx.y;
    const int c0 = (sp == 0) ? 0 : 17 + (sp - 1) * 16;
    const int c1 = (sp == 0) ? 17 : c0 + 16;

    const int tid = threadIdx.x, lane = tid & 31, wid = tid >> 5;
    const int gid = lane >> 2, tig = lane & 3;
    const int wq = wid >> 1, wg = wid & 1;
    const int r0 = wq * 16, j0 = wg * 32;

    const float* thb = th + (size_t)b * CTX * HID + h * HD;
    const float* hsb = hs + (size_t)b * QL  * HID + h * HD;

    auto load_chunk = [&](int c) {
        const uint32_t rS = smBase + (c & 1) * A_RAW_SLOT;
        const float* base = (c < 64) ? (thb + (size_t)c * 64 * HID) : hsb;
#pragma unroll
        for (int i = 0; i < 8; i++) {
            int u = tid + i * 256, j = u >> 5, d4 = u & 31;
            cpa16(rS + j * 512 + d4 * 16, base + (size_t)j * HID + d4 * 4);
        }
        CP_COMMIT();
    };

    load_chunk(c0); load_chunk(c0 + 1);

    // Q staging (via Kh temp) -> register fragments
    const float* qsrc = g_q + (size_t)bh * (QL * HD);
    for (int e = tid * 4; e < QL * HD; e += 1024) {
        int j = e >> 7, dd = e & 127;
        float4 v = *(const float4*)(qsrc + e);
        *(uint2*)&Kh[j * 136 + dd] = make_uint2(pack2(v.x, v.y), pack2(v.z, v.w));
    }
    __syncthreads();
    uint32_t qa[8][4];
    {
        const uint32_t qA = smBase + A_KH_BASE
                          + (uint32_t)((r0 + (lane & 15)) * 272 + (lane >> 4) * 16);
#pragma unroll
        for (int kd = 0; kd < 8; kd++)
            ldsm4(qa[kd][0], qa[kd][1], qa[kd][2], qa[kd][3], qA + kd * 32);
    }

    const uint32_t kA = smBase + A_KH_BASE
        + (uint32_t)((j0 + (lane & 7) + 8 * (lane >> 4)) * 272 + ((lane >> 3) & 1) * 16);
    const uint32_t vA = smBase + A_VH_BASE
        + (uint32_t)((j0 + (lane & 7) + 8 * ((lane >> 3) & 1)) * 272 + (lane >> 4) * 16);

    float m_lo = -1e30f, m_hi = -1e30f, l_lo = 0.f, l_hi = 0.f;
    float oacc[16][4];
#pragma unroll
    for (int nt = 0; nt < 16; nt++)
#pragma unroll
        for (int i = 0; i < 4; i++) oacc[nt][i] = 0.f;

    for (int t = c0; t < c1; t++) {
        CP_WAIT(1);
        __syncthreads();

        // convert: rope pairs (dd, dd+64) in one pass
        {
            const float* rw = (const float*)(smc + (t & 1) * A_RAW_SLOT);
            const int p0 = t * 64;
#pragma unroll
            for (int e = tid * 4; e < 64 * 64; e += 1024) {
                int j = e >> 6, dl = e & 63;
                int p = p0 + j;
                float4 vlo = *(const float4*)&rw[j * 128 + dl];
                float4 vhi = *(const float4*)&rw[j * 128 + dl + 64];
                uint2 clu = *(const uint2*)&g_csh[(size_t)p * HD + dl];
                uint2 chu = *(const uint2*)&g_csh[(size_t)p * HD + dl + 64];
                uint2 clu2 = *(const uint2*)&g_csh[(size_t)p * HD + dl + 2];
                uint2 chu2 = *(const uint2*)&g_csh[(size_t)p * HD + dl + 66];
                float2 cs0 = __half22float2(*(__half2*)&clu.x);
                float2 cs1 = __half22float2(*(__half2*)&clu.y);
                float2 cs2 = __half22float2(*(__half2*)&clu2.x);
                float2 cs3 = __half22float2(*(__half2*)&clu2.y);
                float2 ch0 = __half22float2(*(__half2*)&chu.x);
                float2 ch1 = __half22float2(*(__half2*)&chu.y);
                float2 ch2 = __half22float2(*(__half2*)&chu2.x);
                float2 ch3 = __half22float2(*(__half2*)&chu2.y);
                // V (raw)
                *(uint2*)&Vh[j * 136 + dl]      = make_uint2(pack2(vlo.x, vlo.y), pack2(vlo.z, vlo.w));
                *(uint2*)&Vh[j * 136 + dl + 64] = make_uint2(pack2(vhi.x, vhi.y), pack2(vhi.z, vhi.w));
                // K roped: lo = v*c - pair*s ; hi = v*c + pair*s
                float klo0 = vlo.x * cs0.x - vhi.x * cs0.y;
                float klo1 = vlo.y * cs1.x - vhi.y * cs1.y;
                float klo2 = vlo.z * cs2.x - vhi.z * cs2.y;
                float klo3 = vlo.w * cs3.x - vhi.w * cs3.y;
                float khi0 = vhi.x * ch0.x + vlo.x * ch0.y;
                float khi1 = vhi.y * ch1.x + vlo.y * ch1.y;
                float khi2 = vhi.z * ch2.x + vlo.z * ch2.y;
                float khi3 = vhi.w * ch3.x + vlo.w * ch3.y;
                *(uint2*)&Kh[j * 136 + dl]      = make_uint2(pack2(klo0, klo1), pack2(klo2, klo3));
                *(uint2*)&Kh[j * 136 + dl + 64] = make_uint2(pack2(khi0, khi1), pack2(khi2, khi3));
            }
        }
        __syncthreads();
        if (t + 2 < c1) load_chunk(t + 2); else CP_COMMIT();

        // QK^T
        float sacc[4][4];
#pragma unroll
        for (int nt = 0; nt < 4; nt++)
#pragma unroll
            for (int i = 0; i < 4; i++) sacc[nt][i] = 0.f;
#pragma unroll
        for (int kd = 0; kd < 8; kd++) {
#pragma unroll
            for (int jt = 0; jt < 2; jt++) {
                uint32_t b0, b1, b2, b3;
                ldsm4(b0, b1, b2, b3, kA + jt * 16 * 272 + kd * 32);
                mma16816(sacc[jt * 2],     qa[kd][0], qa[kd][1], qa[kd][2], qa[kd][3], b0, b1);
                mma16816(sacc[jt * 2 + 1], qa[kd][0], qa[kd][1], qa[kd][2], qa[kd][3], b2, b3);
            }
        }

        // online softmax
        float mx_lo = -1e30f, mx_hi = -1e30f;
#pragma unroll
        for (int nt = 0; nt < 4; nt++) {
            mx_lo = fmaxf(mx_lo, fmaxf(sacc[nt][0], sacc[nt][1]));
            mx_hi = fmaxf(mx_hi, fmaxf(sacc[nt][2], sacc[nt][3]));
        }
        mx_lo = fmaxf(mx_lo, __shfl_xor_sync(0xffffffffu, mx_lo, 1));
        mx_lo = fmaxf(mx_lo, __shfl_xor_sync(0xffffffffu, mx_lo, 2));
        mx_hi = fmaxf(mx_hi, __shfl_xor_sync(0xffffffffu, mx_hi, 1));
        mx_hi = fmaxf(mx_hi, __shfl_xor_sync(0xffffffffu, mx_hi, 2));

        float nm_lo = fmaxf(m_lo, mx_lo), nm_hi = fmaxf(m_hi, mx_hi);
        float al_lo = __expf(m_lo - nm_lo), al_hi = __expf(m_hi - nm_hi);
        float sum_lo = 0.f, sum_hi = 0.f;
        uint32_t pa0[4], pa1[4];
#pragma unroll
        for (int nt = 0; nt < 4; nt++) {
            float e0 = __expf(sacc[nt][0] - nm_lo);
            float e1 = __expf(sacc[nt][1] - nm_lo);
            float e2 = __expf(sacc[nt][2] - nm_hi);
            float e3 = __expf(sacc[nt][3] - nm_hi);
            sum_lo += e0 + e1;  sum_hi += e2 + e3;
            pa0[nt] = pack2(e0, e1);
            pa1[nt] = pack2(e2, e3);
        }
        sum_lo += __shfl_xor_sync(0xffffffffu, sum_lo, 1);
        sum_lo += __shfl_xor_sync(0xffffffffu, sum_lo, 2);
        sum_hi += __shfl_xor_sync(0xffffffffu, sum_hi, 1);
        sum_hi += __shfl_xor_sync(0xffffffffu, sum_hi, 2);
        l_lo = l_lo * al_lo + sum_lo;  l_hi = l_hi * al_hi + sum_hi;
        m_lo = nm_lo;  m_hi = nm_hi;

#pragma unroll
        for (int nt = 0; nt < 16; nt++) {
            oacc[nt][0] *= al_lo; oacc[nt][1] *= al_lo;
            oacc[nt][2] *= al_hi; oacc[nt][3] *= al_hi;
        }

        // PV
#pragma unroll
        for (int kc = 0; kc < 2; kc++) {
            uint32_t a0 = pa0[2 * kc], a1 = pa1[2 * kc];
            uint32_t a2 = pa0[2 * kc + 1], a3 = pa1[2 * kc + 1];
#pragma unroll
            for (int dt = 0; dt < 8; dt++) {
                uint32_t b0, b1, b2, b3;
                ldsm4t(b0, b1, b2, b3, vA + kc * 16 * 272 + dt * 32);
                mma16816(oacc[dt * 2],     a0, a1, a2, a3, b0, b1);
                mma16816(oacc[dt * 2 + 1], a0, a1, a2, a3, b2, b3);
            }
        }
    }

    CP_WAIT(0);
    // in-CTA merge of the 2 key stripes -> partial (unnormalized O, m, l)
    const int rlo = r0 + gid, rhi = r0 + gid + 8;
    if (tig == 0) {
        mred[wg * 64 + rlo] = m_lo;  mred[wg * 64 + rhi] = m_hi;
        lred[wg * 64 + rlo] = l_lo;  lred[wg * 64 + rhi] = l_hi;
    }
    __syncthreads();
    float M_lo = fmaxf(mred[rlo], mred[64 + rlo]);
    float M_hi = fmaxf(mred[rhi], mred[64 + rhi]);
    float L_lo = lred[rlo] * __expf(mred[rlo] - M_lo)
               + lred[64 + rlo] * __expf(mred[64 + rlo] - M_lo);
    float L_hi = lred[rhi] * __expf(mred[rhi] - M_hi)
               + lred[64 + rhi] * __expf(mred[64 + rhi] - M_hi);
    float sc_lo = __expf(m_lo - M_lo);
    float sc_hi = __expf(m_hi - M_hi);
#pragma unroll
    for (int nt = 0; nt < 16; nt++) {
        oacc[nt][0] *= sc_lo; oacc[nt][1] *= sc_lo;
        oacc[nt][2] *= sc_hi; oacc[nt][3] *= sc_hi;
    }

    const size_t pbase = ((size_t)sp * NB * NH + bh) * QL;
    if (tig == 0 && wg == 0) {
        g_pm[pbase + rlo] = M_lo;  g_pm[pbase + rhi] = M_hi;
        g_pl[pbase + rlo] = L_lo;  g_pl[pbase + rhi] = L_hi;
    }

    float* OsmF = (float*)smc;
    if (wg == 0) {
#pragma unroll
        for (int nt = 0; nt < 16; nt++) {
            const int col = nt * 8 + 2 * tig;
            *(float2*)&OsmF[rlo * 128 + col] = make_float2(oacc[nt][0], oacc[nt][1]);
            *(float2*)&OsmF[rhi * 128 + col] = make_float2(oacc[nt][2], oacc[nt][3]);
        }
    }
    __syncthreads();
    if (wg == 1) {
#pragma unroll
        for (int nt = 0; nt < 16; nt++) {
            const int col = nt * 8 + 2 * tig;
            float2 v0 = *(float2*)&OsmF[rlo * 128 + col];
            float2 v1 = *(float2*)&OsmF[rhi * 128 + col];
            *(float2*)&OsmF[rlo * 128 + col] = make_float2(oacc[nt][0] + v0.x, oacc[nt][1] + v0.y);
            *(float2*)&OsmF[rhi * 128 + col] = make_float2(oacc[nt][2] + v1.x, oacc[nt][3] + v1.y);
        }
    }
    __syncthreads();

    float* pO = g_pO + pbase * HD;
    for (int e = tid * 4; e < QL * HD; e += 1024)
        *(float4*)(pO + e) = *(const float4*)&OsmF[e];
}

// ---------------------------------------------------------------------------
// merge the 4 splits -> fp16 attention output
// ---------------------------------------------------------------------------
__global__ __launch_bounds__(256) void merge_k()
{
    __shared__ float sc[SPLIT][64];
    const int bh = blockIdx.x, h = bh & 31, b = bh >> 5;
    const int tid = threadIdx.x;

    if (tid < 64) {
        float m[SPLIT], l[SPLIT];
#pragma unroll
        for (int s = 0; s < SPLIT; s++) {
            size_t pb = ((size_t)s * NB * NH + bh) * QL + tid;
            m[s] = g_pm[pb];  l[s] = g_pl[pb];
        }
        float M = m[0];
#pragma unroll
        for (int s = 1; s < SPLIT; s++) M = fmaxf(M, m[s]);
        float L = 0.f;
#pragma unroll
        for (int s = 0; s < SPLIT; s++) L += l[s] * __expf(m[s] - M);
        float invL = 1.f / L;
#pragma unroll
        for (int s = 0; s < SPLIT; s++) sc[s][tid] = __expf(m[s] - M) * invL;
    }
    __syncthreads();

    for (int e = tid * 4; e < QL * HD; e += 1024) {
        int row = e >> 7, dd = e & 127;
        float4 acc = make_float4(0.f, 0.f, 0.f, 0.f);
#pragma unroll
        for (int s = 0; s < SPLIT; s++) {
            const float* pO = g_pO + (((size_t)s * NB * NH + bh) * QL) * HD + e;
            float4 v = *(const float4*)pO;
            float f = sc[s][row];
            acc.x += f * v.x; acc.y += f * v.y; acc.z += f * v.z; acc.w += f * v.w;
        }
        *(uint2*)(g_attn_h + (size_t)(b * QL + row) * HID + h * HD + dd) =
            make_uint2(pack2(acc.x, acc.y), pack2(acc.z, acc.w));
    }
}

// ---------------------------------------------------------------------------
extern "C" void kernel_launch(void* const* d_in, const int* in_sizes, int n_in,
                              void* d_out, int out_size)
{
    const float* hs   = (const float*)d_in[0];
    const float* th   = (const float*)d_in[1];
    const float* cosb = (const float*)d_in[2];
    const float* sinb = (const float*)d_in[3];
    const float* Wqkv = (const float*)d_in[4];
    const float* Wo   = (const float*)d_in[5];
    const float* qw   = (const float*)d_in[6];
    float* out = (float*)d_out;

    float *qraw_p;
    half *hs_h, *attn_h_p, *wq_h, *wo_h;
    cudaGetSymbolAddress((void**)&qraw_p, g_qraw);
    cudaGetSymbolAddress((void**)&hs_h,   g_hs_h);
    cudaGetSymbolAddress((void**)&attn_h_p, g_attn_h);
    cudaGetSymbolAddress((void**)&wq_h,   g_wq_h);
    cudaGetSymbolAddress((void**)&wo_h,   g_wo_h);

    cudaFuncSetAttribute(hgemm3, cudaFuncAttributeMaxDynamicSharedMemorySize, G3_SMEM);
    cudaFuncSetAttribute(attn_h, cudaFuncAttributeMaxDynamicSharedMemorySize, ASMEM_BYTES);

    // preps
    cvt_f2h<<<4096, 256>>>(Wqkv, wq_h, 3 * HID);
    cvt_f2h<<<256,  256>>>(hs,   hs_h, HID);
    cvt_f2h<<<4096, 256>>>(Wo,   wo_h, HID);
    cs_prep<<<TOT * HD / 256, 256>>>(cosb, sinb);

    dim3 gg(64, 8);
    hgemm3<<<gg, 128, G3_SMEM>>>(hs_h, wq_h, qraw_p);
    qnorm_rope_k<<<1024, 256>>>(cosb, sinb, qw);
    attn_h<<<dim3(NB * NH, SPLIT), 256, ASMEM_BYTES>>>(th, hs);
    merge_k<<<NB * NH, 256>>>();
    hgemm3<<<gg, 128, G3_SMEM>>>(attn_h_p, wo_h, out);
}

// round 8
// speedup vs baseline: 6.0758x; 1.0014x over previous
#include <cuda_runtime.h>
#include <cuda_fp16.h>
#include <math.h>
#include <stdint.h>

#define NB    4
#define QL    64
#define NH    32
#define HD    128
#define CTX   4096
#define TOT   4160
#define HID   4096
#define EPSR  1e-6f
#define INV_SQRT_D 0.08838834764831843f
#define SPLIT 8

__device__ float g_qraw[NB * QL * HID];
__device__ float g_q   [NB * NH * QL * HD];
__device__ half  g_hs_h [NB * QL * HID];
__device__ half  g_attn_h[NB * QL * HID];
__device__ half  g_wq_h[HID * HID];
__device__ half  g_wo_h[HID * HID];
__device__ uint4 g_cs2[TOT * 32];                    // [p][half][g]: c01,c23,±s01,±s23
__device__ float g_pO[SPLIT * NB * NH * QL * HD];
__device__ float g_pm[SPLIT * NB * NH * QL];
__device__ float g_pl[SPLIT * NB * NH * QL];

// ---------------------------------------------------------------------------
// helpers
// ---------------------------------------------------------------------------
__device__ __forceinline__ uint32_t smaddr(const void* p) {
    return (uint32_t)__cvta_generic_to_shared(p);
}
__device__ __forceinline__ void ldsm4(uint32_t& r0, uint32_t& r1, uint32_t& r2, uint32_t& r3, uint32_t a) {
    asm volatile("ldmatrix.sync.aligned.m8n8.x4.shared.b16 {%0,%1,%2,%3}, [%4];"
                 : "=r"(r0), "=r"(r1), "=r"(r2), "=r"(r3) : "r"(a));
}
__device__ __forceinline__ void ldsm4t(uint32_t& r0, uint32_t& r1, uint32_t& r2, uint32_t& r3, uint32_t a) {
    asm volatile("ldmatrix.sync.aligned.m8n8.x4.trans.shared.b16 {%0,%1,%2,%3}, [%4];"
                 : "=r"(r0), "=r"(r1), "=r"(r2), "=r"(r3) : "r"(a));
}
__device__ __forceinline__ void mma16816(float d[4],
                                         uint32_t a0, uint32_t a1, uint32_t a2, uint32_t a3,
                                         uint32_t b0, uint32_t b1) {
    asm volatile(
        "mma.sync.aligned.m16n8k16.row.col.f32.f16.f16.f32 "
        "{%0,%1,%2,%3},{%4,%5,%6,%7},{%8,%9},{%0,%1,%2,%3};"
        : "+f"(d[0]), "+f"(d[1]), "+f"(d[2]), "+f"(d[3])
        : "r"(a0), "r"(a1), "r"(a2), "r"(a3), "r"(b0), "r"(b1));
}
__device__ __forceinline__ uint32_t pack2(float x, float y) {
    __half2 h = __floats2half2_rn(x, y);
    return *(uint32_t*)&h;
}
__device__ __forceinline__ uint32_t hfma2u(uint32_t a, uint32_t b, uint32_t c) {
    // a*b + c  on packed half2
    __half2 r = __hfma2(*(__half2*)&a, *(__half2*)&b, *(__half2*)&c);
    return *(uint32_t*)&r;
}
__device__ __forceinline__ uint32_t hmul2u(uint32_t a, uint32_t b) {
    __half2 r = __hmul2(*(__half2*)&a, *(__half2*)&b);
    return *(uint32_t*)&r;
}
__device__ __forceinline__ void cpa16(uint32_t dst, const void* src) {
    asm volatile("cp.async.cg.shared.global [%0], [%1], 16;" :: "r"(dst), "l"(src));
}
#define CP_COMMIT() asm volatile("cp.async.commit_group;")
#define CP_WAIT(n)  asm volatile("cp.async.wait_group %0;" :: "n"(n))

// ---------------------------------------------------------------------------
// fp32 -> fp16 conversion, 16 elems/thread. cols fixed at 4096.
// ---------------------------------------------------------------------------
__global__ __launch_bounds__(256) void cvt_f2h(const float* __restrict__ src,
                                               half* __restrict__ dst, int ld)
{
    size_t i = ((size_t)blockIdx.x * 256 + threadIdx.x) * 16;
    size_t row = i >> 12;
    int    col = (int)(i & 4095);
    const float* s = src + row * (size_t)ld + col;
    half* d = dst + row * 4096 + col;
    float4 v0 = *(const float4*)(s);
    float4 v1 = *(const float4*)(s + 4);
    float4 v2 = *(const float4*)(s + 8);
    float4 v3 = *(const float4*)(s + 12);
    *(uint2*)(d)      = make_uint2(pack2(v0.x, v0.y), pack2(v0.z, v0.w));
    *(uint2*)(d + 4)  = make_uint2(pack2(v1.x, v1.y), pack2(v1.z, v1.w));
    *(uint2*)(d + 8)  = make_uint2(pack2(v2.x, v2.y), pack2(v2.z, v2.w));
    *(uint2*)(d + 12) = make_uint2(pack2(v3.x, v3.y), pack2(v3.z, v3.w));
}

// sign-folded packed (c, +/-s) table:
//   g_cs2[p*32 + half*16 + g] = {c2(d0,d1), c2(d2,d3), s'2(d0,d1), s'2(d2,d3)}
//   d0 = half*64 + g*4 ; s' = -s for lo half, +s for hi half
__global__ __launch_bounds__(256) void cs2_prep(const float* __restrict__ cosb,
                                                const float* __restrict__ sinb)
{
    int i = blockIdx.x * 256 + threadIdx.x;     // 0 .. TOT*32-1
    if (i >= TOT * 32) return;
    int g    = i & 15;
    int half_ = (i >> 4) & 1;
    int p    = i >> 5;
    int d0   = half_ * 64 + g * 4;
    const float* cp = cosb + (size_t)p * HD + d0;
    const float* sp = sinb + (size_t)p * HD + d0;
    float4 c = *(const float4*)cp;
    float4 s = *(const float4*)sp;
    float sgn = half_ ? 1.f : -1.f;
    uint4 out;
    out.x = pack2(c.x, c.y);
    out.y = pack2(c.z, c.w);
    out.z = pack2(sgn * s.x, sgn * s.y);
    out.w = pack2(sgn * s.z, sgn * s.w);
    g_cs2[i] = out;
}

// ---------------------------------------------------------------------------
// fp16 GEMM, BM=32 BN=64 BK=64, 128 threads, 4-stage cp.async, 4 CTAs/SM.
// ---------------------------------------------------------------------------
#define G3_ASLOT 4608
#define G3_BSLOT 9216
#define G3_STAGE (G3_ASLOT + G3_BSLOT)
#define G3_SMEM  (4 * G3_STAGE)

__global__ __launch_bounds__(128, 4) void hgemm3(const half* __restrict__ A,
                                                 const half* __restrict__ B,
                                                 float* __restrict__ C)
{
    extern __shared__ char smc[];
    const uint32_t smBase = smaddr(smc);
    const int tid = threadIdx.x, lane = tid & 31, wid = tid >> 5;
    const int gid = lane >> 2, tig = lane & 3;
    const int wm = wid >> 1, wn = wid & 1;
    const int bx = blockIdx.x, by = blockIdx.y;

    const half* Ab = A + (size_t)(by * 32) * HID;
    const half* Bb = B + (size_t)(bx * 64);

    float acc[4][4];
#pragma unroll
    for (int nt = 0; nt < 4; nt++)
#pragma unroll
        for (int i = 0; i < 4; i++) acc[nt][i] = 0.f;

    const uint32_t aOff = (uint32_t)((wm * 16 + (lane & 15)) * 144 + (lane >> 4) * 16);
    const uint32_t bOff = (uint32_t)(((lane & 7) + 8 * ((lane >> 3) & 1)) * 144
                                     + (wn * 32 + 8 * (lane >> 4)) * 2);

    auto load_stage = [&](int kt) {
        const int slot = kt & 3;
        const int k0 = kt * 64;
        const uint32_t aS = smBase + slot * G3_STAGE;
        const uint32_t bS = aS + G3_ASLOT;
#pragma unroll
        for (int i = 0; i < 2; i++) {
            int u = tid + i * 128, r = u >> 3, c = u & 7;
            cpa16(aS + r * 144 + c * 16, Ab + (size_t)r * HID + k0 + c * 8);
        }
#pragma unroll
        for (int i = 0; i < 4; i++) {
            int u = tid + i * 128, r = u >> 3, c = u & 7;
            cpa16(bS + r * 144 + c * 16, Bb + (size_t)(k0 + r) * HID + c * 8);
        }
        CP_COMMIT();
    };

    load_stage(0); load_stage(1); load_stage(2);

    const int NK = HID / 64;
    for (int kt = 0; kt < NK; kt++) {
        CP_WAIT(2);
        __syncthreads();
        if (kt + 3 < NK) load_stage(kt + 3); else CP_COMMIT();

        const uint32_t aA = smBase + (kt & 3) * G3_STAGE + aOff;
        const uint32_t bA = smBase + (kt & 3) * G3_STAGE + G3_ASLOT + bOff;
#pragma unroll
        for (int kk = 0; kk < 4; kk++) {
            uint32_t x0, x1, x2, x3;
            ldsm4(x0, x1, x2, x3, aA + kk * 32);
#pragma unroll
            for (int nt2 = 0; nt2 < 2; nt2++) {
                uint32_t b0, b1, b2, b3;
                ldsm4t(b0, b1, b2, b3, bA + kk * 16 * 144 + nt2 * 32);
                mma16816(acc[nt2 * 2],     x0, x1, x2, x3, b0, b1);
                mma16816(acc[nt2 * 2 + 1], x0, x1, x2, x3, b2, b3);
            }
        }
    }

    const int row = by * 32 + wm * 16 + gid;
#pragma unroll
    for (int nt = 0; nt < 4; nt++) {
        const int col = bx * 64 + wn * 32 + nt * 8 + 2 * tig;
        *(float2*)(C + (size_t)row * HID + col) =
            make_float2(acc[nt][0], acc[nt][1]);
        *(float2*)(C + (size_t)(row + 8) * HID + col) =
            make_float2(acc[nt][2], acc[nt][3]);
    }
}

// ---------------------------------------------------------------------------
// Q: double RMSNorm + RoPE + fold 1/sqrt(D).
// ---------------------------------------------------------------------------
__global__ __launch_bounds__(256) void qnorm_rope_k(const float* __restrict__ cosb,
                                                    const float* __restrict__ sinb,
                                                    const float* __restrict__ w)
{
    const int gw   = (blockIdx.x * 256 + threadIdx.x) >> 5;
    const int lane = threadIdx.x & 31;
    const int h = gw & 31;
    const int q = (gw >> 5) & 63;
    const int b = gw >> 11;

    const float* src = g_qraw + (size_t)(b * QL + q) * HID + h * HD + lane * 4;
    float4 x4 = *(const float4*)src;
    float  x[4] = {x4.x, x4.y, x4.z, x4.w};
    float4 w4 = *(const float4*)(w + lane * 4);
    float  wv[4] = {w4.x, w4.y, w4.z, w4.w};

    float ss = x[0]*x[0] + x[1]*x[1] + x[2]*x[2] + x[3]*x[3];
#pragma unroll
    for (int o = 16; o > 0; o >>= 1) ss += __shfl_xor_sync(0xffffffffu, ss, o);
    float r1 = rsqrtf(ss * (1.f / 128.f) + EPSR);

    float y[4];
#pragma unroll
    for (int j = 0; j < 4; j++) y[j] = x[j] * r1 * wv[j];

    float ss2 = y[0]*y[0] + y[1]*y[1] + y[2]*y[2] + y[3]*y[3];
#pragma unroll
    for (int o = 16; o > 0; o >>= 1) ss2 += __shfl_xor_sync(0xffffffffu, ss2, o);
    float r2 = rsqrtf(ss2 * (1.f / 128.f) + EPSR);

    float z[4];
#pragma unroll
    for (int j = 0; j < 4; j++) z[j] = y[j] * r2 * wv[j];

    const float4 c4 = *(const float4*)(cosb + (size_t)(CTX + q) * HD + lane * 4);
    const float4 s4 = *(const float4*)(sinb + (size_t)(CTX + q) * HD + lane * 4);
    const float cf[4] = {c4.x, c4.y, c4.z, c4.w};
    const float sf[4] = {s4.x, s4.y, s4.z, s4.w};

    float o_[4];
#pragma unroll
    for (int j = 0; j < 4; j++) {
        float p   = __shfl_xor_sync(0xffffffffu, z[j], 16);
        float rot = (lane < 16) ? -p : p;
        o_[j] = (z[j] * cf[j] + rot * sf[j]) * INV_SQRT_D;
    }
    float* dst = g_q + (size_t)((b * NH + h) * QL + q) * HD + lane * 4;
    *(float4*)dst = make_float4(o_[0], o_[1], o_[2], o_[3]);
}

// ---------------------------------------------------------------------------
// KV-split flash attention. Grid (128 bh, 8 split), 256 threads, 2 CTAs/SM.
// half2 rope convert with sign-folded cs table.
// ---------------------------------------------------------------------------
#define A_RAW_SLOT 32768
#define A_KH_BASE  (2 * A_RAW_SLOT)
#define A_VH_BASE  (A_KH_BASE + 17408)
#define A_MRED     (A_VH_BASE + 17408)
#define ASMEM_BYTES (A_MRED + 1024)

__global__ __launch_bounds__(256, 2) void attn_h(const float* __restrict__ th,
                                                 const float* __restrict__ hs)
{
    extern __shared__ char smc[];
    const uint32_t smBase = smaddr(smc);
    half*  Kh   = (half*)(smc + A_KH_BASE);
    half*  Vh   = (half*)(smc + A_VH_BASE);
    float* mred = (float*)(smc + A_MRED);
    float* lred = mred + 128;

    const int bh = blockIdx.x, h = bh & 31, b = bh >> 5;
    const int sp = blockIdx.y;
    const int c0 = (sp == 0) ? 0 : 9 + (sp - 1) * 8;
    const int c1 = (sp == 0) ? 9 : c0 + 8;

    const int tid = threadIdx.x, lane = tid & 31, wid = tid >> 5;
    const int gid = lane >> 2, tig = lane & 3;
    const int wq = wid >> 1, wg = wid & 1;
    const int r0 = wq * 16, j0 = wg * 32;

    const float* thb = th + (size_t)b * CTX * HID + h * HD;
    const float* hsb = hs + (size_t)b * QL  * HID + h * HD;

    auto load_chunk = [&](int c) {
        const uint32_t rS = smBase + (c & 1) * A_RAW_SLOT;
        const float* base = (c < 64) ? (thb + (size_t)c * 64 * HID) : hsb;
#pragma unroll
        for (int i = 0; i < 8; i++) {
            int u = tid + i * 256, j = u >> 5, d4 = u & 31;
            cpa16(rS + j * 512 + d4 * 16, base + (size_t)j * HID + d4 * 4);
        }
        CP_COMMIT();
    };

    load_chunk(c0); load_chunk(c0 + 1);

    // Q staging (via Kh temp) -> register fragments
    const float* qsrc = g_q + (size_t)bh * (QL * HD);
    for (int e = tid * 4; e < QL * HD; e += 1024) {
        int j = e >> 7, dd = e & 127;
        float4 v = *(const float4*)(qsrc + e);
        *(uint2*)&Kh[j * 136 + dd] = make_uint2(pack2(v.x, v.y), pack2(v.z, v.w));
    }
    __syncthreads();
    uint32_t qa[8][4];
    {
        const uint32_t qA = smBase + A_KH_BASE
                          + (uint32_t)((r0 + (lane & 15)) * 272 + (lane >> 4) * 16);
#pragma unroll
        for (int kd = 0; kd < 8; kd++)
            ldsm4(qa[kd][0], qa[kd][1], qa[kd][2], qa[kd][3], qA + kd * 32);
    }

    const uint32_t kA = smBase + A_KH_BASE
        + (uint32_t)((j0 + (lane & 7) + 8 * (lane >> 4)) * 272 + ((lane >> 3) & 1) * 16);
    const uint32_t vA = smBase + A_VH_BASE
        + (uint32_t)((j0 + (lane & 7) + 8 * ((lane >> 3) & 1)) * 272 + (lane >> 4) * 16);

    float m_lo = -1e30f, m_hi = -1e30f, l_lo = 0.f, l_hi = 0.f;
    float oacc[16][4];
#pragma unroll
    for (int nt = 0; nt < 16; nt++)
#pragma unroll
        for (int i = 0; i < 4; i++) oacc[nt][i] = 0.f;

    for (int t = c0; t < c1; t++) {
        CP_WAIT(1);
        __syncthreads();

        // half2 rope convert: groups of 4 dims; lo/hi halves together
        {
            const float* rw = (const float*)(smc + (t & 1) * A_RAW_SLOT);
            const int p0 = t * 64;
#pragma unroll
            for (int e = tid * 4; e < 64 * 64; e += 1024) {
                int j = e >> 6, dl = e & 63;      // dl multiple of 4
                int p = p0 + j;
                int g = dl >> 2;
                float4 vlo = *(const float4*)&rw[j * 128 + dl];
                float4 vhi = *(const float4*)&rw[j * 128 + dl + 64];
                uint32_t vl0 = pack2(vlo.x, vlo.y), vl1 = pack2(vlo.z, vlo.w);
                uint32_t vh0 = pack2(vhi.x, vhi.y), vh1 = pack2(vhi.z, vhi.w);
                *(uint2*)&Vh[j * 136 + dl]      = make_uint2(vl0, vl1);
                *(uint2*)&Vh[j * 136 + dl + 64] = make_uint2(vh0, vh1);
                uint4 L = g_cs2[p * 32 + g];          // c01,c23,-s01,-s23
                uint4 H = g_cs2[p * 32 + 16 + g];     // c01,c23,+s01,+s23
                uint32_t klo0 = hfma2u(vl0, L.x, hmul2u(vh0, L.z));
                uint32_t klo1 = hfma2u(vl1, L.y, hmul2u(vh1, L.w));
                uint32_t khi0 = hfma2u(vh0, H.x, hmul2u(vl0, H.z));
                uint32_t khi1 = hfma2u(vh1, H.y, hmul2u(vl1, H.w));
                *(uint2*)&Kh[j * 136 + dl]      = make_uint2(klo0, klo1);
                *(uint2*)&Kh[j * 136 + dl + 64] = make_uint2(khi0, khi1);
            }
        }
        __syncthreads();
        if (t + 2 < c1) load_chunk(t + 2); else CP_COMMIT();

        // QK^T
        float sacc[4][4];
#pragma unroll
        for (int nt = 0; nt < 4; nt++)
#pragma unroll
            for (int i = 0; i < 4; i++) sacc[nt][i] = 0.f;
#pragma unroll
        for (int kd = 0; kd < 8; kd++) {
#pragma unroll
            for (int jt = 0; jt < 2; jt++) {
                uint32_t b0, b1, b2, b3;
                ldsm4(b0, b1, b2, b3, kA + jt * 16 * 272 + kd * 32);
                mma16816(sacc[jt * 2],     qa[kd][0], qa[kd][1], qa[kd][2], qa[kd][3], b0, b1);
                mma16816(sacc[jt * 2 + 1], qa[kd][0], qa[kd][1], qa[kd][2], qa[kd][3], b2, b3);
            }
        }

        // online softmax
        float mx_lo = -1e30f, mx_hi = -1e30f;
#pragma unroll
        for (int nt = 0; nt < 4; nt++) {
            mx_lo = fmaxf(mx_lo, fmaxf(sacc[nt][0], sacc[nt][1]));
            mx_hi = fmaxf(mx_hi, fmaxf(sacc[nt][2], sacc[nt][3]));
        }
        mx_lo = fmaxf(mx_lo, __shfl_xor_sync(0xffffffffu, mx_lo, 1));
        mx_lo = fmaxf(mx_lo, __shfl_xor_sync(0xffffffffu, mx_lo, 2));
        mx_hi = fmaxf(mx_hi, __shfl_xor_sync(0xffffffffu, mx_hi, 1));
        mx_hi = fmaxf(mx_hi, __shfl_xor_sync(0xffffffffu, mx_hi, 2));

        float nm_lo = fmaxf(m_lo, mx_lo), nm_hi = fmaxf(m_hi, mx_hi);
        float al_lo = __expf(m_lo - nm_lo), al_hi = __expf(m_hi - nm_hi);
        float sum_lo = 0.f, sum_hi = 0.f;
        uint32_t pa0[4], pa1[4];
#pragma unroll
        for (int nt = 0; nt < 4; nt++) {
            float e0 = __expf(sacc[nt][0] - nm_lo);
            float e1 = __expf(sacc[nt][1] - nm_lo);
            float e2 = __expf(sacc[nt][2] - nm_hi);
            float e3 = __expf(sacc[nt][3] - nm_hi);
            sum_lo += e0 + e1;  sum_hi += e2 + e3;
            pa0[nt] = pack2(e0, e1);
            pa1[nt] = pack2(e2, e3);
        }
        sum_lo += __shfl_xor_sync(0xffffffffu, sum_lo, 1);
        sum_lo += __shfl_xor_sync(0xffffffffu, sum_lo, 2);
        sum_hi += __shfl_xor_sync(0xffffffffu, sum_hi, 1);
        sum_hi += __shfl_xor_sync(0xffffffffu, sum_hi, 2);
        l_lo = l_lo * al_lo + sum_lo;  l_hi = l_hi * al_hi + sum_hi;
        m_lo = nm_lo;  m_hi = nm_hi;

#pragma unroll
        for (int nt = 0; nt < 16; nt++) {
            oacc[nt][0] *= al_lo; oacc[nt][1] *= al_lo;
            oacc[nt][2] *= al_hi; oacc[nt][3] *= al_hi;
        }

        // PV
#pragma unroll
        for (int kc = 0; kc < 2; kc++) {
            uint32_t a0 = pa0[2 * kc], a1 = pa1[2 * kc];
            uint32_t a2 = pa0[2 * kc + 1], a3 = pa1[2 * kc + 1];
#pragma unroll
            for (int dt = 0; dt < 8; dt++) {
                uint32_t b0, b1, b2, b3;
                ldsm4t(b0, b1, b2, b3, vA + kc * 16 * 272 + dt * 32);
                mma16816(oacc[dt * 2],     a0, a1, a2, a3, b0, b1);
                mma16816(oacc[dt * 2 + 1], a0, a1, a2, a3, b2, b3);
            }
        }
    }

    CP_WAIT(0);
    // in-CTA merge of the 2 key stripes -> partial (unnormalized O, m, l)
    const int rlo = r0 + gid, rhi = r0 + gid + 8;
    if (tig == 0) {
        mred[wg * 64 + rlo] = m_lo;  mred[wg * 64 + rhi] = m_hi;
        lred[wg * 64 + rlo] = l_lo;  lred[wg * 64 + rhi] = l_hi;
    }
    __syncthreads();
    float M_lo = fmaxf(mred[rlo], mred[64 + rlo]);
    float M_hi = fmaxf(mred[rhi], mred[64 + rhi]);
    float L_lo = lred[rlo] * __expf(mred[rlo] - M_lo)
               + lred[64 + rlo] * __expf(mred[64 + rlo] - M_lo);
    float L_hi = lred[rhi] * __expf(mred[rhi] - M_hi)
               + lred[64 + rhi] * __expf(mred[64 + rhi] - M_hi);
    float sc_lo = __expf(m_lo - M_lo);
    float sc_hi = __expf(m_hi - M_hi);
#pragma unroll
    for (int nt = 0; nt < 16; nt++) {
        oacc[nt][0] *= sc_lo; oacc[nt][1] *= sc_lo;
        oacc[nt][2] *= sc_hi; oacc[nt][3] *= sc_hi;
    }

    const size_t pbase = ((size_t)sp * NB * NH + bh) * QL;
    if (tig == 0 && wg == 0) {
        g_pm[pbase + rlo] = M_lo;  g_pm[pbase + rhi] = M_hi;
        g_pl[pbase + rlo] = L_lo;  g_pl[pbase + rhi] = L_hi;
    }

    float* OsmF = (float*)smc;
    if (wg == 0) {
#pragma unroll
        for (int nt = 0; nt < 16; nt++) {
            const int col = nt * 8 + 2 * tig;
            *(float2*)&OsmF[rlo * 128 + col] = make_float2(oacc[nt][0], oacc[nt][1]);
            *(float2*)&OsmF[rhi * 128 + col] = make_float2(oacc[nt][2], oacc[nt][3]);
        }
    }
    __syncthreads();
    if (wg == 1) {
#pragma unroll
        for (int nt = 0; nt < 16; nt++) {
            const int col = nt * 8 + 2 * tig;
            float2 v0 = *(float2*)&OsmF[rlo * 128 + col];
            float2 v1 = *(float2*)&OsmF[rhi * 128 + col];
            *(float2*)&OsmF[rlo * 128 + col] = make_float2(oacc[nt][0] + v0.x, oacc[nt][1] + v0.y);
            *(float2*)&OsmF[rhi * 128 + col] = make_float2(oacc[nt][2] + v1.x, oacc[nt][3] + v1.y);
        }
    }
    __syncthreads();

    float* pO = g_pO + pbase * HD;
    for (int e = tid * 4; e < QL * HD; e += 1024)
        *(float4*)(pO + e) = *(const float4*)&OsmF[e];
}

// ---------------------------------------------------------------------------
// merge the 8 splits -> fp16 attention output
// ---------------------------------------------------------------------------
__global__ __launch_bounds__(256) void merge_k()
{
    __shared__ float sc[SPLIT][64];
    const int bh = blockIdx.x, h = bh & 31, b = bh >> 5;
    const int tid = threadIdx.x;

    if (tid < 64) {
        float m[SPLIT], l[SPLIT];
#pragma unroll
        for (int s = 0; s < SPLIT; s++) {
            size_t pb = ((size_t)s * NB * NH + bh) * QL + tid;
            m[s] = g_pm[pb];  l[s] = g_pl[pb];
        }
        float M = m[0];
#pragma unroll
        for (int s = 1; s < SPLIT; s++) M = fmaxf(M, m[s]);
        float L = 0.f;
#pragma unroll
        for (int s = 0; s < SPLIT; s++) L += l[s] * __expf(m[s] - M);
        float invL = 1.f / L;
#pragma unroll
        for (int s = 0; s < SPLIT; s++) sc[s][tid] = __expf(m[s] - M) * invL;
    }
    __syncthreads();

    for (int e = tid * 4; e < QL * HD; e += 1024) {
        int row = e >> 7, dd = e & 127;
        float4 acc = make_float4(0.f, 0.f, 0.f, 0.f);
#pragma unroll
        for (int s = 0; s < SPLIT; s++) {
            const float* pO = g_pO + (((size_t)s * NB * NH + bh) * QL) * HD + e;
            float4 v = *(const float4*)pO;
            float f = sc[s][row];
            acc.x += f * v.x; acc.y += f * v.y; acc.z += f * v.z; acc.w += f * v.w;
        }
        *(uint2*)(g_attn_h + (size_t)(b * QL + row) * HID + h * HD + dd) =
            make_uint2(pack2(acc.x, acc.y), pack2(acc.z, acc.w));
    }
}

// ---------------------------------------------------------------------------
extern "C" void kernel_launch(void* const* d_in, const int* in_sizes, int n_in,
                              void* d_out, int out_size)
{
    const float* hs   = (const float*)d_in[0];
    const float* th   = (const float*)d_in[1];
    const float* cosb = (const float*)d_in[2];
    const float* sinb = (const float*)d_in[3];
    const float* Wqkv = (const float*)d_in[4];
    const float* Wo   = (const float*)d_in[5];
    const float* qw   = (const float*)d_in[6];
    float* out = (float*)d_out;

    float *qraw_p;
    half *hs_h, *attn_h_p, *wq_h, *wo_h;
    cudaGetSymbolAddress((void**)&qraw_p, g_qraw);
    cudaGetSymbolAddress((void**)&hs_h,   g_hs_h);
    cudaGetSymbolAddress((void**)&attn_h_p, g_attn_h);
    cudaGetSymbolAddress((void**)&wq_h,   g_wq_h);
    cudaGetSymbolAddress((void**)&wo_h,   g_wo_h);

    cudaFuncSetAttribute(hgemm3, cudaFuncAttributeMaxDynamicSharedMemorySize, G3_SMEM);
    cudaFuncSetAttribute(attn_h, cudaFuncAttributeMaxDynamicSharedMemorySize, ASMEM_BYTES);

    // preps
    cvt_f2h<<<4096, 256>>>(Wqkv, wq_h, 3 * HID);
    cvt_f2h<<<256,  256>>>(hs,   hs_h, HID);
    cvt_f2h<<<4096, 256>>>(Wo,   wo_h, HID);
    cs2_prep<<<(TOT * 32 + 255) / 256, 256>>>(cosb, sinb);

    dim3 gg(64, 8);
    hgemm3<<<gg, 128, G3_SMEM>>>(hs_h, wq_h, qraw_p);
    qnorm_rope_k<<<1024, 256>>>(cosb, sinb, qw);
    attn_h<<<dim3(NB * NH, SPLIT), 256, ASMEM_BYTES>>>(th, hs);
    merge_k<<<NB * NH, 256>>>();
    hgemm3<<<gg, 128, G3_SMEM>>>(attn_h_p, wo_h, out);
}

// round 9
// speedup vs baseline: 6.1646x; 1.0146x over previous
#include <cuda_runtime.h>
#include <cuda_fp16.h>
#include <math.h>
#include <stdint.h>

#define NB    4
#define QL    64
#define NH    32
#define HD    128
#define CTX   4096
#define TOT   4160
#define HID   4096
#define EPSR  1e-6f
#define INV_SQRT_D 0.08838834764831843f
#define SPLIT 8

__device__ float g_qraw[NB * QL * HID];
__device__ half  g_q_h [NB * NH * QL * HD];
__device__ half  g_hs_h [NB * QL * HID];
__device__ half  g_attn_h[NB * QL * HID];
__device__ half  g_wq_h[HID * HID];
__device__ half  g_wo_h[HID * HID];
__device__ uint4 g_cs2[TOT * 32];
__device__ float g_pO[SPLIT * NB * NH * QL * HD];
__device__ float g_pm[SPLIT * NB * NH * QL];
__device__ float g_pl[SPLIT * NB * NH * QL];

// ---------------------------------------------------------------------------
// helpers
// ---------------------------------------------------------------------------
__device__ __forceinline__ uint32_t smaddr(const void* p) {
    return (uint32_t)__cvta_generic_to_shared(p);
}
__device__ __forceinline__ void ldsm4(uint32_t& r0, uint32_t& r1, uint32_t& r2, uint32_t& r3, uint32_t a) {
    asm volatile("ldmatrix.sync.aligned.m8n8.x4.shared.b16 {%0,%1,%2,%3}, [%4];"
                 : "=r"(r0), "=r"(r1), "=r"(r2), "=r"(r3) : "r"(a));
}
__device__ __forceinline__ void ldsm4t(uint32_t& r0, uint32_t& r1, uint32_t& r2, uint32_t& r3, uint32_t a) {
    asm volatile("ldmatrix.sync.aligned.m8n8.x4.trans.shared.b16 {%0,%1,%2,%3}, [%4];"
                 : "=r"(r0), "=r"(r1), "=r"(r2), "=r"(r3) : "r"(a));
}
__device__ __forceinline__ void mma16816(float d[4],
                                         uint32_t a0, uint32_t a1, uint32_t a2, uint32_t a3,
                                         uint32_t b0, uint32_t b1) {
    asm volatile(
        "mma.sync.aligned.m16n8k16.row.col.f32.f16.f16.f32 "
        "{%0,%1,%2,%3},{%4,%5,%6,%7},{%8,%9},{%0,%1,%2,%3};"
        : "+f"(d[0]), "+f"(d[1]), "+f"(d[2]), "+f"(d[3])
        : "r"(a0), "r"(a1), "r"(a2), "r"(a3), "r"(b0), "r"(b1));
}
__device__ __forceinline__ uint32_t pack2(float x, float y) {
    __half2 h = __floats2half2_rn(x, y);
    return *(uint32_t*)&h;
}
__device__ __forceinline__ uint32_t hfma2u(uint32_t a, uint32_t b, uint32_t c) {
    __half2 r = __hfma2(*(__half2*)&a, *(__half2*)&b, *(__half2*)&c);
    return *(uint32_t*)&r;
}
__device__ __forceinline__ uint32_t hmul2u(uint32_t a, uint32_t b) {
    __half2 r = __hmul2(*(__half2*)&a, *(__half2*)&b);
    return *(uint32_t*)&r;
}
__device__ __forceinline__ void cpa16(uint32_t dst, const void* src) {
    asm volatile("cp.async.cg.shared.global [%0], [%1], 16;" :: "r"(dst), "l"(src));
}
#define CP_COMMIT() asm volatile("cp.async.commit_group;")
#define CP_WAIT(n)  asm volatile("cp.async.wait_group %0;" :: "n"(n))

// ---------------------------------------------------------------------------
// fp32 -> fp16 conversion, 16 elems/thread. cols fixed at 4096.
// ---------------------------------------------------------------------------
__global__ __launch_bounds__(256) void cvt_f2h(const float* __restrict__ src,
                                               half* __restrict__ dst, int ld)
{
    size_t i = ((size_t)blockIdx.x * 256 + threadIdx.x) * 16;
    size_t row = i >> 12;
    int    col = (int)(i & 4095);
    const float* s = src + row * (size_t)ld + col;
    half* d = dst + row * 4096 + col;
    float4 v0 = *(const float4*)(s);
    float4 v1 = *(const float4*)(s + 4);
    float4 v2 = *(const float4*)(s + 8);
    float4 v3 = *(const float4*)(s + 12);
    *(uint2*)(d)      = make_uint2(pack2(v0.x, v0.y), pack2(v0.z, v0.w));
    *(uint2*)(d + 4)  = make_uint2(pack2(v1.x, v1.y), pack2(v1.z, v1.w));
    *(uint2*)(d + 8)  = make_uint2(pack2(v2.x, v2.y), pack2(v2.z, v2.w));
    *(uint2*)(d + 12) = make_uint2(pack2(v3.x, v3.y), pack2(v3.z, v3.w));
}

// sign-folded packed (c, +/-s) table
__global__ __launch_bounds__(256) void cs2_prep(const float* __restrict__ cosb,
                                                const float* __restrict__ sinb)
{
    int i = blockIdx.x * 256 + threadIdx.x;
    if (i >= TOT * 32) return;
    int g    = i & 15;
    int half_ = (i >> 4) & 1;
    int p    = i >> 5;
    int d0   = half_ * 64 + g * 4;
    float4 c = *(const float4*)(cosb + (size_t)p * HD + d0);
    float4 s = *(const float4*)(sinb + (size_t)p * HD + d0);
    float sgn = half_ ? 1.f : -1.f;
    uint4 out;
    out.x = pack2(c.x, c.y);
    out.y = pack2(c.z, c.w);
    out.z = pack2(sgn * s.x, sgn * s.y);
    out.w = pack2(sgn * s.z, sgn * s.w);
    g_cs2[i] = out;
}

// ---------------------------------------------------------------------------
// fp16 GEMM, BM=32 BN=64 BK=64, 128 threads, 4-stage cp.async, 4 CTAs/SM.
// ---------------------------------------------------------------------------
#define G3_ASLOT 4608
#define G3_BSLOT 9216
#define G3_STAGE (G3_ASLOT + G3_BSLOT)
#define G3_SMEM  (4 * G3_STAGE)

__global__ __launch_bounds__(128, 4) void hgemm3(const half* __restrict__ A,
                                                 const half* __restrict__ B,
                                                 float* __restrict__ C)
{
    extern __shared__ char smc[];
    const uint32_t smBase = smaddr(smc);
    const int tid = threadIdx.x, lane = tid & 31, wid = tid >> 5;
    const int gid = lane >> 2, tig = lane & 3;
    const int wm = wid >> 1, wn = wid & 1;
    const int bx = blockIdx.x, by = blockIdx.y;

    const half* Ab = A + (size_t)(by * 32) * HID;
    const half* Bb = B + (size_t)(bx * 64);

    float acc[4][4];
#pragma unroll
    for (int nt = 0; nt < 4; nt++)
#pragma unroll
        for (int i = 0; i < 4; i++) acc[nt][i] = 0.f;

    const uint32_t aOff = (uint32_t)((wm * 16 + (lane & 15)) * 144 + (lane >> 4) * 16);
    const uint32_t bOff = (uint32_t)(((lane & 7) + 8 * ((lane >> 3) & 1)) * 144
                                     + (wn * 32 + 8 * (lane >> 4)) * 2);

    auto load_stage = [&](int kt) {
        const int slot = kt & 3;
        const int k0 = kt * 64;
        const uint32_t aS = smBase + slot * G3_STAGE;
        const uint32_t bS = aS + G3_ASLOT;
#pragma unroll
        for (int i = 0; i < 2; i++) {
            int u = tid + i * 128, r = u >> 3, c = u & 7;
            cpa16(aS + r * 144 + c * 16, Ab + (size_t)r * HID + k0 + c * 8);
        }
#pragma unroll
        for (int i = 0; i < 4; i++) {
            int u = tid + i * 128, r = u >> 3, c = u & 7;
            cpa16(bS + r * 144 + c * 16, Bb + (size_t)(k0 + r) * HID + c * 8);
        }
        CP_COMMIT();
    };

    load_stage(0); load_stage(1); load_stage(2);

    const int NK = HID / 64;
    for (int kt = 0; kt < NK; kt++) {
        CP_WAIT(2);
        __syncthreads();
        if (kt + 3 < NK) load_stage(kt + 3); else CP_COMMIT();

        const uint32_t aA = smBase + (kt & 3) * G3_STAGE + aOff;
        const uint32_t bA = smBase + (kt & 3) * G3_STAGE + G3_ASLOT + bOff;
#pragma unroll
        for (int kk = 0; kk < 4; kk++) {
            uint32_t x0, x1, x2, x3;
            ldsm4(x0, x1, x2, x3, aA + kk * 32);
#pragma unroll
            for (int nt2 = 0; nt2 < 2; nt2++) {
                uint32_t b0, b1, b2, b3;
                ldsm4t(b0, b1, b2, b3, bA + kk * 16 * 144 + nt2 * 32);
                mma16816(acc[nt2 * 2],     x0, x1, x2, x3, b0, b1);
                mma16816(acc[nt2 * 2 + 1], x0, x1, x2, x3, b2, b3);
            }
        }
    }

    const int row = by * 32 + wm * 16 + gid;
#pragma unroll
    for (int nt = 0; nt < 4; nt++) {
        const int col = bx * 64 + wn * 32 + nt * 8 + 2 * tig;
        *(float2*)(C + (size_t)row * HID + col) =
            make_float2(acc[nt][0], acc[nt][1]);
        *(float2*)(C + (size_t)(row + 8) * HID + col) =
            make_float2(acc[nt][2], acc[nt][3]);
    }
}

// ---------------------------------------------------------------------------
// Q: double RMSNorm + RoPE + fold 1/sqrt(D); writes fp16 directly.
// ---------------------------------------------------------------------------
__global__ __launch_bounds__(256) void qnorm_rope_k(const float* __restrict__ cosb,
                                                    const float* __restrict__ sinb,
                                                    const float* __restrict__ w)
{
    const int gw   = (blockIdx.x * 256 + threadIdx.x) >> 5;
    const int lane = threadIdx.x & 31;
    const int h = gw & 31;
    const int q = (gw >> 5) & 63;
    const int b = gw >> 11;

    const float* src = g_qraw + (size_t)(b * QL + q) * HID + h * HD + lane * 4;
    float4 x4 = *(const float4*)src;
    float  x[4] = {x4.x, x4.y, x4.z, x4.w};
    float4 w4 = *(const float4*)(w + lane * 4);
    float  wv[4] = {w4.x, w4.y, w4.z, w4.w};

    float ss = x[0]*x[0] + x[1]*x[1] + x[2]*x[2] + x[3]*x[3];
#pragma unroll
    for (int o = 16; o > 0; o >>= 1) ss += __shfl_xor_sync(0xffffffffu, ss, o);
    float r1 = rsqrtf(ss * (1.f / 128.f) + EPSR);

    float y[4];
#pragma unroll
    for (int j = 0; j < 4; j++) y[j] = x[j] * r1 * wv[j];

    float ss2 = y[0]*y[0] + y[1]*y[1] + y[2]*y[2] + y[3]*y[3];
#pragma unroll
    for (int o = 16; o > 0; o >>= 1) ss2 += __shfl_xor_sync(0xffffffffu, ss2, o);
    float r2 = rsqrtf(ss2 * (1.f / 128.f) + EPSR);

    float z[4];
#pragma unroll
    for (int j = 0; j < 4; j++) z[j] = y[j] * r2 * wv[j];

    const float4 c4 = *(const float4*)(cosb + (size_t)(CTX + q) * HD + lane * 4);
    const float4 s4 = *(const float4*)(sinb + (size_t)(CTX + q) * HD + lane * 4);
    const float cf[4] = {c4.x, c4.y, c4.z, c4.w};
    const float sf[4] = {s4.x, s4.y, s4.z, s4.w};

    float o_[4];
#pragma unroll
    for (int j = 0; j < 4; j++) {
        float p   = __shfl_xor_sync(0xffffffffu, z[j], 16);
        float rot = (lane < 16) ? -p : p;
        o_[j] = (z[j] * cf[j] + rot * sf[j]) * INV_SQRT_D;
    }
    half* dst = g_q_h + (size_t)((b * NH + h) * QL + q) * HD + lane * 4;
    *(uint2*)dst = make_uint2(pack2(o_[0], o_[1]), pack2(o_[2], o_[3]));
}

// ---------------------------------------------------------------------------
// KV-split flash attention. Grid (128 bh, 8 split), 256 threads, 2 CTAs/SM.
// ---------------------------------------------------------------------------
#define A_RAW_SLOT 32768
#define A_KH_BASE  (2 * A_RAW_SLOT)
#define A_VH_BASE  (A_KH_BASE + 17408)
#define A_MRED     (A_VH_BASE + 17408)
#define ASMEM_BYTES (A_MRED + 1024)

__global__ __launch_bounds__(256, 2) void attn_h(const float* __restrict__ th,
                                                 const float* __restrict__ hs)
{
    extern __shared__ char smc[];
    const uint32_t smBase = smaddr(smc);
    half*  Kh   = (half*)(smc + A_KH_BASE);
    half*  Vh   = (half*)(smc + A_VH_BASE);
    float* mred = (float*)(smc + A_MRED);
    float* lred = mred + 128;

    const int bh = blockIdx.x, h = bh & 31, b = bh >> 5;
    const int sp = blockIdx.y;
    const int c0 = (sp == 0) ? 0 : 9 + (sp - 1) * 8;
    const int c1 = (sp == 0) ? 9 : c0 + 8;

    const int tid = threadIdx.x, lane = tid & 31, wid = tid >> 5;
    const int gid = lane >> 2, tig = lane & 3;
    const int wq = wid >> 1, wg = wid & 1;
    const int r0 = wq * 16, j0 = wg * 32;

    const float* thb = th + (size_t)b * CTX * HID + h * HD;
    const float* hsb = hs + (size_t)b * QL  * HID + h * HD;

    auto load_chunk = [&](int c) {
        const uint32_t rS = smBase + (c & 1) * A_RAW_SLOT;
        const float* base = (c < 64) ? (thb + (size_t)c * 64 * HID) : hsb;
#pragma unroll
        for (int i = 0; i < 8; i++) {
            int u = tid + i * 256, j = u >> 5, d4 = u & 31;
            cpa16(rS + j * 512 + d4 * 16, base + (size_t)j * HID + d4 * 4);
        }
        CP_COMMIT();
    };

    load_chunk(c0); load_chunk(c0 + 1);

    // Q staging (fp16 source) -> register fragments
    const half* qsrc = g_q_h + (size_t)bh * (QL * HD);
    for (int e = tid * 4; e < QL * HD; e += 1024) {
        int j = e >> 7, dd = e & 127;
        *(uint2*)&Kh[j * 136 + dd] = *(const uint2*)(qsrc + e);
    }
    __syncthreads();
    uint32_t qa[8][4];
    {
        const uint32_t qA = smBase + A_KH_BASE
                          + (uint32_t)((r0 + (lane & 15)) * 272 + (lane >> 4) * 16);
#pragma unroll
        for (int kd = 0; kd < 8; kd++)
            ldsm4(qa[kd][0], qa[kd][1], qa[kd][2], qa[kd][3], qA + kd * 32);
    }

    const uint32_t kA = smBase + A_KH_BASE
        + (uint32_t)((j0 + (lane & 7) + 8 * (lane >> 4)) * 272 + ((lane >> 3) & 1) * 16);
    const uint32_t vA = smBase + A_VH_BASE
        + (uint32_t)((j0 + (lane & 7) + 8 * ((lane >> 3) & 1)) * 272 + (lane >> 4) * 16);

    float m_lo = -1e30f, m_hi = -1e30f, l_lo = 0.f, l_hi = 0.f;
    float oacc[16][4];
#pragma unroll
    for (int nt = 0; nt < 16; nt++)
#pragma unroll
        for (int i = 0; i < 4; i++) oacc[nt][i] = 0.f;

    for (int t = c0; t < c1; t++) {
        CP_WAIT(1);
        __syncthreads();

        // half2 rope convert
        {
            const float* rw = (const float*)(smc + (t & 1) * A_RAW_SLOT);
            const int p0 = t * 64;
#pragma unroll
            for (int e = tid * 4; e < 64 * 64; e += 1024) {
                int j = e >> 6, dl = e & 63;
                int p = p0 + j;
                int g = dl >> 2;
                float4 vlo = *(const float4*)&rw[j * 128 + dl];
                float4 vhi = *(const float4*)&rw[j * 128 + dl + 64];
                uint32_t vl0 = pack2(vlo.x, vlo.y), vl1 = pack2(vlo.z, vlo.w);
                uint32_t vh0 = pack2(vhi.x, vhi.y), vh1 = pack2(vhi.z, vhi.w);
                *(uint2*)&Vh[j * 136 + dl]      = make_uint2(vl0, vl1);
                *(uint2*)&Vh[j * 136 + dl + 64] = make_uint2(vh0, vh1);
                uint4 L = g_cs2[p * 32 + g];
                uint4 H = g_cs2[p * 32 + 16 + g];
                uint32_t klo0 = hfma2u(vl0, L.x, hmul2u(vh0, L.z));
                uint32_t klo1 = hfma2u(vl1, L.y, hmul2u(vh1, L.w));
                uint32_t khi0 = hfma2u(vh0, H.x, hmul2u(vl0, H.z));
                uint32_t khi1 = hfma2u(vh1, H.y, hmul2u(vl1, H.w));
                *(uint2*)&Kh[j * 136 + dl]      = make_uint2(klo0, klo1);
                *(uint2*)&Kh[j * 136 + dl + 64] = make_uint2(khi0, khi1);
            }
        }
        __syncthreads();
        if (t + 2 < c1) load_chunk(t + 2); else CP_COMMIT();

        // QK^T
        float sacc[4][4];
#pragma unroll
        for (int nt = 0; nt < 4; nt++)
#pragma unroll
            for (int i = 0; i < 4; i++) sacc[nt][i] = 0.f;
#pragma unroll
        for (int kd = 0; kd < 8; kd++) {
#pragma unroll
            for (int jt = 0; jt < 2; jt++) {
                uint32_t b0, b1, b2, b3;
                ldsm4(b0, b1, b2, b3, kA + jt * 16 * 272 + kd * 32);
                mma16816(sacc[jt * 2],     qa[kd][0], qa[kd][1], qa[kd][2], qa[kd][3], b0, b1);
                mma16816(sacc[jt * 2 + 1], qa[kd][0], qa[kd][1], qa[kd][2], qa[kd][3], b2, b3);
            }
        }

        // online softmax
        float mx_lo = -1e30f, mx_hi = -1e30f;
#pragma unroll
        for (int nt = 0; nt < 4; nt++) {
            mx_lo = fmaxf(mx_lo, fmaxf(sacc[nt][0], sacc[nt][1]));
            mx_hi = fmaxf(mx_hi, fmaxf(sacc[nt][2], sacc[nt][3]));
        }
        mx_lo = fmaxf(mx_lo, __shfl_xor_sync(0xffffffffu, mx_lo, 1));
        mx_lo = fmaxf(mx_lo, __shfl_xor_sync(0xffffffffu, mx_lo, 2));
        mx_hi = fmaxf(mx_hi, __shfl_xor_sync(0xffffffffu, mx_hi, 1));
        mx_hi = fmaxf(mx_hi, __shfl_xor_sync(0xffffffffu, mx_hi, 2));

        float nm_lo = fmaxf(m_lo, mx_lo), nm_hi = fmaxf(m_hi, mx_hi);
        float al_lo = __expf(m_lo - nm_lo), al_hi = __expf(m_hi - nm_hi);
        float sum_lo = 0.f, sum_hi = 0.f;
        uint32_t pa0[4], pa1[4];
#pragma unroll
        for (int nt = 0; nt < 4; nt++) {
            float e0 = __expf(sacc[nt][0] - nm_lo);
            float e1 = __expf(sacc[nt][1] - nm_lo);
            float e2 = __expf(sacc[nt][2] - nm_hi);
            float e3 = __expf(sacc[nt][3] - nm_hi);
            sum_lo += e0 + e1;  sum_hi += e2 + e3;
            pa0[nt] = pack2(e0, e1);
            pa1[nt] = pack2(e2, e3);
        }
        sum_lo += __shfl_xor_sync(0xffffffffu, sum_lo, 1);
        sum_lo += __shfl_xor_sync(0xffffffffu, sum_lo, 2);
        sum_hi += __shfl_xor_sync(0xffffffffu, sum_hi, 1);
        sum_hi += __shfl_xor_sync(0xffffffffu, sum_hi, 2);
        l_lo = l_lo * al_lo + sum_lo;  l_hi = l_hi * al_hi + sum_hi;
        m_lo = nm_lo;  m_hi = nm_hi;

#pragma unroll
        for (int nt = 0; nt < 16; nt++) {
            oacc[nt][0] *= al_lo; oacc[nt][1] *= al_lo;
            oacc[nt][2] *= al_hi; oacc[nt][3] *= al_hi;
        }

        // PV
#pragma unroll
        for (int kc = 0; kc < 2; kc++) {
            uint32_t a0 = pa0[2 * kc], a1 = pa1[2 * kc];
            uint32_t a2 = pa0[2 * kc + 1], a3 = pa1[2 * kc + 1];
#pragma unroll
            for (int dt = 0; dt < 8; dt++) {
                uint32_t b0, b1, b2, b3;
                ldsm4t(b0, b1, b2, b3, vA + kc * 16 * 272 + dt * 32);
                mma16816(oacc[dt * 2],     a0, a1, a2, a3, b0, b1);
                mma16816(oacc[dt * 2 + 1], a0, a1, a2, a3, b2, b3);
            }
        }
    }

    CP_WAIT(0);
    const int rlo = r0 + gid, rhi = r0 + gid + 8;
    if (tig == 0) {
        mred[wg * 64 + rlo] = m_lo;  mred[wg * 64 + rhi] = m_hi;
        lred[wg * 64 + rlo] = l_lo;  lred[wg * 64 + rhi] = l_hi;
    }
    __syncthreads();
    float M_lo = fmaxf(mred[rlo], mred[64 + rlo]);
    float M_hi = fmaxf(mred[rhi], mred[64 + rhi]);
    float L_lo = lred[rlo] * __expf(mred[rlo] - M_lo)
               + lred[64 + rlo] * __expf(mred[64 + rlo] - M_lo);
    float L_hi = lred[rhi] * __expf(mred[rhi] - M_hi)
               + lred[64 + rhi] * __expf(mred[64 + rhi] - M_hi);
    float sc_lo = __expf(m_lo - M_lo);
    float sc_hi = __expf(m_hi - M_hi);
#pragma unroll
    for (int nt = 0; nt < 16; nt++) {
        oacc[nt][0] *= sc_lo; oacc[nt][1] *= sc_lo;
        oacc[nt][2] *= sc_hi; oacc[nt][3] *= sc_hi;
    }

    const size_t pbase = ((size_t)sp * NB * NH + bh) * QL;
    if (tig == 0 && wg == 0) {
        g_pm[pbase + rlo] = M_lo;  g_pm[pbase + rhi] = M_hi;
        g_pl[pbase + rlo] = L_lo;  g_pl[pbase + rhi] = L_hi;
    }

    float* OsmF = (float*)smc;
    if (wg == 0) {
#pragma unroll
        for (int nt = 0; nt < 16; nt++) {
            const int col = nt * 8 + 2 * tig;
            *(float2*)&OsmF[rlo * 128 + col] = make_float2(oacc[nt][0], oacc[nt][1]);
            *(float2*)&OsmF[rhi * 128 + col] = make_float2(oacc[nt][2], oacc[nt][3]);
        }
    }
    __syncthreads();
    if (wg == 1) {
#pragma unroll
        for (int nt = 0; nt < 16; nt++) {
            const int col = nt * 8 + 2 * tig;
            float2 v0 = *(float2*)&OsmF[rlo * 128 + col];
            float2 v1 = *(float2*)&OsmF[rhi * 128 + col];
            *(float2*)&OsmF[rlo * 128 + col] = make_float2(oacc[nt][0] + v0.x, oacc[nt][1] + v0.y);
            *(float2*)&OsmF[rhi * 128 + col] = make_float2(oacc[nt][2] + v1.x, oacc[nt][3] + v1.y);
        }
    }
    __syncthreads();

    float* pO = g_pO + pbase * HD;
    for (int e = tid * 4; e < QL * HD; e += 1024)
        *(float4*)(pO + e) = *(const float4*)&OsmF[e];
}

// ---------------------------------------------------------------------------
// merge the splits -> fp16 attention output
// ---------------------------------------------------------------------------
__global__ __launch_bounds__(256) void merge_k()
{
    __shared__ float sc[SPLIT][64];
    const int bh = blockIdx.x, h = bh & 31, b = bh >> 5;
    const int tid = threadIdx.x;

    if (tid < 64) {
        float m[SPLIT], l[SPLIT];
#pragma unroll
        for (int s = 0; s < SPLIT; s++) {
            size_t pb = ((size_t)s * NB * NH + bh) * QL + tid;
            m[s] = g_pm[pb];  l[s] = g_pl[pb];
        }
        float M = m[0];
#pragma unroll
        for (int s = 1; s < SPLIT; s++) M = fmaxf(M, m[s]);
        float L = 0.f;
#pragma unroll
        for (int s = 0; s < SPLIT; s++) L += l[s] * __expf(m[s] - M);
        float invL = 1.f / L;
#pragma unroll
        for (int s = 0; s < SPLIT; s++) sc[s][tid] = __expf(m[s] - M) * invL;
    }
    __syncthreads();

    for (int e = tid * 4; e < QL * HD; e += 1024) {
        int row = e >> 7, dd = e & 127;
        float4 acc = make_float4(0.f, 0.f, 0.f, 0.f);
#pragma unroll
        for (int s = 0; s < SPLIT; s++) {
            const float* pO = g_pO + (((size_t)s * NB * NH + bh) * QL) * HD + e;
            float4 v = *(const float4*)pO;
            float f = sc[s][row];
            acc.x += f * v.x; acc.y += f * v.y; acc.z += f * v.z; acc.w += f * v.w;
        }
        *(uint2*)(g_attn_h + (size_t)(b * QL + row) * HID + h * HD + dd) =
            make_uint2(pack2(acc.x, acc.y), pack2(acc.z, acc.w));
    }
}

// ---------------------------------------------------------------------------
extern "C" void kernel_launch(void* const* d_in, const int* in_sizes, int n_in,
                              void* d_out, int out_size)
{
    const float* hs   = (const float*)d_in[0];
    const float* th   = (const float*)d_in[1];
    const float* cosb = (const float*)d_in[2];
    const float* sinb = (const float*)d_in[3];
    const float* Wqkv = (const float*)d_in[4];
    const float* Wo   = (const float*)d_in[5];
    const float* qw   = (const float*)d_in[6];
    float* out = (float*)d_out;

    float *qraw_p;
    half *hs_h, *attn_h_p, *wq_h, *wo_h;
    cudaGetSymbolAddress((void**)&qraw_p, g_qraw);
    cudaGetSymbolAddress((void**)&hs_h,   g_hs_h);
    cudaGetSymbolAddress((void**)&attn_h_p, g_attn_h);
    cudaGetSymbolAddress((void**)&wq_h,   g_wq_h);
    cudaGetSymbolAddress((void**)&wo_h,   g_wo_h);

    cudaFuncSetAttribute(hgemm3, cudaFuncAttributeMaxDynamicSharedMemorySize, G3_SMEM);
    cudaFuncSetAttribute(attn_h, cudaFuncAttributeMaxDynamicSharedMemorySize, ASMEM_BYTES);

    // Lazy one-time stream/event creation. First call is the (non-capturing)
    // correctness run, so creation happens outside graph capture. The work
    // launched per call is identical every call.
    static cudaStream_t s1 = nullptr;
    static cudaEvent_t evRoot = nullptr, evCS = nullptr, evWO = nullptr;
    if (!s1) {
        cudaStreamCreateWithFlags(&s1, cudaStreamNonBlocking);
        cudaEventCreateWithFlags(&evRoot, cudaEventDisableTiming);
        cudaEventCreateWithFlags(&evCS,   cudaEventDisableTiming);
        cudaEventCreateWithFlags(&evWO,   cudaEventDisableTiming);
    }

    // fork side stream from the (captured) legacy stream
    cudaEventRecord(evRoot, 0);
    cudaStreamWaitEvent(s1, evRoot, 0);

    // side stream: cs table + Wo convert (off the critical path)
    cs2_prep<<<(TOT * 32 + 255) / 256, 256, 0, s1>>>(cosb, sinb);
    cudaEventRecord(evCS, s1);
    cvt_f2h<<<4096, 256, 0, s1>>>(Wo, wo_h, HID);
    cudaEventRecord(evWO, s1);

    // main (critical) path
    cvt_f2h<<<256,  256>>>(hs,   hs_h, HID);
    cvt_f2h<<<4096, 256>>>(Wqkv, wq_h, 3 * HID);

    dim3 gg(64, 8);
    hgemm3<<<gg, 128, G3_SMEM>>>(hs_h, wq_h, qraw_p);
    qnorm_rope_k<<<1024, 256>>>(cosb, sinb, qw);

    cudaStreamWaitEvent((cudaStream_t)0, evCS, 0);
    attn_h<<<dim3(NB * NH, SPLIT), 256, ASMEM_BYTES>>>(th, hs);
    merge_k<<<NB * NH, 256>>>();

    cudaStreamWaitEvent((cudaStream_t)0, evWO, 0);   // also joins s1 tail into capture
    hgemm3<<<gg, 128, G3_SMEM>>>(attn_h_p, wo_h, out);
}